// round 9
// baseline (speedup 1.0000x reference)
#include <cuda_runtime.h>
#include <cuda_bf16.h>
#include <cstdint>

#define N_NODES 50000
#define E_MAX   800000
#define D 128
#define D_OUT 64
#define BN_EPS 1e-5f
#define WTOT (2 * 128 * 256 + 128 * 128)

// ---------------- scratch (device globals; no allocation allowed) ----------
__device__ __nv_bfloat16 g_Mhi[(size_t)N_NODES * D];   // mean hi
__device__ __nv_bfloat16 g_Mlo[(size_t)N_NODES * D];   // mean lo
__device__ __nv_bfloat16 g_Whi[WTOT];
__device__ __nv_bfloat16 g_Wlo[WTOT];
__device__ float g_h0[(size_t)N_NODES * D];   // layer0 out; later reused for [z2|s2]
__device__ float g_h1[(size_t)N_NODES * D];
__device__ int   g_cnti[N_NODES];
__device__ int   g_rowptr[N_NODES + 1];
__device__ int   g_rank[E_MAX];
__device__ int   g_csr[E_MAX];
__device__ float g_sum0[D];
__device__ float g_sq0[D];
__device__ float g_sum1[D];
__device__ float g_sq1[D];

// ---------------- helpers ----------------------------------------------------
__device__ __forceinline__ uint32_t smem_u32(const void* p) {
    return (uint32_t)__cvta_generic_to_shared(p);
}

__device__ __forceinline__ void ldsm4(uint32_t* r, uint32_t a) {
    asm volatile("ldmatrix.sync.aligned.m8n8.x4.shared.b16 {%0,%1,%2,%3}, [%4];"
                 : "=r"(r[0]), "=r"(r[1]), "=r"(r[2]), "=r"(r[3]) : "r"(a));
}

__device__ __forceinline__ void mma16816(float* d, const uint32_t* a, const uint32_t* b) {
    asm volatile("mma.sync.aligned.m16n8k16.row.col.f32.bf16.bf16.f32 "
                 "{%0,%1,%2,%3}, {%4,%5,%6,%7}, {%8,%9}, {%0,%1,%2,%3};"
                 : "+f"(d[0]), "+f"(d[1]), "+f"(d[2]), "+f"(d[3])
                 : "r"(a[0]), "r"(a[1]), "r"(a[2]), "r"(a[3]), "r"(b[0]), "r"(b[1]));
}

__device__ __forceinline__ void bf16split(float v, __nv_bfloat16& hi, __nv_bfloat16& lo) {
    hi = __float2bfloat16(v);
    lo = __float2bfloat16(v - __bfloat162float(hi));
}

// ---------------- prep: weight convert + degree histogram + ranks -----------
__global__ void k_prep(const int* __restrict__ dst, int E,
                       int* __restrict__ cnt, int* __restrict__ rank,
                       const float* __restrict__ Wl0, const float* __restrict__ Wr0,
                       const float* __restrict__ Wl1, const float* __restrict__ Wr1,
                       const float* __restrict__ Wl2, const float* __restrict__ Wr2,
                       __nv_bfloat16* __restrict__ Whi, __nv_bfloat16* __restrict__ Wlo) {
    int idx = blockIdx.x * blockDim.x + threadIdx.x;
    if (idx < WTOT) {
        const int T01 = 128 * 256;
        float v;
        if (idx < T01) {
            int n = idx >> 8, k = idx & 255;
            v = (k < 128) ? __ldg(Wl0 + k * 128 + n) : __ldg(Wr0 + (k - 128) * 128 + n);
        } else if (idx < 2 * T01) {
            int l = idx - T01;
            int n = l >> 8, k = l & 255;
            v = (k < 128) ? __ldg(Wl1 + k * 128 + n) : __ldg(Wr1 + (k - 128) * 128 + n);
        } else {
            int l = idx - 2 * T01;
            int n = l >> 7, k = l & 127;
            v = (n < 64) ? __ldg(Wl2 + k * 64 + n) : __ldg(Wr2 + k * 64 + (n - 64));
        }
        __nv_bfloat16 h, lo;
        bf16split(v, h, lo);
        Whi[idx] = h;
        Wlo[idx] = lo;
    }
    int stride = gridDim.x * blockDim.x;
    int nQ = E >> 2;
    for (int q = idx; q < nQ; q += stride) {
        int4 d = __ldg(reinterpret_cast<const int4*>(dst) + q);
        int4 r;
        r.x = atomicAdd(&cnt[d.x], 1);
        r.y = atomicAdd(&cnt[d.y], 1);
        r.z = atomicAdd(&cnt[d.z], 1);
        r.w = atomicAdd(&cnt[d.w], 1);
        *(reinterpret_cast<int4*>(rank) + q) = r;
    }
    for (int e = nQ * 4 + idx; e < E; e += stride)
        rank[e] = atomicAdd(&cnt[__ldg(dst + e)], 1);
}

// single block, 1024 threads: exclusive scan; self-zeroes cnt for next replay
__global__ void k_scan(int* __restrict__ cnt, int* __restrict__ row_ptr) {
    constexpr int SEG = (N_NODES + 1023) / 1024;
    int t = threadIdx.x;
    int beg = t * SEG;
    int end = min(beg + SEG, N_NODES);
    int s = 0;
    for (int i = beg; i < end; i++) s += cnt[i];
    __shared__ int sh[1024];
    sh[t] = s;
    __syncthreads();
    for (int off = 1; off < 1024; off <<= 1) {
        int v = (t >= off) ? sh[t - off] : 0;
        __syncthreads();
        sh[t] += v;
        __syncthreads();
    }
    int pos = sh[t] - s;
    for (int i = beg; i < end; i++) {
        int c = cnt[i];
        row_ptr[i] = pos;
        pos += c;
        cnt[i] = 0;
    }
    if (beg < N_NODES && end == N_NODES) row_ptr[N_NODES] = pos;
}

// atomic-free fill using precomputed ranks
__global__ void k_fill(const int* __restrict__ src, const int* __restrict__ dst,
                       int E, const int* __restrict__ rank,
                       const int* __restrict__ row_ptr, int* __restrict__ csr) {
    int i = blockIdx.x * blockDim.x + threadIdx.x;
    int stride = gridDim.x * blockDim.x;
    int nQ = E >> 2;
    for (int q = i; q < nQ; q += stride) {
        int4 d = __ldg(reinterpret_cast<const int4*>(dst) + q);
        int4 s = __ldg(reinterpret_cast<const int4*>(src) + q);
        int4 r = __ldg(reinterpret_cast<const int4*>(rank) + q);
        csr[__ldg(row_ptr + d.x) + r.x] = s.x;
        csr[__ldg(row_ptr + d.y) + r.y] = s.y;
        csr[__ldg(row_ptr + d.z) + r.z] = s.z;
        csr[__ldg(row_ptr + d.w) + r.w] = s.w;
    }
    for (int e = nQ * 4 + i; e < E; e += stride)
        csr[__ldg(row_ptr + __ldg(dst + e)) + __ldg(rank + e)] = __ldg(src + e);
}

// ---------------- aggregation: mean only (+ optional inline BN+ReLU) --------
// One warp per node; 4-way unrolled gather; writes mean hi/lo (N x 128).
// Block 0 zeroes the NEXT layer's stats buffers.
template <bool APPLY_BN>
__global__ __launch_bounds__(256)
void k_aggregate(const float* __restrict__ xin, const int* __restrict__ csr,
                 const int* __restrict__ row_ptr,
                 __nv_bfloat16* __restrict__ Mhi, __nv_bfloat16* __restrict__ Mlo,
                 const float* __restrict__ stSum, const float* __restrict__ stSq,
                 const float* __restrict__ gamma, const float* __restrict__ beta,
                 float* __restrict__ zSum, float* __restrict__ zSq) {
    __shared__ float ssc[128], ssh[128];
    int tid = threadIdx.x;
    if (blockIdx.x == 0 && tid < 128) { zSum[tid] = 0.f; zSq[tid] = 0.f; }
    if (APPLY_BN) {
        if (tid < 128) {
            float mu = __ldg(stSum + tid) / (float)N_NODES;
            float var = __ldg(stSq + tid) / (float)N_NODES - mu * mu;
            float sc = __ldg(gamma + tid) * rsqrtf(var + BN_EPS);
            ssc[tid] = sc;
            ssh[tid] = __ldg(beta + tid) - mu * sc;
        }
        __syncthreads();
    }

    int w = (blockIdx.x * blockDim.x + tid) >> 5;
    if (w >= N_NODES) return;
    int lane = tid & 31;

    float4 sc, sh;
    if (APPLY_BN) {
        sc = *reinterpret_cast<const float4*>(ssc + lane * 4);
        sh = *reinterpret_cast<const float4*>(ssh + lane * 4);
    }

    int beg = __ldg(row_ptr + w);
    int end = __ldg(row_ptr + w + 1);
    float4 acc[4];
#pragma unroll
    for (int j = 0; j < 4; j++) acc[j] = make_float4(0.f, 0.f, 0.f, 0.f);

    int i = beg;
    for (; i + 3 < end; i += 4) {
        int s0 = __ldg(csr + i);
        int s1 = __ldg(csr + i + 1);
        int s2 = __ldg(csr + i + 2);
        int s3 = __ldg(csr + i + 3);
        float4 v0 = __ldg(reinterpret_cast<const float4*>(xin + (size_t)s0 * D) + lane);
        float4 v1 = __ldg(reinterpret_cast<const float4*>(xin + (size_t)s1 * D) + lane);
        float4 v2 = __ldg(reinterpret_cast<const float4*>(xin + (size_t)s2 * D) + lane);
        float4 v3 = __ldg(reinterpret_cast<const float4*>(xin + (size_t)s3 * D) + lane);
        float4 vv[4] = {v0, v1, v2, v3};
#pragma unroll
        for (int j = 0; j < 4; j++) {
            float4 v = vv[j];
            if (APPLY_BN) {
                v.x = fmaxf(fmaf(v.x, sc.x, sh.x), 0.f);
                v.y = fmaxf(fmaf(v.y, sc.y, sh.y), 0.f);
                v.z = fmaxf(fmaf(v.z, sc.z, sh.z), 0.f);
                v.w = fmaxf(fmaf(v.w, sc.w, sh.w), 0.f);
            }
            acc[j].x += v.x; acc[j].y += v.y; acc[j].z += v.z; acc[j].w += v.w;
        }
    }
    for (; i < end; i++) {
        int s0 = __ldg(csr + i);
        float4 v = __ldg(reinterpret_cast<const float4*>(xin + (size_t)s0 * D) + lane);
        if (APPLY_BN) {
            v.x = fmaxf(fmaf(v.x, sc.x, sh.x), 0.f);
            v.y = fmaxf(fmaf(v.y, sc.y, sh.y), 0.f);
            v.z = fmaxf(fmaf(v.z, sc.z, sh.z), 0.f);
            v.w = fmaxf(fmaf(v.w, sc.w, sh.w), 0.f);
        }
        acc[0].x += v.x; acc[0].y += v.y; acc[0].z += v.z; acc[0].w += v.w;
    }

    float inv = 1.f / (float)max(end - beg, 1);
    float v[4] = {(acc[0].x + acc[1].x + acc[2].x + acc[3].x) * inv,
                  (acc[0].y + acc[1].y + acc[2].y + acc[3].y) * inv,
                  (acc[0].z + acc[1].z + acc[2].z + acc[3].z) * inv,
                  (acc[0].w + acc[1].w + acc[2].w + acc[3].w) * inv};
    __nv_bfloat16 hb[4], lb[4];
#pragma unroll
    for (int j = 0; j < 4; j++) bf16split(v[j], hb[j], lb[j]);
    size_t off = (size_t)w * D + lane * 4;
    *reinterpret_cast<uint2*>(Mhi + off) = *reinterpret_cast<uint2*>(hb);
    *reinterpret_cast<uint2*>(Mlo + off) = *reinterpret_cast<uint2*>(lb);
}

// ---------------- HMMA GEMM layers 0/1 (K=256, N=128) -----------------------
// A = [mean (bf16 hi/lo) | self (fp32, optional BN+ReLU, split on the fly)]
// out = A @ W^T + b; fused BN column-stat accumulation into stOut.
template <bool HAS_BN>
__global__ __launch_bounds__(256)
void k_mma_gemm(const __nv_bfloat16* __restrict__ Mhi, const __nv_bfloat16* __restrict__ Mlo,
                const float* __restrict__ selfSrc,
                const float* __restrict__ stSum, const float* __restrict__ stSq,
                const float* __restrict__ gamma, const float* __restrict__ beta,
                const __nv_bfloat16* __restrict__ Whi, const __nv_bfloat16* __restrict__ Wlo,
                const float* __restrict__ bias, float* __restrict__ out,
                float* __restrict__ stOutSum, float* __restrict__ stOutSq) {
    constexpr int RS = 72;
    constexpr int NT = 8;
    extern __shared__ __nv_bfloat16 sm[];
    __nv_bfloat16* sAh = sm;
    __nv_bfloat16* sAl = sm + 128 * RS;
    __nv_bfloat16* sWh = sm + 2 * 128 * RS;
    __nv_bfloat16* sWl = sWh + 128 * RS;

    __shared__ float ssum[128];
    __shared__ float ssq[128];
    __shared__ float ssc[128], ssh[128];

    const int tid = threadIdx.x;
    const int lane = tid & 31;
    const int warp = tid >> 5;
    const int wr = warp & 3;
    const int wc = warp >> 2;
    const int rowBase = blockIdx.x * 128;

    if (tid < 128) { ssum[tid] = 0.f; ssq[tid] = 0.f; }
    if (HAS_BN) {
        if (tid < 128) {
            float mu = __ldg(stSum + tid) / (float)N_NODES;
            float var = __ldg(stSq + tid) / (float)N_NODES - mu * mu;
            float sc = __ldg(gamma + tid) * rsqrtf(var + BN_EPS);
            ssc[tid] = sc;
            ssh[tid] = __ldg(beta + tid) - mu * sc;
        }
        __syncthreads();
    }

    const uint32_t sbAh = smem_u32(sAh);
    const uint32_t sbAl = smem_u32(sAl);
    const uint32_t sbWh = smem_u32(sWh);
    const uint32_t sbWl = smem_u32(sWl);

    float acc[2][NT][4];
#pragma unroll
    for (int mt = 0; mt < 2; mt++)
#pragma unroll
        for (int nt = 0; nt < NT; nt++)
#pragma unroll
            for (int j = 0; j < 4; j++) acc[mt][nt][j] = 0.f;

    for (int stage = 0; stage < 4; stage++) {
        // A tile: stages 0-1 from mean bf16 hi/lo; stages 2-3 from fp32 self
#pragma unroll
        for (int t = 0; t < 4; t++) {
            int idx = tid + t * 256;
            int r = idx >> 3, c = idx & 7;
            int row = rowBase + r;
            if (stage < 2) {
                uint4 vh = make_uint4(0, 0, 0, 0), vl = make_uint4(0, 0, 0, 0);
                if (row < N_NODES) {
                    vh = __ldg(reinterpret_cast<const uint4*>(Mhi + (size_t)row * D + stage * 64) + c);
                    vl = __ldg(reinterpret_cast<const uint4*>(Mlo + (size_t)row * D + stage * 64) + c);
                }
                *reinterpret_cast<uint4*>(sAh + r * RS + c * 8) = vh;
                *reinterpret_cast<uint4*>(sAl + r * RS + c * 8) = vl;
            } else {
                int col0 = (stage - 2) * 64 + c * 8;
                __nv_bfloat16 hb[8], lb[8];
                if (row < N_NODES) {
                    float4 u0 = __ldg(reinterpret_cast<const float4*>(selfSrc + (size_t)row * D + col0));
                    float4 u1 = __ldg(reinterpret_cast<const float4*>(selfSrc + (size_t)row * D + col0 + 4));
                    float a[8] = {u0.x, u0.y, u0.z, u0.w, u1.x, u1.y, u1.z, u1.w};
#pragma unroll
                    for (int j = 0; j < 8; j++) {
                        float bn = a[j];
                        if (HAS_BN) bn = fmaxf(fmaf(bn, ssc[col0 + j], ssh[col0 + j]), 0.f);
                        bf16split(bn, hb[j], lb[j]);
                    }
                } else {
#pragma unroll
                    for (int j = 0; j < 8; j++) { hb[j] = __float2bfloat16(0.f); lb[j] = hb[j]; }
                }
                *reinterpret_cast<uint4*>(sAh + r * RS + c * 8) = *reinterpret_cast<uint4*>(hb);
                *reinterpret_cast<uint4*>(sAl + r * RS + c * 8) = *reinterpret_cast<uint4*>(lb);
            }
        }
#pragma unroll
        for (int t = 0; t < 4; t++) {
            int idx = tid + t * 256;
            int n = idx >> 3, c = idx & 7;
            uint4 vh = __ldg(reinterpret_cast<const uint4*>(Whi + (size_t)n * 256 + stage * 64) + c);
            uint4 vl = __ldg(reinterpret_cast<const uint4*>(Wlo + (size_t)n * 256 + stage * 64) + c);
            *reinterpret_cast<uint4*>(sWh + n * RS + c * 8) = vh;
            *reinterpret_cast<uint4*>(sWl + n * RS + c * 8) = vl;
        }
        __syncthreads();

#pragma unroll
        for (int ks = 0; ks < 4; ks++) {
            const uint32_t koff = (uint32_t)(ks * 16 + (lane >> 4) * 8) * 2;
            uint32_t ah[2][4], al[2][4];
#pragma unroll
            for (int mt = 0; mt < 2; mt++) {
                uint32_t roff = (uint32_t)(wr * 32 + mt * 16 + (lane & 15)) * (RS * 2) + koff;
                ldsm4(ah[mt], sbAh + roff);
                ldsm4(al[mt], sbAl + roff);
            }
            uint32_t bh[NT][2], bl[NT][2];
#pragma unroll
            for (int g = 0; g < NT / 2; g++) {
                uint32_t roff = (uint32_t)(wc * 64 + g * 16 + (lane & 15)) * (RS * 2) + koff;
                uint32_t r[4];
                ldsm4(r, sbWh + roff);
                bh[2 * g][0] = r[0]; bh[2 * g][1] = r[2];
                bh[2 * g + 1][0] = r[1]; bh[2 * g + 1][1] = r[3];
                ldsm4(r, sbWl + roff);
                bl[2 * g][0] = r[0]; bl[2 * g][1] = r[2];
                bl[2 * g + 1][0] = r[1]; bl[2 * g + 1][1] = r[3];
            }
#pragma unroll
            for (int mt = 0; mt < 2; mt++)
#pragma unroll
                for (int nt = 0; nt < NT; nt++) {
                    mma16816(acc[mt][nt], ah[mt], bh[nt]);
                    mma16816(acc[mt][nt], al[mt], bh[nt]);
                    mma16816(acc[mt][nt], ah[mt], bl[nt]);
                }
        }
        __syncthreads();
    }

#pragma unroll
    for (int nt = 0; nt < NT; nt++) {
        int col = wc * 64 + nt * 8 + (lane & 3) * 2;
        float2 bb = *reinterpret_cast<const float2*>(bias + col);
        float s0 = 0.f, s1 = 0.f, q0 = 0.f, q1 = 0.f;
#pragma unroll
        for (int mt = 0; mt < 2; mt++) {
            int r0 = rowBase + wr * 32 + mt * 16 + (lane >> 2);
            float v0 = acc[mt][nt][0] + bb.x, v1 = acc[mt][nt][1] + bb.y;
            float v2 = acc[mt][nt][2] + bb.x, v3 = acc[mt][nt][3] + bb.y;
            if (r0 < N_NODES) {
                *reinterpret_cast<float2*>(out + (size_t)r0 * 128 + col) = make_float2(v0, v1);
                s0 += v0; s1 += v1; q0 += v0 * v0; q1 += v1 * v1;
            }
            if (r0 + 8 < N_NODES) {
                *reinterpret_cast<float2*>(out + (size_t)(r0 + 8) * 128 + col) = make_float2(v2, v3);
                s0 += v2; s1 += v3; q0 += v2 * v2; q1 += v3 * v3;
            }
        }
#pragma unroll
        for (int off = 4; off < 32; off <<= 1) {
            s0 += __shfl_down_sync(0xffffffffu, s0, off);
            s1 += __shfl_down_sync(0xffffffffu, s1, off);
            q0 += __shfl_down_sync(0xffffffffu, q0, off);
            q1 += __shfl_down_sync(0xffffffffu, q1, off);
        }
        if ((lane >> 2) == 0) {
            atomicAdd(&ssum[col], s0); atomicAdd(&ssum[col + 1], s1);
            atomicAdd(&ssq[col], q0);  atomicAdd(&ssq[col + 1], q1);
        }
    }
    __syncthreads();
    if (tid < 128) {
        atomicAdd(&stOutSum[tid], ssum[tid]);
        atomicAdd(&stOutSq[tid], ssq[tid]);
    }
}

// ---------------- layer-2 GEMM: [z|s] = relu(bn(h1)) @ [Wl2|Wr2]^T ----------
__global__ __launch_bounds__(256)
void k_gemm_l2(const float* __restrict__ hin,
               const float* __restrict__ stSum, const float* __restrict__ stSq,
               const float* __restrict__ gamma, const float* __restrict__ beta,
               const __nv_bfloat16* __restrict__ Whi, const __nv_bfloat16* __restrict__ Wlo,
               float* __restrict__ zout) {
    constexpr int RS = 72;
    constexpr int NT = 8;
    extern __shared__ __nv_bfloat16 sm[];
    __nv_bfloat16* sAh = sm;
    __nv_bfloat16* sAl = sm + 128 * RS;
    __nv_bfloat16* sWh = sm + 2 * 128 * RS;
    __nv_bfloat16* sWl = sWh + 128 * RS;

    __shared__ float ssc[128], ssh[128];

    const int tid = threadIdx.x;
    const int lane = tid & 31;
    const int warp = tid >> 5;
    const int wr = warp & 3;
    const int wc = warp >> 2;
    const int rowBase = blockIdx.x * 128;

    if (tid < 128) {
        float mu = __ldg(stSum + tid) / (float)N_NODES;
        float var = __ldg(stSq + tid) / (float)N_NODES - mu * mu;
        float sc = __ldg(gamma + tid) * rsqrtf(var + BN_EPS);
        ssc[tid] = sc;
        ssh[tid] = __ldg(beta + tid) - mu * sc;
    }
    __syncthreads();

    const uint32_t sbAh = smem_u32(sAh);
    const uint32_t sbAl = smem_u32(sAl);
    const uint32_t sbWh = smem_u32(sWh);
    const uint32_t sbWl = smem_u32(sWl);

    float acc[2][NT][4];
#pragma unroll
    for (int mt = 0; mt < 2; mt++)
#pragma unroll
        for (int nt = 0; nt < NT; nt++)
#pragma unroll
            for (int j = 0; j < 4; j++) acc[mt][nt][j] = 0.f;

    for (int stage = 0; stage < 2; stage++) {
#pragma unroll
        for (int t = 0; t < 4; t++) {
            int idx = tid + t * 256;
            int r = idx >> 3, c = idx & 7;
            int row = rowBase + r;
            int col0 = stage * 64 + c * 8;
            __nv_bfloat16 hb[8], lb[8];
            if (row < N_NODES) {
                float4 u0 = __ldg(reinterpret_cast<const float4*>(hin + (size_t)row * D + col0));
                float4 u1 = __ldg(reinterpret_cast<const float4*>(hin + (size_t)row * D + col0 + 4));
                float a[8] = {u0.x, u0.y, u0.z, u0.w, u1.x, u1.y, u1.z, u1.w};
#pragma unroll
                for (int j = 0; j < 8; j++) {
                    float bn = fmaxf(fmaf(a[j], ssc[col0 + j], ssh[col0 + j]), 0.f);
                    bf16split(bn, hb[j], lb[j]);
                }
            } else {
#pragma unroll
                for (int j = 0; j < 8; j++) { hb[j] = __float2bfloat16(0.f); lb[j] = hb[j]; }
            }
            *reinterpret_cast<uint4*>(sAh + r * RS + c * 8) = *reinterpret_cast<uint4*>(hb);
            *reinterpret_cast<uint4*>(sAl + r * RS + c * 8) = *reinterpret_cast<uint4*>(lb);
        }
#pragma unroll
        for (int t = 0; t < 4; t++) {
            int idx = tid + t * 256;
            int n = idx >> 3, c = idx & 7;
            uint4 vh = __ldg(reinterpret_cast<const uint4*>(Whi + (size_t)n * 128 + stage * 64) + c);
            uint4 vl = __ldg(reinterpret_cast<const uint4*>(Wlo + (size_t)n * 128 + stage * 64) + c);
            *reinterpret_cast<uint4*>(sWh + n * RS + c * 8) = vh;
            *reinterpret_cast<uint4*>(sWl + n * RS + c * 8) = vl;
        }
        __syncthreads();

#pragma unroll
        for (int ks = 0; ks < 4; ks++) {
            const uint32_t koff = (uint32_t)(ks * 16 + (lane >> 4) * 8) * 2;
            uint32_t ah[2][4], al[2][4];
#pragma unroll
            for (int mt = 0; mt < 2; mt++) {
                uint32_t roff = (uint32_t)(wr * 32 + mt * 16 + (lane & 15)) * (RS * 2) + koff;
                ldsm4(ah[mt], sbAh + roff);
                ldsm4(al[mt], sbAl + roff);
            }
            uint32_t bh[NT][2], bl[NT][2];
#pragma unroll
            for (int g = 0; g < NT / 2; g++) {
                uint32_t roff = (uint32_t)(wc * 64 + g * 16 + (lane & 15)) * (RS * 2) + koff;
                uint32_t r[4];
                ldsm4(r, sbWh + roff);
                bh[2 * g][0] = r[0]; bh[2 * g][1] = r[2];
                bh[2 * g + 1][0] = r[1]; bh[2 * g + 1][1] = r[3];
                ldsm4(r, sbWl + roff);
                bl[2 * g][0] = r[0]; bl[2 * g][1] = r[2];
                bl[2 * g + 1][0] = r[1]; bl[2 * g + 1][1] = r[3];
            }
#pragma unroll
            for (int mt = 0; mt < 2; mt++)
#pragma unroll
                for (int nt = 0; nt < NT; nt++) {
                    mma16816(acc[mt][nt], ah[mt], bh[nt]);
                    mma16816(acc[mt][nt], al[mt], bh[nt]);
                    mma16816(acc[mt][nt], ah[mt], bl[nt]);
                }
        }
        __syncthreads();
    }

#pragma unroll
    for (int nt = 0; nt < NT; nt++) {
        int col = wc * 64 + nt * 8 + (lane & 3) * 2;
#pragma unroll
        for (int mt = 0; mt < 2; mt++) {
            int r0 = rowBase + wr * 32 + mt * 16 + (lane >> 2);
            if (r0 < N_NODES)
                *reinterpret_cast<float2*>(zout + (size_t)r0 * 128 + col) =
                    make_float2(acc[mt][nt][0], acc[mt][nt][1]);
            if (r0 + 8 < N_NODES)
                *reinterpret_cast<float2*>(zout + (size_t)(r0 + 8) * 128 + col) =
                    make_float2(acc[mt][nt][2], acc[mt][nt][3]);
        }
    }
}

// ---------------- final: out = log_softmax(mean(z[src]) + s + b2) -----------
__global__ __launch_bounds__(256)
void k_final(const float* __restrict__ zs, const int* __restrict__ csr,
             const int* __restrict__ row_ptr, const float* __restrict__ b2,
             float* __restrict__ out) {
    int w = (blockIdx.x * blockDim.x + threadIdx.x) >> 5;
    if (w >= N_NODES) return;
    int lane = threadIdx.x & 31;
    int beg = __ldg(row_ptr + w);
    int end = __ldg(row_ptr + w + 1);
    float2 acc[4];
#pragma unroll
    for (int j = 0; j < 4; j++) acc[j] = make_float2(0.f, 0.f);
    int i = beg;
    for (; i + 3 < end; i += 4) {
        int s0 = __ldg(csr + i);
        int s1 = __ldg(csr + i + 1);
        int s2 = __ldg(csr + i + 2);
        int s3 = __ldg(csr + i + 3);
        float2 v0 = __ldg(reinterpret_cast<const float2*>(zs + (size_t)s0 * 128) + lane);
        float2 v1 = __ldg(reinterpret_cast<const float2*>(zs + (size_t)s1 * 128) + lane);
        float2 v2 = __ldg(reinterpret_cast<const float2*>(zs + (size_t)s2 * 128) + lane);
        float2 v3 = __ldg(reinterpret_cast<const float2*>(zs + (size_t)s3 * 128) + lane);
        acc[0].x += v0.x; acc[0].y += v0.y;
        acc[1].x += v1.x; acc[1].y += v1.y;
        acc[2].x += v2.x; acc[2].y += v2.y;
        acc[3].x += v3.x; acc[3].y += v3.y;
    }
    for (; i < end; i++) {
        int s0 = __ldg(csr + i);
        float2 v0 = __ldg(reinterpret_cast<const float2*>(zs + (size_t)s0 * 128) + lane);
        acc[0].x += v0.x; acc[0].y += v0.y;
    }
    float inv = 1.f / (float)max(end - beg, 1);
    float2 sv = __ldg(reinterpret_cast<const float2*>(zs + (size_t)w * 128 + 64) + lane);
    float2 bb = __ldg(reinterpret_cast<const float2*>(b2) + lane);
    float v0 = (acc[0].x + acc[1].x + acc[2].x + acc[3].x) * inv + sv.x + bb.x;
    float v1 = (acc[0].y + acc[1].y + acc[2].y + acc[3].y) * inv + sv.y + bb.y;
    float m = fmaxf(v0, v1);
#pragma unroll
    for (int o = 16; o > 0; o >>= 1) m = fmaxf(m, __shfl_xor_sync(0xffffffffu, m, o));
    float e = expf(v0 - m) + expf(v1 - m);
#pragma unroll
    for (int o = 16; o > 0; o >>= 1) e += __shfl_xor_sync(0xffffffffu, e, o);
    float l = m + logf(e);
    *(reinterpret_cast<float2*>(out + (size_t)w * D_OUT) + lane) = make_float2(v0 - l, v1 - l);
}

// ---------------- launch ----------------------------------------------------
extern "C" void kernel_launch(void* const* d_in, const int* in_sizes, int n_in,
                              void* d_out, int out_size) {
    const float* x   = (const float*)d_in[0];
    const int* ei    = (const int*)d_in[1];
    const float* Wl0 = (const float*)d_in[2];
    const float* Wr0 = (const float*)d_in[3];
    const float* b0  = (const float*)d_in[4];
    const float* g0  = (const float*)d_in[5];
    const float* be0 = (const float*)d_in[6];
    const float* Wl1 = (const float*)d_in[7];
    const float* Wr1 = (const float*)d_in[8];
    const float* b1  = (const float*)d_in[9];
    const float* g1  = (const float*)d_in[10];
    const float* be1 = (const float*)d_in[11];
    const float* Wl2 = (const float*)d_in[12];
    const float* Wr2 = (const float*)d_in[13];
    const float* b2  = (const float*)d_in[14];
    float* out = (float*)d_out;

    const int E = in_sizes[1] / 2;
    const int* src = ei;
    const int* dst = ei + E;

    float *h0, *h1, *sum0, *sq0, *sum1, *sq1;
    __nv_bfloat16 *Mhi, *Mlo, *Whi, *Wlo;
    int *cnti, *rowptr, *rank, *csr;
    cudaGetSymbolAddress((void**)&h0, g_h0);
    cudaGetSymbolAddress((void**)&h1, g_h1);
    cudaGetSymbolAddress((void**)&Mhi, g_Mhi);
    cudaGetSymbolAddress((void**)&Mlo, g_Mlo);
    cudaGetSymbolAddress((void**)&Whi, g_Whi);
    cudaGetSymbolAddress((void**)&Wlo, g_Wlo);
    cudaGetSymbolAddress((void**)&cnti, g_cnti);
    cudaGetSymbolAddress((void**)&rowptr, g_rowptr);
    cudaGetSymbolAddress((void**)&rank, g_rank);
    cudaGetSymbolAddress((void**)&csr, g_csr);
    cudaGetSymbolAddress((void**)&sum0, g_sum0);
    cudaGetSymbolAddress((void**)&sq0, g_sq0);
    cudaGetSymbolAddress((void**)&sum1, g_sum1);
    cudaGetSymbolAddress((void**)&sq1, g_sq1);

    constexpr int RS = 72;
    const int SMEM = (2 * 128 + 2 * 128) * RS * 2;  // 73728
    cudaFuncSetAttribute((const void*)k_mma_gemm<false>, cudaFuncAttributeMaxDynamicSharedMemorySize, SMEM);
    cudaFuncSetAttribute((const void*)k_mma_gemm<true>,  cudaFuncAttributeMaxDynamicSharedMemorySize, SMEM);
    cudaFuncSetAttribute((const void*)k_gemm_l2, cudaFuncAttributeMaxDynamicSharedMemorySize, SMEM);

    const int aggBlocks  = (N_NODES * 32 + 255) / 256;
    const int gemmBlocks = (N_NODES + 127) / 128;

    __nv_bfloat16* W0h = Whi;               __nv_bfloat16* W0l = Wlo;
    __nv_bfloat16* W1h = Whi + 128 * 256;   __nv_bfloat16* W1l = Wlo + 128 * 256;
    __nv_bfloat16* W2h = Whi + 256 * 256;   __nv_bfloat16* W2l = Wlo + 256 * 256;

    // ---- prep: weights + CSR ----
    k_prep<<<512, 256>>>(dst, E, cnti, rank, Wl0, Wr0, Wl1, Wr1, Wl2, Wr2, Whi, Wlo);
    k_scan<<<1, 1024>>>(cnti, rowptr);
    k_fill<<<512, 256>>>(src, dst, E, rank, rowptr, csr);

    // ---- layer 0 ----
    k_aggregate<false><<<aggBlocks, 256>>>(x, csr, rowptr, Mhi, Mlo,
                                           nullptr, nullptr, nullptr, nullptr, sum0, sq0);
    k_mma_gemm<false><<<gemmBlocks, 256, SMEM>>>(Mhi, Mlo, x,
                                                 nullptr, nullptr, nullptr, nullptr,
                                                 W0h, W0l, b0, h0, sum0, sq0);

    // ---- layer 1 (BN0+ReLU fused into aggregation and GEMM self-half) ----
    k_aggregate<true><<<aggBlocks, 256>>>(h0, csr, rowptr, Mhi, Mlo,
                                          sum0, sq0, g0, be0, sum1, sq1);
    k_mma_gemm<true><<<gemmBlocks, 256, SMEM>>>(Mhi, Mlo, h0,
                                                sum0, sq0, g0, be0,
                                                W1h, W1l, b1, h1, sum1, sq1);

    // ---- layer 2 (commuted: GEMM first with BN1 inline, then 64-wide gather) ----
    k_gemm_l2<<<gemmBlocks, 256, SMEM>>>(h1, sum1, sq1, g1, be1, W2h, W2l, h0);
    k_final<<<aggBlocks, 256>>>(h0, csr, rowptr, b2, out);
}

// round 10
// speedup vs baseline: 1.0572x; 1.0572x over previous
#include <cuda_runtime.h>
#include <cuda_bf16.h>
#include <cstdint>

#define N_NODES 50000
#define E_MAX   800000
#define D 128
#define D_OUT 64
#define BN_EPS 1e-5f
#define WTOT (2 * 128 * 256 + 128 * 128)

// ---------------- scratch (device globals; no allocation allowed) ----------
__device__ __nv_bfloat16 g_Mhi[(size_t)N_NODES * D];   // mean hi
__device__ __nv_bfloat16 g_Mlo[(size_t)N_NODES * D];   // mean lo
__device__ __nv_bfloat16 g_Whi[WTOT];
__device__ __nv_bfloat16 g_Wlo[WTOT];
__device__ float g_h0[(size_t)N_NODES * D];   // layer0 out; later reused for [z2|s2]
__device__ float g_h1[(size_t)N_NODES * D];
__device__ int   g_cnti[N_NODES];
__device__ int   g_rowptr[N_NODES + 1];
__device__ int   g_rank[E_MAX];
__device__ int   g_csr[E_MAX];
__device__ float g_sum0[D];
__device__ float g_sq0[D];
__device__ float g_sum1[D];
__device__ float g_sq1[D];

// ---------------- helpers ----------------------------------------------------
__device__ __forceinline__ uint32_t smem_u32(const void* p) {
    return (uint32_t)__cvta_generic_to_shared(p);
}

__device__ __forceinline__ void ldsm4(uint32_t* r, uint32_t a) {
    asm volatile("ldmatrix.sync.aligned.m8n8.x4.shared.b16 {%0,%1,%2,%3}, [%4];"
                 : "=r"(r[0]), "=r"(r[1]), "=r"(r[2]), "=r"(r[3]) : "r"(a));
}

__device__ __forceinline__ void mma16816(float* d, const uint32_t* a, const uint32_t* b) {
    asm volatile("mma.sync.aligned.m16n8k16.row.col.f32.bf16.bf16.f32 "
                 "{%0,%1,%2,%3}, {%4,%5,%6,%7}, {%8,%9}, {%0,%1,%2,%3};"
                 : "+f"(d[0]), "+f"(d[1]), "+f"(d[2]), "+f"(d[3])
                 : "r"(a[0]), "r"(a[1]), "r"(a[2]), "r"(a[3]), "r"(b[0]), "r"(b[1]));
}

__device__ __forceinline__ void bf16split(float v, __nv_bfloat16& hi, __nv_bfloat16& lo) {
    hi = __float2bfloat16(v);
    lo = __float2bfloat16(v - __bfloat162float(hi));
}

// ---------------- prep: weight convert + degree histogram + ranks -----------
__global__ void k_prep(const int* __restrict__ dst, int E,
                       int* __restrict__ cnt, int* __restrict__ rank,
                       const float* __restrict__ Wl0, const float* __restrict__ Wr0,
                       const float* __restrict__ Wl1, const float* __restrict__ Wr1,
                       const float* __restrict__ Wl2, const float* __restrict__ Wr2,
                       __nv_bfloat16* __restrict__ Whi, __nv_bfloat16* __restrict__ Wlo) {
    int idx = blockIdx.x * blockDim.x + threadIdx.x;
    if (idx < WTOT) {
        const int T01 = 128 * 256;
        float v;
        if (idx < T01) {
            int n = idx >> 8, k = idx & 255;
            v = (k < 128) ? __ldg(Wl0 + k * 128 + n) : __ldg(Wr0 + (k - 128) * 128 + n);
        } else if (idx < 2 * T01) {
            int l = idx - T01;
            int n = l >> 8, k = l & 255;
            v = (k < 128) ? __ldg(Wl1 + k * 128 + n) : __ldg(Wr1 + (k - 128) * 128 + n);
        } else {
            int l = idx - 2 * T01;
            int n = l >> 7, k = l & 127;
            v = (n < 64) ? __ldg(Wl2 + k * 64 + n) : __ldg(Wr2 + k * 64 + (n - 64));
        }
        __nv_bfloat16 h, lo;
        bf16split(v, h, lo);
        Whi[idx] = h;
        Wlo[idx] = lo;
    }
    int stride = gridDim.x * blockDim.x;
    int nQ = E >> 2;
    for (int q = idx; q < nQ; q += stride) {
        int4 d = __ldg(reinterpret_cast<const int4*>(dst) + q);
        int4 r;
        r.x = atomicAdd(&cnt[d.x], 1);
        r.y = atomicAdd(&cnt[d.y], 1);
        r.z = atomicAdd(&cnt[d.z], 1);
        r.w = atomicAdd(&cnt[d.w], 1);
        *(reinterpret_cast<int4*>(rank) + q) = r;
    }
    for (int e = nQ * 4 + idx; e < E; e += stride)
        rank[e] = atomicAdd(&cnt[__ldg(dst + e)], 1);
}

// single block, 1024 threads: exclusive scan; self-zeroes cnt for next replay
__global__ void k_scan(int* __restrict__ cnt, int* __restrict__ row_ptr) {
    constexpr int SEG = (N_NODES + 1023) / 1024;
    int t = threadIdx.x;
    int beg = t * SEG;
    int end = min(beg + SEG, N_NODES);
    int s = 0;
    for (int i = beg; i < end; i++) s += cnt[i];
    __shared__ int sh[1024];
    sh[t] = s;
    __syncthreads();
    for (int off = 1; off < 1024; off <<= 1) {
        int v = (t >= off) ? sh[t - off] : 0;
        __syncthreads();
        sh[t] += v;
        __syncthreads();
    }
    int pos = sh[t] - s;
    for (int i = beg; i < end; i++) {
        int c = cnt[i];
        row_ptr[i] = pos;
        pos += c;
        cnt[i] = 0;
    }
    if (beg < N_NODES && end == N_NODES) row_ptr[N_NODES] = pos;
}

// atomic-free fill using precomputed ranks
__global__ void k_fill(const int* __restrict__ src, const int* __restrict__ dst,
                       int E, const int* __restrict__ rank,
                       const int* __restrict__ row_ptr, int* __restrict__ csr) {
    int i = blockIdx.x * blockDim.x + threadIdx.x;
    int stride = gridDim.x * blockDim.x;
    int nQ = E >> 2;
    for (int q = i; q < nQ; q += stride) {
        int4 d = __ldg(reinterpret_cast<const int4*>(dst) + q);
        int4 s = __ldg(reinterpret_cast<const int4*>(src) + q);
        int4 r = __ldg(reinterpret_cast<const int4*>(rank) + q);
        csr[__ldg(row_ptr + d.x) + r.x] = s.x;
        csr[__ldg(row_ptr + d.y) + r.y] = s.y;
        csr[__ldg(row_ptr + d.z) + r.z] = s.z;
        csr[__ldg(row_ptr + d.w) + r.w] = s.w;
    }
    for (int e = nQ * 4 + i; e < E; e += stride)
        csr[__ldg(row_ptr + __ldg(dst + e)) + __ldg(rank + e)] = __ldg(src + e);
}

// ---------------- aggregation: mean only (+ optional inline BN+ReLU) --------
// One warp per node; 2-way unrolled gather (register-lean, high occupancy);
// writes mean hi/lo (N x 128). Block 0 zeroes the NEXT layer's stats buffers.
template <bool APPLY_BN>
__global__ __launch_bounds__(256)
void k_aggregate(const float* __restrict__ xin, const int* __restrict__ csr,
                 const int* __restrict__ row_ptr,
                 __nv_bfloat16* __restrict__ Mhi, __nv_bfloat16* __restrict__ Mlo,
                 const float* __restrict__ stSum, const float* __restrict__ stSq,
                 const float* __restrict__ gamma, const float* __restrict__ beta,
                 float* __restrict__ zSum, float* __restrict__ zSq) {
    __shared__ float ssc[128], ssh[128];
    int tid = threadIdx.x;
    if (blockIdx.x == 0 && tid < 128) { zSum[tid] = 0.f; zSq[tid] = 0.f; }
    if (APPLY_BN) {
        if (tid < 128) {
            float mu = __ldg(stSum + tid) / (float)N_NODES;
            float var = __ldg(stSq + tid) / (float)N_NODES - mu * mu;
            float sc = __ldg(gamma + tid) * rsqrtf(var + BN_EPS);
            ssc[tid] = sc;
            ssh[tid] = __ldg(beta + tid) - mu * sc;
        }
        __syncthreads();
    }

    int w = (blockIdx.x * blockDim.x + tid) >> 5;
    if (w >= N_NODES) return;
    int lane = tid & 31;

    float4 sc, sh;
    if (APPLY_BN) {
        sc = *reinterpret_cast<const float4*>(ssc + lane * 4);
        sh = *reinterpret_cast<const float4*>(ssh + lane * 4);
    }

    int beg = __ldg(row_ptr + w);
    int end = __ldg(row_ptr + w + 1);
    float4 a0 = make_float4(0.f, 0.f, 0.f, 0.f);
    float4 a1 = make_float4(0.f, 0.f, 0.f, 0.f);

    int i = beg;
    for (; i + 1 < end; i += 2) {
        int s0 = __ldg(csr + i);
        int s1 = __ldg(csr + i + 1);
        float4 v0 = __ldg(reinterpret_cast<const float4*>(xin + (size_t)s0 * D) + lane);
        float4 v1 = __ldg(reinterpret_cast<const float4*>(xin + (size_t)s1 * D) + lane);
        if (APPLY_BN) {
            v0.x = fmaxf(fmaf(v0.x, sc.x, sh.x), 0.f);
            v0.y = fmaxf(fmaf(v0.y, sc.y, sh.y), 0.f);
            v0.z = fmaxf(fmaf(v0.z, sc.z, sh.z), 0.f);
            v0.w = fmaxf(fmaf(v0.w, sc.w, sh.w), 0.f);
            v1.x = fmaxf(fmaf(v1.x, sc.x, sh.x), 0.f);
            v1.y = fmaxf(fmaf(v1.y, sc.y, sh.y), 0.f);
            v1.z = fmaxf(fmaf(v1.z, sc.z, sh.z), 0.f);
            v1.w = fmaxf(fmaf(v1.w, sc.w, sh.w), 0.f);
        }
        a0.x += v0.x; a0.y += v0.y; a0.z += v0.z; a0.w += v0.w;
        a1.x += v1.x; a1.y += v1.y; a1.z += v1.z; a1.w += v1.w;
    }
    if (i < end) {
        int s0 = __ldg(csr + i);
        float4 v0 = __ldg(reinterpret_cast<const float4*>(xin + (size_t)s0 * D) + lane);
        if (APPLY_BN) {
            v0.x = fmaxf(fmaf(v0.x, sc.x, sh.x), 0.f);
            v0.y = fmaxf(fmaf(v0.y, sc.y, sh.y), 0.f);
            v0.z = fmaxf(fmaf(v0.z, sc.z, sh.z), 0.f);
            v0.w = fmaxf(fmaf(v0.w, sc.w, sh.w), 0.f);
        }
        a0.x += v0.x; a0.y += v0.y; a0.z += v0.z; a0.w += v0.w;
    }

    float inv = 1.f / (float)max(end - beg, 1);
    float v[4] = {(a0.x + a1.x) * inv, (a0.y + a1.y) * inv,
                  (a0.z + a1.z) * inv, (a0.w + a1.w) * inv};
    __nv_bfloat16 hb[4], lb[4];
#pragma unroll
    for (int j = 0; j < 4; j++) bf16split(v[j], hb[j], lb[j]);
    size_t off = (size_t)w * D + lane * 4;
    *reinterpret_cast<uint2*>(Mhi + off) = *reinterpret_cast<uint2*>(hb);
    *reinterpret_cast<uint2*>(Mlo + off) = *reinterpret_cast<uint2*>(lb);
}

// ---------------- HMMA GEMM layers 0/1 (K=256, N=128) -----------------------
// A = [mean (bf16 hi/lo) | self (fp32, optional BN+ReLU, split on the fly)]
// out = A @ W^T + b; fused BN column-stat accumulation into stOut.
template <bool HAS_BN>
__global__ __launch_bounds__(256)
void k_mma_gemm(const __nv_bfloat16* __restrict__ Mhi, const __nv_bfloat16* __restrict__ Mlo,
                const float* __restrict__ selfSrc,
                const float* __restrict__ stSum, const float* __restrict__ stSq,
                const float* __restrict__ gamma, const float* __restrict__ beta,
                const __nv_bfloat16* __restrict__ Whi, const __nv_bfloat16* __restrict__ Wlo,
                const float* __restrict__ bias, float* __restrict__ out,
                float* __restrict__ stOutSum, float* __restrict__ stOutSq) {
    constexpr int RS = 72;
    constexpr int NT = 8;
    extern __shared__ __nv_bfloat16 sm[];
    __nv_bfloat16* sAh = sm;
    __nv_bfloat16* sAl = sm + 128 * RS;
    __nv_bfloat16* sWh = sm + 2 * 128 * RS;
    __nv_bfloat16* sWl = sWh + 128 * RS;

    __shared__ float ssum[128];
    __shared__ float ssq[128];
    __shared__ float ssc[128], ssh[128];

    const int tid = threadIdx.x;
    const int lane = tid & 31;
    const int warp = tid >> 5;
    const int wr = warp & 3;
    const int wc = warp >> 2;
    const int rowBase = blockIdx.x * 128;

    if (tid < 128) { ssum[tid] = 0.f; ssq[tid] = 0.f; }
    if (HAS_BN) {
        if (tid < 128) {
            float mu = __ldg(stSum + tid) / (float)N_NODES;
            float var = __ldg(stSq + tid) / (float)N_NODES - mu * mu;
            float sc = __ldg(gamma + tid) * rsqrtf(var + BN_EPS);
            ssc[tid] = sc;
            ssh[tid] = __ldg(beta + tid) - mu * sc;
        }
        __syncthreads();
    }

    const uint32_t sbAh = smem_u32(sAh);
    const uint32_t sbAl = smem_u32(sAl);
    const uint32_t sbWh = smem_u32(sWh);
    const uint32_t sbWl = smem_u32(sWl);

    float acc[2][NT][4];
#pragma unroll
    for (int mt = 0; mt < 2; mt++)
#pragma unroll
        for (int nt = 0; nt < NT; nt++)
#pragma unroll
            for (int j = 0; j < 4; j++) acc[mt][nt][j] = 0.f;

    for (int stage = 0; stage < 4; stage++) {
        // A tile: stages 0-1 from mean bf16 hi/lo; stages 2-3 from fp32 self
#pragma unroll
        for (int t = 0; t < 4; t++) {
            int idx = tid + t * 256;
            int r = idx >> 3, c = idx & 7;
            int row = rowBase + r;
            if (stage < 2) {
                uint4 vh = make_uint4(0, 0, 0, 0), vl = make_uint4(0, 0, 0, 0);
                if (row < N_NODES) {
                    vh = __ldg(reinterpret_cast<const uint4*>(Mhi + (size_t)row * D + stage * 64) + c);
                    vl = __ldg(reinterpret_cast<const uint4*>(Mlo + (size_t)row * D + stage * 64) + c);
                }
                *reinterpret_cast<uint4*>(sAh + r * RS + c * 8) = vh;
                *reinterpret_cast<uint4*>(sAl + r * RS + c * 8) = vl;
            } else {
                int col0 = (stage - 2) * 64 + c * 8;
                __nv_bfloat16 hb[8], lb[8];
                if (row < N_NODES) {
                    float4 u0 = __ldg(reinterpret_cast<const float4*>(selfSrc + (size_t)row * D + col0));
                    float4 u1 = __ldg(reinterpret_cast<const float4*>(selfSrc + (size_t)row * D + col0 + 4));
                    float a[8] = {u0.x, u0.y, u0.z, u0.w, u1.x, u1.y, u1.z, u1.w};
#pragma unroll
                    for (int j = 0; j < 8; j++) {
                        float bn = a[j];
                        if (HAS_BN) bn = fmaxf(fmaf(bn, ssc[col0 + j], ssh[col0 + j]), 0.f);
                        bf16split(bn, hb[j], lb[j]);
                    }
                } else {
#pragma unroll
                    for (int j = 0; j < 8; j++) { hb[j] = __float2bfloat16(0.f); lb[j] = hb[j]; }
                }
                *reinterpret_cast<uint4*>(sAh + r * RS + c * 8) = *reinterpret_cast<uint4*>(hb);
                *reinterpret_cast<uint4*>(sAl + r * RS + c * 8) = *reinterpret_cast<uint4*>(lb);
            }
        }
#pragma unroll
        for (int t = 0; t < 4; t++) {
            int idx = tid + t * 256;
            int n = idx >> 3, c = idx & 7;
            uint4 vh = __ldg(reinterpret_cast<const uint4*>(Whi + (size_t)n * 256 + stage * 64) + c);
            uint4 vl = __ldg(reinterpret_cast<const uint4*>(Wlo + (size_t)n * 256 + stage * 64) + c);
            *reinterpret_cast<uint4*>(sWh + n * RS + c * 8) = vh;
            *reinterpret_cast<uint4*>(sWl + n * RS + c * 8) = vl;
        }
        __syncthreads();

#pragma unroll
        for (int ks = 0; ks < 4; ks++) {
            const uint32_t koff = (uint32_t)(ks * 16 + (lane >> 4) * 8) * 2;
            uint32_t ah[2][4], al[2][4];
#pragma unroll
            for (int mt = 0; mt < 2; mt++) {
                uint32_t roff = (uint32_t)(wr * 32 + mt * 16 + (lane & 15)) * (RS * 2) + koff;
                ldsm4(ah[mt], sbAh + roff);
                ldsm4(al[mt], sbAl + roff);
            }
            uint32_t bh[NT][2], bl[NT][2];
#pragma unroll
            for (int g = 0; g < NT / 2; g++) {
                uint32_t roff = (uint32_t)(wc * 64 + g * 16 + (lane & 15)) * (RS * 2) + koff;
                uint32_t r[4];
                ldsm4(r, sbWh + roff);
                bh[2 * g][0] = r[0]; bh[2 * g][1] = r[2];
                bh[2 * g + 1][0] = r[1]; bh[2 * g + 1][1] = r[3];
                ldsm4(r, sbWl + roff);
                bl[2 * g][0] = r[0]; bl[2 * g][1] = r[2];
                bl[2 * g + 1][0] = r[1]; bl[2 * g + 1][1] = r[3];
            }
#pragma unroll
            for (int mt = 0; mt < 2; mt++)
#pragma unroll
                for (int nt = 0; nt < NT; nt++) {
                    mma16816(acc[mt][nt], ah[mt], bh[nt]);
                    mma16816(acc[mt][nt], al[mt], bh[nt]);
                    mma16816(acc[mt][nt], ah[mt], bl[nt]);
                }
        }
        __syncthreads();
    }

#pragma unroll
    for (int nt = 0; nt < NT; nt++) {
        int col = wc * 64 + nt * 8 + (lane & 3) * 2;
        float2 bb = *reinterpret_cast<const float2*>(bias + col);
        float s0 = 0.f, s1 = 0.f, q0 = 0.f, q1 = 0.f;
#pragma unroll
        for (int mt = 0; mt < 2; mt++) {
            int r0 = rowBase + wr * 32 + mt * 16 + (lane >> 2);
            float v0 = acc[mt][nt][0] + bb.x, v1 = acc[mt][nt][1] + bb.y;
            float v2 = acc[mt][nt][2] + bb.x, v3 = acc[mt][nt][3] + bb.y;
            if (r0 < N_NODES) {
                *reinterpret_cast<float2*>(out + (size_t)r0 * 128 + col) = make_float2(v0, v1);
                s0 += v0; s1 += v1; q0 += v0 * v0; q1 += v1 * v1;
            }
            if (r0 + 8 < N_NODES) {
                *reinterpret_cast<float2*>(out + (size_t)(r0 + 8) * 128 + col) = make_float2(v2, v3);
                s0 += v2; s1 += v3; q0 += v2 * v2; q1 += v3 * v3;
            }
        }
#pragma unroll
        for (int off = 4; off < 32; off <<= 1) {
            s0 += __shfl_down_sync(0xffffffffu, s0, off);
            s1 += __shfl_down_sync(0xffffffffu, s1, off);
            q0 += __shfl_down_sync(0xffffffffu, q0, off);
            q1 += __shfl_down_sync(0xffffffffu, q1, off);
        }
        if ((lane >> 2) == 0) {
            atomicAdd(&ssum[col], s0); atomicAdd(&ssum[col + 1], s1);
            atomicAdd(&ssq[col], q0);  atomicAdd(&ssq[col + 1], q1);
        }
    }
    __syncthreads();
    if (tid < 128) {
        atomicAdd(&stOutSum[tid], ssum[tid]);
        atomicAdd(&stOutSq[tid], ssq[tid]);
    }
}

// ---------------- layer-2 GEMM: [z|s] = relu(bn(h1)) @ [Wl2|Wr2]^T ----------
__global__ __launch_bounds__(256)
void k_gemm_l2(const float* __restrict__ hin,
               const float* __restrict__ stSum, const float* __restrict__ stSq,
               const float* __restrict__ gamma, const float* __restrict__ beta,
               const __nv_bfloat16* __restrict__ Whi, const __nv_bfloat16* __restrict__ Wlo,
               float* __restrict__ zout) {
    constexpr int RS = 72;
    constexpr int NT = 8;
    extern __shared__ __nv_bfloat16 sm[];
    __nv_bfloat16* sAh = sm;
    __nv_bfloat16* sAl = sm + 128 * RS;
    __nv_bfloat16* sWh = sm + 2 * 128 * RS;
    __nv_bfloat16* sWl = sWh + 128 * RS;

    __shared__ float ssc[128], ssh[128];

    const int tid = threadIdx.x;
    const int lane = tid & 31;
    const int warp = tid >> 5;
    const int wr = warp & 3;
    const int wc = warp >> 2;
    const int rowBase = blockIdx.x * 128;

    if (tid < 128) {
        float mu = __ldg(stSum + tid) / (float)N_NODES;
        float var = __ldg(stSq + tid) / (float)N_NODES - mu * mu;
        float sc = __ldg(gamma + tid) * rsqrtf(var + BN_EPS);
        ssc[tid] = sc;
        ssh[tid] = __ldg(beta + tid) - mu * sc;
    }
    __syncthreads();

    const uint32_t sbAh = smem_u32(sAh);
    const uint32_t sbAl = smem_u32(sAl);
    const uint32_t sbWh = smem_u32(sWh);
    const uint32_t sbWl = smem_u32(sWl);

    float acc[2][NT][4];
#pragma unroll
    for (int mt = 0; mt < 2; mt++)
#pragma unroll
        for (int nt = 0; nt < NT; nt++)
#pragma unroll
            for (int j = 0; j < 4; j++) acc[mt][nt][j] = 0.f;

    for (int stage = 0; stage < 2; stage++) {
#pragma unroll
        for (int t = 0; t < 4; t++) {
            int idx = tid + t * 256;
            int r = idx >> 3, c = idx & 7;
            int row = rowBase + r;
            int col0 = stage * 64 + c * 8;
            __nv_bfloat16 hb[8], lb[8];
            if (row < N_NODES) {
                float4 u0 = __ldg(reinterpret_cast<const float4*>(hin + (size_t)row * D + col0));
                float4 u1 = __ldg(reinterpret_cast<const float4*>(hin + (size_t)row * D + col0 + 4));
                float a[8] = {u0.x, u0.y, u0.z, u0.w, u1.x, u1.y, u1.z, u1.w};
#pragma unroll
                for (int j = 0; j < 8; j++) {
                    float bn = fmaxf(fmaf(a[j], ssc[col0 + j], ssh[col0 + j]), 0.f);
                    bf16split(bn, hb[j], lb[j]);
                }
            } else {
#pragma unroll
                for (int j = 0; j < 8; j++) { hb[j] = __float2bfloat16(0.f); lb[j] = hb[j]; }
            }
            *reinterpret_cast<uint4*>(sAh + r * RS + c * 8) = *reinterpret_cast<uint4*>(hb);
            *reinterpret_cast<uint4*>(sAl + r * RS + c * 8) = *reinterpret_cast<uint4*>(lb);
        }
#pragma unroll
        for (int t = 0; t < 4; t++) {
            int idx = tid + t * 256;
            int n = idx >> 3, c = idx & 7;
            uint4 vh = __ldg(reinterpret_cast<const uint4*>(Whi + (size_t)n * 128 + stage * 64) + c);
            uint4 vl = __ldg(reinterpret_cast<const uint4*>(Wlo + (size_t)n * 128 + stage * 64) + c);
            *reinterpret_cast<uint4*>(sWh + n * RS + c * 8) = vh;
            *reinterpret_cast<uint4*>(sWl + n * RS + c * 8) = vl;
        }
        __syncthreads();

#pragma unroll
        for (int ks = 0; ks < 4; ks++) {
            const uint32_t koff = (uint32_t)(ks * 16 + (lane >> 4) * 8) * 2;
            uint32_t ah[2][4], al[2][4];
#pragma unroll
            for (int mt = 0; mt < 2; mt++) {
                uint32_t roff = (uint32_t)(wr * 32 + mt * 16 + (lane & 15)) * (RS * 2) + koff;
                ldsm4(ah[mt], sbAh + roff);
                ldsm4(al[mt], sbAl + roff);
            }
            uint32_t bh[NT][2], bl[NT][2];
#pragma unroll
            for (int g = 0; g < NT / 2; g++) {
                uint32_t roff = (uint32_t)(wc * 64 + g * 16 + (lane & 15)) * (RS * 2) + koff;
                uint32_t r[4];
                ldsm4(r, sbWh + roff);
                bh[2 * g][0] = r[0]; bh[2 * g][1] = r[2];
                bh[2 * g + 1][0] = r[1]; bh[2 * g + 1][1] = r[3];
                ldsm4(r, sbWl + roff);
                bl[2 * g][0] = r[0]; bl[2 * g][1] = r[2];
                bl[2 * g + 1][0] = r[1]; bl[2 * g + 1][1] = r[3];
            }
#pragma unroll
            for (int mt = 0; mt < 2; mt++)
#pragma unroll
                for (int nt = 0; nt < NT; nt++) {
                    mma16816(acc[mt][nt], ah[mt], bh[nt]);
                    mma16816(acc[mt][nt], al[mt], bh[nt]);
                    mma16816(acc[mt][nt], ah[mt], bl[nt]);
                }
        }
        __syncthreads();
    }

#pragma unroll
    for (int nt = 0; nt < NT; nt++) {
        int col = wc * 64 + nt * 8 + (lane & 3) * 2;
#pragma unroll
        for (int mt = 0; mt < 2; mt++) {
            int r0 = rowBase + wr * 32 + mt * 16 + (lane >> 2);
            if (r0 < N_NODES)
                *reinterpret_cast<float2*>(zout + (size_t)r0 * 128 + col) =
                    make_float2(acc[mt][nt][0], acc[mt][nt][1]);
            if (r0 + 8 < N_NODES)
                *reinterpret_cast<float2*>(zout + (size_t)(r0 + 8) * 128 + col) =
                    make_float2(acc[mt][nt][2], acc[mt][nt][3]);
        }
    }
}

// ---------------- final: out = log_softmax(mean(z[src]) + s + b2) -----------
__global__ __launch_bounds__(256)
void k_final(const float* __restrict__ zs, const int* __restrict__ csr,
             const int* __restrict__ row_ptr, const float* __restrict__ b2,
             float* __restrict__ out) {
    int w = (blockIdx.x * blockDim.x + threadIdx.x) >> 5;
    if (w >= N_NODES) return;
    int lane = threadIdx.x & 31;
    int beg = __ldg(row_ptr + w);
    int end = __ldg(row_ptr + w + 1);
    float2 a0 = make_float2(0.f, 0.f), a1 = make_float2(0.f, 0.f);
    int i = beg;
    for (; i + 1 < end; i += 2) {
        int s0 = __ldg(csr + i);
        int s1 = __ldg(csr + i + 1);
        float2 v0 = __ldg(reinterpret_cast<const float2*>(zs + (size_t)s0 * 128) + lane);
        float2 v1 = __ldg(reinterpret_cast<const float2*>(zs + (size_t)s1 * 128) + lane);
        a0.x += v0.x; a0.y += v0.y;
        a1.x += v1.x; a1.y += v1.y;
    }
    if (i < end) {
        int s0 = __ldg(csr + i);
        float2 v0 = __ldg(reinterpret_cast<const float2*>(zs + (size_t)s0 * 128) + lane);
        a0.x += v0.x; a0.y += v0.y;
    }
    float inv = 1.f / (float)max(end - beg, 1);
    float2 sv = __ldg(reinterpret_cast<const float2*>(zs + (size_t)w * 128 + 64) + lane);
    float2 bb = __ldg(reinterpret_cast<const float2*>(b2) + lane);
    float v0 = (a0.x + a1.x) * inv + sv.x + bb.x;
    float v1 = (a0.y + a1.y) * inv + sv.y + bb.y;
    float m = fmaxf(v0, v1);
#pragma unroll
    for (int o = 16; o > 0; o >>= 1) m = fmaxf(m, __shfl_xor_sync(0xffffffffu, m, o));
    float e = expf(v0 - m) + expf(v1 - m);
#pragma unroll
    for (int o = 16; o > 0; o >>= 1) e += __shfl_xor_sync(0xffffffffu, e, o);
    float l = m + logf(e);
    *(reinterpret_cast<float2*>(out + (size_t)w * D_OUT) + lane) = make_float2(v0 - l, v1 - l);
}

// ---------------- launch ----------------------------------------------------
extern "C" void kernel_launch(void* const* d_in, const int* in_sizes, int n_in,
                              void* d_out, int out_size) {
    const float* x   = (const float*)d_in[0];
    const int* ei    = (const int*)d_in[1];
    const float* Wl0 = (const float*)d_in[2];
    const float* Wr0 = (const float*)d_in[3];
    const float* b0  = (const float*)d_in[4];
    const float* g0  = (const float*)d_in[5];
    const float* be0 = (const float*)d_in[6];
    const float* Wl1 = (const float*)d_in[7];
    const float* Wr1 = (const float*)d_in[8];
    const float* b1  = (const float*)d_in[9];
    const float* g1  = (const float*)d_in[10];
    const float* be1 = (const float*)d_in[11];
    const float* Wl2 = (const float*)d_in[12];
    const float* Wr2 = (const float*)d_in[13];
    const float* b2  = (const float*)d_in[14];
    float* out = (float*)d_out;

    const int E = in_sizes[1] / 2;
    const int* src = ei;
    const int* dst = ei + E;

    float *h0, *h1, *sum0, *sq0, *sum1, *sq1;
    __nv_bfloat16 *Mhi, *Mlo, *Whi, *Wlo;
    int *cnti, *rowptr, *rank, *csr;
    cudaGetSymbolAddress((void**)&h0, g_h0);
    cudaGetSymbolAddress((void**)&h1, g_h1);
    cudaGetSymbolAddress((void**)&Mhi, g_Mhi);
    cudaGetSymbolAddress((void**)&Mlo, g_Mlo);
    cudaGetSymbolAddress((void**)&Whi, g_Whi);
    cudaGetSymbolAddress((void**)&Wlo, g_Wlo);
    cudaGetSymbolAddress((void**)&cnti, g_cnti);
    cudaGetSymbolAddress((void**)&rowptr, g_rowptr);
    cudaGetSymbolAddress((void**)&rank, g_rank);
    cudaGetSymbolAddress((void**)&csr, g_csr);
    cudaGetSymbolAddress((void**)&sum0, g_sum0);
    cudaGetSymbolAddress((void**)&sq0, g_sq0);
    cudaGetSymbolAddress((void**)&sum1, g_sum1);
    cudaGetSymbolAddress((void**)&sq1, g_sq1);

    constexpr int RS = 72;
    const int SMEM = (2 * 128 + 2 * 128) * RS * 2;  // 73728
    cudaFuncSetAttribute((const void*)k_mma_gemm<false>, cudaFuncAttributeMaxDynamicSharedMemorySize, SMEM);
    cudaFuncSetAttribute((const void*)k_mma_gemm<true>,  cudaFuncAttributeMaxDynamicSharedMemorySize, SMEM);
    cudaFuncSetAttribute((const void*)k_gemm_l2, cudaFuncAttributeMaxDynamicSharedMemorySize, SMEM);

    const int aggBlocks  = (N_NODES * 32 + 255) / 256;
    const int gemmBlocks = (N_NODES + 127) / 128;

    __nv_bfloat16* W0h = Whi;               __nv_bfloat16* W0l = Wlo;
    __nv_bfloat16* W1h = Whi + 128 * 256;   __nv_bfloat16* W1l = Wlo + 128 * 256;
    __nv_bfloat16* W2h = Whi + 256 * 256;   __nv_bfloat16* W2l = Wlo + 256 * 256;

    // ---- prep: weights + CSR ----
    k_prep<<<512, 256>>>(dst, E, cnti, rank, Wl0, Wr0, Wl1, Wr1, Wl2, Wr2, Whi, Wlo);
    k_scan<<<1, 1024>>>(cnti, rowptr);
    k_fill<<<512, 256>>>(src, dst, E, rank, rowptr, csr);

    // ---- layer 0 ----
    k_aggregate<false><<<aggBlocks, 256>>>(x, csr, rowptr, Mhi, Mlo,
                                           nullptr, nullptr, nullptr, nullptr, sum0, sq0);
    k_mma_gemm<false><<<gemmBlocks, 256, SMEM>>>(Mhi, Mlo, x,
                                                 nullptr, nullptr, nullptr, nullptr,
                                                 W0h, W0l, b0, h0, sum0, sq0);

    // ---- layer 1 (BN0+ReLU fused into aggregation and GEMM self-half) ----
    k_aggregate<true><<<aggBlocks, 256>>>(h0, csr, rowptr, Mhi, Mlo,
                                          sum0, sq0, g0, be0, sum1, sq1);
    k_mma_gemm<true><<<gemmBlocks, 256, SMEM>>>(Mhi, Mlo, h0,
                                                sum0, sq0, g0, be0,
                                                W1h, W1l, b1, h1, sum1, sq1);

    // ---- layer 2 (commuted: GEMM first with BN1 inline, then 64-wide gather) ----
    k_gemm_l2<<<gemmBlocks, 256, SMEM>>>(h1, sum1, sq1, g1, be1, W2h, W2l, h0);
    k_final<<<aggBlocks, 256>>>(h0, csr, rowptr, b2, out);
}

// round 11
// speedup vs baseline: 1.2317x; 1.1650x over previous
#include <cuda_runtime.h>
#include <cuda_fp16.h>
#include <cstdint>

#define N_NODES 50000
#define E_MAX   800000
#define D 128
#define D_OUT 64
#define BN_EPS 1e-5f
#define WTOT (2 * 128 * 256 + 128 * 128)

// ---------------- scratch (device globals; no allocation allowed) ----------
__device__ __half g_xh[(size_t)N_NODES * D];   // fp16 copy of x
__device__ __half g_M[(size_t)N_NODES * D];    // neighbor mean (fp16)
__device__ __half g_W[WTOT];                   // fp16 weights (all layers, transposed)
__device__ __half g_h0[(size_t)N_NODES * D];   // layer0 out; later reused for [z2|s2]
__device__ __half g_h1[(size_t)N_NODES * D];
__device__ int    g_cnti[N_NODES];
__device__ int    g_rowptr[N_NODES + 1];
__device__ int    g_rank[E_MAX];
__device__ int    g_csr[E_MAX];
__device__ float  g_sum0[D];
__device__ float  g_sq0[D];
__device__ float  g_sum1[D];
__device__ float  g_sq1[D];

// ---------------- helpers ----------------------------------------------------
__device__ __forceinline__ uint32_t smem_u32(const void* p) {
    return (uint32_t)__cvta_generic_to_shared(p);
}

__device__ __forceinline__ void ldsm4(uint32_t* r, uint32_t a) {
    asm volatile("ldmatrix.sync.aligned.m8n8.x4.shared.b16 {%0,%1,%2,%3}, [%4];"
                 : "=r"(r[0]), "=r"(r[1]), "=r"(r[2]), "=r"(r[3]) : "r"(a));
}

__device__ __forceinline__ void mma16816f(float* d, const uint32_t* a, const uint32_t* b) {
    asm volatile("mma.sync.aligned.m16n8k16.row.col.f32.f16.f16.f32 "
                 "{%0,%1,%2,%3}, {%4,%5,%6,%7}, {%8,%9}, {%0,%1,%2,%3};"
                 : "+f"(d[0]), "+f"(d[1]), "+f"(d[2]), "+f"(d[3])
                 : "r"(a[0]), "r"(a[1]), "r"(a[2]), "r"(a[3]), "r"(b[0]), "r"(b[1]));
}

// ---------------- prep: weights->fp16, x->fp16, degree hist + ranks ---------
__global__ void k_prep(const int* __restrict__ dst, int E,
                       int* __restrict__ cnt, int* __restrict__ rank,
                       const float* __restrict__ x, __half* __restrict__ xh,
                       const float* __restrict__ Wl0, const float* __restrict__ Wr0,
                       const float* __restrict__ Wl1, const float* __restrict__ Wr1,
                       const float* __restrict__ Wl2, const float* __restrict__ Wr2,
                       __half* __restrict__ W) {
    int idx = blockIdx.x * blockDim.x + threadIdx.x;
    int stride = gridDim.x * blockDim.x;

    if (idx < WTOT) {
        const int T01 = 128 * 256;
        float v;
        if (idx < T01) {
            int n = idx >> 8, k = idx & 255;
            v = (k < 128) ? __ldg(Wl0 + k * 128 + n) : __ldg(Wr0 + (k - 128) * 128 + n);
        } else if (idx < 2 * T01) {
            int l = idx - T01;
            int n = l >> 8, k = l & 255;
            v = (k < 128) ? __ldg(Wl1 + k * 128 + n) : __ldg(Wr1 + (k - 128) * 128 + n);
        } else {
            int l = idx - 2 * T01;
            int n = l >> 7, k = l & 127;
            v = (n < 64) ? __ldg(Wl2 + k * 64 + n) : __ldg(Wr2 + k * 64 + (n - 64));
        }
        W[idx] = __float2half_rn(v);
    }

    // x -> fp16 (8 elements per iteration)
    const int X8 = N_NODES * D / 8;
    for (int i = idx; i < X8; i += stride) {
        float4 u0 = __ldg(reinterpret_cast<const float4*>(x) + i * 2);
        float4 u1 = __ldg(reinterpret_cast<const float4*>(x) + i * 2 + 1);
        __half2 h[4];
        h[0] = __float22half2_rn(make_float2(u0.x, u0.y));
        h[1] = __float22half2_rn(make_float2(u0.z, u0.w));
        h[2] = __float22half2_rn(make_float2(u1.x, u1.y));
        h[3] = __float22half2_rn(make_float2(u1.z, u1.w));
        reinterpret_cast<uint4*>(xh)[i] = *reinterpret_cast<uint4*>(h);
    }

    int nQ = E >> 2;
    for (int q = idx; q < nQ; q += stride) {
        int4 d = __ldg(reinterpret_cast<const int4*>(dst) + q);
        int4 r;
        r.x = atomicAdd(&cnt[d.x], 1);
        r.y = atomicAdd(&cnt[d.y], 1);
        r.z = atomicAdd(&cnt[d.z], 1);
        r.w = atomicAdd(&cnt[d.w], 1);
        *(reinterpret_cast<int4*>(rank) + q) = r;
    }
    for (int e = nQ * 4 + idx; e < E; e += stride)
        rank[e] = atomicAdd(&cnt[__ldg(dst + e)], 1);
}

// single block, 1024 threads: exclusive scan; self-zeroes cnt for next replay
__global__ void k_scan(int* __restrict__ cnt, int* __restrict__ row_ptr) {
    constexpr int SEG = (N_NODES + 1023) / 1024;
    int t = threadIdx.x;
    int beg = t * SEG;
    int end = min(beg + SEG, N_NODES);
    int s = 0;
    for (int i = beg; i < end; i++) s += cnt[i];
    __shared__ int sh[1024];
    sh[t] = s;
    __syncthreads();
    for (int off = 1; off < 1024; off <<= 1) {
        int v = (t >= off) ? sh[t - off] : 0;
        __syncthreads();
        sh[t] += v;
        __syncthreads();
    }
    int pos = sh[t] - s;
    for (int i = beg; i < end; i++) {
        int c = cnt[i];
        row_ptr[i] = pos;
        pos += c;
        cnt[i] = 0;
    }
    if (beg < N_NODES && end == N_NODES) row_ptr[N_NODES] = pos;
}

// atomic-free fill using precomputed ranks
__global__ void k_fill(const int* __restrict__ src, const int* __restrict__ dst,
                       int E, const int* __restrict__ rank,
                       const int* __restrict__ row_ptr, int* __restrict__ csr) {
    int i = blockIdx.x * blockDim.x + threadIdx.x;
    int stride = gridDim.x * blockDim.x;
    int nQ = E >> 2;
    for (int q = i; q < nQ; q += stride) {
        int4 d = __ldg(reinterpret_cast<const int4*>(dst) + q);
        int4 s = __ldg(reinterpret_cast<const int4*>(src) + q);
        int4 r = __ldg(reinterpret_cast<const int4*>(rank) + q);
        csr[__ldg(row_ptr + d.x) + r.x] = s.x;
        csr[__ldg(row_ptr + d.y) + r.y] = s.y;
        csr[__ldg(row_ptr + d.z) + r.z] = s.z;
        csr[__ldg(row_ptr + d.w) + r.w] = s.w;
    }
    for (int e = nQ * 4 + i; e < E; e += stride)
        csr[__ldg(row_ptr + __ldg(dst + e)) + __ldg(rank + e)] = __ldg(src + e);
}

// ---------------- aggregation: fp16 gather -> fp16 mean ---------------------
// One warp per node; 2-way unroll; optional inline BN+ReLU (fp32 math).
// Block 0 zeroes the NEXT layer's stats buffers.
template <bool APPLY_BN>
__global__ __launch_bounds__(256)
void k_aggregate(const __half* __restrict__ xin, const int* __restrict__ csr,
                 const int* __restrict__ row_ptr, __half* __restrict__ M,
                 const float* __restrict__ stSum, const float* __restrict__ stSq,
                 const float* __restrict__ gamma, const float* __restrict__ beta,
                 float* __restrict__ zSum, float* __restrict__ zSq) {
    __shared__ float ssc[128], ssh[128];
    int tid = threadIdx.x;
    if (blockIdx.x == 0 && tid < 128) { zSum[tid] = 0.f; zSq[tid] = 0.f; }
    if (APPLY_BN) {
        if (tid < 128) {
            float mu = __ldg(stSum + tid) / (float)N_NODES;
            float var = __ldg(stSq + tid) / (float)N_NODES - mu * mu;
            float sc = __ldg(gamma + tid) * rsqrtf(var + BN_EPS);
            ssc[tid] = sc;
            ssh[tid] = __ldg(beta + tid) - mu * sc;
        }
        __syncthreads();
    }

    int w = (blockIdx.x * blockDim.x + tid) >> 5;
    if (w >= N_NODES) return;
    int lane = tid & 31;

    float4 sc, sh;
    if (APPLY_BN) {
        sc = *reinterpret_cast<const float4*>(ssc + lane * 4);
        sh = *reinterpret_cast<const float4*>(ssh + lane * 4);
    }

    int beg = __ldg(row_ptr + w);
    int end = __ldg(row_ptr + w + 1);
    float4 a0 = make_float4(0.f, 0.f, 0.f, 0.f);
    float4 a1 = make_float4(0.f, 0.f, 0.f, 0.f);

    int i = beg;
    for (; i + 1 < end; i += 2) {
        int s0 = __ldg(csr + i);
        int s1 = __ldg(csr + i + 1);
        uint2 u0 = __ldg(reinterpret_cast<const uint2*>(xin + (size_t)s0 * D) + lane);
        uint2 u1 = __ldg(reinterpret_cast<const uint2*>(xin + (size_t)s1 * D) + lane);
        float2 p0 = __half22float2(*reinterpret_cast<__half2*>(&u0.x));
        float2 p1 = __half22float2(*reinterpret_cast<__half2*>(&u0.y));
        float2 q0 = __half22float2(*reinterpret_cast<__half2*>(&u1.x));
        float2 q1 = __half22float2(*reinterpret_cast<__half2*>(&u1.y));
        if (APPLY_BN) {
            p0.x = fmaxf(fmaf(p0.x, sc.x, sh.x), 0.f);
            p0.y = fmaxf(fmaf(p0.y, sc.y, sh.y), 0.f);
            p1.x = fmaxf(fmaf(p1.x, sc.z, sh.z), 0.f);
            p1.y = fmaxf(fmaf(p1.y, sc.w, sh.w), 0.f);
            q0.x = fmaxf(fmaf(q0.x, sc.x, sh.x), 0.f);
            q0.y = fmaxf(fmaf(q0.y, sc.y, sh.y), 0.f);
            q1.x = fmaxf(fmaf(q1.x, sc.z, sh.z), 0.f);
            q1.y = fmaxf(fmaf(q1.y, sc.w, sh.w), 0.f);
        }
        a0.x += p0.x; a0.y += p0.y; a0.z += p1.x; a0.w += p1.y;
        a1.x += q0.x; a1.y += q0.y; a1.z += q1.x; a1.w += q1.y;
    }
    if (i < end) {
        int s0 = __ldg(csr + i);
        uint2 u0 = __ldg(reinterpret_cast<const uint2*>(xin + (size_t)s0 * D) + lane);
        float2 p0 = __half22float2(*reinterpret_cast<__half2*>(&u0.x));
        float2 p1 = __half22float2(*reinterpret_cast<__half2*>(&u0.y));
        if (APPLY_BN) {
            p0.x = fmaxf(fmaf(p0.x, sc.x, sh.x), 0.f);
            p0.y = fmaxf(fmaf(p0.y, sc.y, sh.y), 0.f);
            p1.x = fmaxf(fmaf(p1.x, sc.z, sh.z), 0.f);
            p1.y = fmaxf(fmaf(p1.y, sc.w, sh.w), 0.f);
        }
        a0.x += p0.x; a0.y += p0.y; a0.z += p1.x; a0.w += p1.y;
    }

    float inv = 1.f / (float)max(end - beg, 1);
    __half2 o[2];
    o[0] = __float22half2_rn(make_float2((a0.x + a1.x) * inv, (a0.y + a1.y) * inv));
    o[1] = __float22half2_rn(make_float2((a0.z + a1.z) * inv, (a0.w + a1.w) * inv));
    *reinterpret_cast<uint2*>(M + (size_t)w * D + lane * 4) = *reinterpret_cast<uint2*>(o);
}

// ---------------- fp16 HMMA GEMM layers 0/1 (K=256, N=128) ------------------
// A = [mean (fp16) | self (fp16, optional BN+ReLU)]; out = A @ W^T + b (fp16 store)
// Fused BN column-stat accumulation (fp32) into stOut.
template <bool HAS_BN>
__global__ __launch_bounds__(256)
void k_mma_gemm(const __half* __restrict__ M, const __half* __restrict__ selfSrc,
                const float* __restrict__ stSum, const float* __restrict__ stSq,
                const float* __restrict__ gamma, const float* __restrict__ beta,
                const __half* __restrict__ W, const float* __restrict__ bias,
                __half* __restrict__ out,
                float* __restrict__ stOutSum, float* __restrict__ stOutSq) {
    constexpr int RS = 72;
    constexpr int NT = 8;
    extern __shared__ __half sm[];
    __half* sA = sm;
    __half* sW = sm + 128 * RS;

    __shared__ float ssum[128];
    __shared__ float ssq[128];
    __shared__ float ssc[128], ssh[128];

    const int tid = threadIdx.x;
    const int lane = tid & 31;
    const int warp = tid >> 5;
    const int wr = warp & 3;
    const int wc = warp >> 2;
    const int rowBase = blockIdx.x * 128;

    if (tid < 128) { ssum[tid] = 0.f; ssq[tid] = 0.f; }
    if (HAS_BN) {
        if (tid < 128) {
            float mu = __ldg(stSum + tid) / (float)N_NODES;
            float var = __ldg(stSq + tid) / (float)N_NODES - mu * mu;
            float sc = __ldg(gamma + tid) * rsqrtf(var + BN_EPS);
            ssc[tid] = sc;
            ssh[tid] = __ldg(beta + tid) - mu * sc;
        }
        __syncthreads();
    }

    const uint32_t sbA = smem_u32(sA);
    const uint32_t sbW = smem_u32(sW);

    float acc[2][NT][4];
#pragma unroll
    for (int mt = 0; mt < 2; mt++)
#pragma unroll
        for (int nt = 0; nt < NT; nt++)
#pragma unroll
            for (int j = 0; j < 4; j++) acc[mt][nt][j] = 0.f;

    for (int stage = 0; stage < 4; stage++) {
        // A tile: stages 0-1 from mean fp16; stages 2-3 from self fp16 (+BN)
#pragma unroll
        for (int t = 0; t < 4; t++) {
            int idx = tid + t * 256;
            int r = idx >> 3, c = idx & 7;
            int row = rowBase + r;
            uint4 u = make_uint4(0, 0, 0, 0);
            if (stage < 2) {
                if (row < N_NODES)
                    u = __ldg(reinterpret_cast<const uint4*>(M + (size_t)row * D + stage * 64) + c);
            } else {
                int col0 = (stage - 2) * 64 + c * 8;
                if (row < N_NODES) {
                    u = __ldg(reinterpret_cast<const uint4*>(selfSrc + (size_t)row * D + col0));
                    if (HAS_BN) {
                        __half2* hp = reinterpret_cast<__half2*>(&u);
#pragma unroll
                        for (int j = 0; j < 4; j++) {
                            float2 f = __half22float2(hp[j]);
                            f.x = fmaxf(fmaf(f.x, ssc[col0 + 2 * j], ssh[col0 + 2 * j]), 0.f);
                            f.y = fmaxf(fmaf(f.y, ssc[col0 + 2 * j + 1], ssh[col0 + 2 * j + 1]), 0.f);
                            hp[j] = __float22half2_rn(f);
                        }
                    }
                }
            }
            *reinterpret_cast<uint4*>(sA + r * RS + c * 8) = u;
        }
#pragma unroll
        for (int t = 0; t < 4; t++) {
            int idx = tid + t * 256;
            int n = idx >> 3, c = idx & 7;
            uint4 v = __ldg(reinterpret_cast<const uint4*>(W + (size_t)n * 256 + stage * 64) + c);
            *reinterpret_cast<uint4*>(sW + n * RS + c * 8) = v;
        }
        __syncthreads();

#pragma unroll
        for (int ks = 0; ks < 4; ks++) {
            const uint32_t koff = (uint32_t)(ks * 16 + (lane >> 4) * 8) * 2;
            uint32_t a[2][4];
#pragma unroll
            for (int mt = 0; mt < 2; mt++) {
                uint32_t roff = (uint32_t)(wr * 32 + mt * 16 + (lane & 15)) * (RS * 2) + koff;
                ldsm4(a[mt], sbA + roff);
            }
            uint32_t b[NT][2];
#pragma unroll
            for (int g = 0; g < NT / 2; g++) {
                uint32_t roff = (uint32_t)(wc * 64 + g * 16 + (lane & 15)) * (RS * 2) + koff;
                uint32_t r[4];
                ldsm4(r, sbW + roff);
                b[2 * g][0] = r[0]; b[2 * g][1] = r[2];
                b[2 * g + 1][0] = r[1]; b[2 * g + 1][1] = r[3];
            }
#pragma unroll
            for (int mt = 0; mt < 2; mt++)
#pragma unroll
                for (int nt = 0; nt < NT; nt++)
                    mma16816f(acc[mt][nt], a[mt], b[nt]);
        }
        __syncthreads();
    }

#pragma unroll
    for (int nt = 0; nt < NT; nt++) {
        int col = wc * 64 + nt * 8 + (lane & 3) * 2;
        float2 bb = *reinterpret_cast<const float2*>(bias + col);
        float s0 = 0.f, s1 = 0.f, q0 = 0.f, q1 = 0.f;
#pragma unroll
        for (int mt = 0; mt < 2; mt++) {
            int r0 = rowBase + wr * 32 + mt * 16 + (lane >> 2);
            float v0 = acc[mt][nt][0] + bb.x, v1 = acc[mt][nt][1] + bb.y;
            float v2 = acc[mt][nt][2] + bb.x, v3 = acc[mt][nt][3] + bb.y;
            if (r0 < N_NODES) {
                *reinterpret_cast<__half2*>(out + (size_t)r0 * 128 + col) =
                    __float22half2_rn(make_float2(v0, v1));
                s0 += v0; s1 += v1; q0 += v0 * v0; q1 += v1 * v1;
            }
            if (r0 + 8 < N_NODES) {
                *reinterpret_cast<__half2*>(out + (size_t)(r0 + 8) * 128 + col) =
                    __float22half2_rn(make_float2(v2, v3));
                s0 += v2; s1 += v3; q0 += v2 * v2; q1 += v3 * v3;
            }
        }
#pragma unroll
        for (int off = 4; off < 32; off <<= 1) {
            s0 += __shfl_down_sync(0xffffffffu, s0, off);
            s1 += __shfl_down_sync(0xffffffffu, s1, off);
            q0 += __shfl_down_sync(0xffffffffu, q0, off);
            q1 += __shfl_down_sync(0xffffffffu, q1, off);
        }
        if ((lane >> 2) == 0) {
            atomicAdd(&ssum[col], s0); atomicAdd(&ssum[col + 1], s1);
            atomicAdd(&ssq[col], q0);  atomicAdd(&ssq[col + 1], q1);
        }
    }
    __syncthreads();
    if (tid < 128) {
        atomicAdd(&stOutSum[tid], ssum[tid]);
        atomicAdd(&stOutSq[tid], ssq[tid]);
    }
}

// ---------------- layer-2 GEMM: [z|s] = relu(bn(h1)) @ [Wl2|Wr2]^T (fp16) ---
__global__ __launch_bounds__(256)
void k_gemm_l2(const __half* __restrict__ hin,
               const float* __restrict__ stSum, const float* __restrict__ stSq,
               const float* __restrict__ gamma, const float* __restrict__ beta,
               const __half* __restrict__ W, __half* __restrict__ zout) {
    constexpr int RS = 72;
    constexpr int NT = 8;
    extern __shared__ __half sm[];
    __half* sA = sm;
    __half* sW = sm + 128 * RS;

    __shared__ float ssc[128], ssh[128];

    const int tid = threadIdx.x;
    const int lane = tid & 31;
    const int warp = tid >> 5;
    const int wr = warp & 3;
    const int wc = warp >> 2;
    const int rowBase = blockIdx.x * 128;

    if (tid < 128) {
        float mu = __ldg(stSum + tid) / (float)N_NODES;
        float var = __ldg(stSq + tid) / (float)N_NODES - mu * mu;
        float sc = __ldg(gamma + tid) * rsqrtf(var + BN_EPS);
        ssc[tid] = sc;
        ssh[tid] = __ldg(beta + tid) - mu * sc;
    }
    __syncthreads();

    const uint32_t sbA = smem_u32(sA);
    const uint32_t sbW = smem_u32(sW);

    float acc[2][NT][4];
#pragma unroll
    for (int mt = 0; mt < 2; mt++)
#pragma unroll
        for (int nt = 0; nt < NT; nt++)
#pragma unroll
            for (int j = 0; j < 4; j++) acc[mt][nt][j] = 0.f;

    for (int stage = 0; stage < 2; stage++) {
#pragma unroll
        for (int t = 0; t < 4; t++) {
            int idx = tid + t * 256;
            int r = idx >> 3, c = idx & 7;
            int row = rowBase + r;
            int col0 = stage * 64 + c * 8;
            uint4 u = make_uint4(0, 0, 0, 0);
            if (row < N_NODES) {
                u = __ldg(reinterpret_cast<const uint4*>(hin + (size_t)row * D + col0));
                __half2* hp = reinterpret_cast<__half2*>(&u);
#pragma unroll
                for (int j = 0; j < 4; j++) {
                    float2 f = __half22float2(hp[j]);
                    f.x = fmaxf(fmaf(f.x, ssc[col0 + 2 * j], ssh[col0 + 2 * j]), 0.f);
                    f.y = fmaxf(fmaf(f.y, ssc[col0 + 2 * j + 1], ssh[col0 + 2 * j + 1]), 0.f);
                    hp[j] = __float22half2_rn(f);
                }
            }
            *reinterpret_cast<uint4*>(sA + r * RS + c * 8) = u;
        }
#pragma unroll
        for (int t = 0; t < 4; t++) {
            int idx = tid + t * 256;
            int n = idx >> 3, c = idx & 7;
            uint4 v = __ldg(reinterpret_cast<const uint4*>(W + (size_t)n * 128 + stage * 64) + c);
            *reinterpret_cast<uint4*>(sW + n * RS + c * 8) = v;
        }
        __syncthreads();

#pragma unroll
        for (int ks = 0; ks < 4; ks++) {
            const uint32_t koff = (uint32_t)(ks * 16 + (lane >> 4) * 8) * 2;
            uint32_t a[2][4];
#pragma unroll
            for (int mt = 0; mt < 2; mt++) {
                uint32_t roff = (uint32_t)(wr * 32 + mt * 16 + (lane & 15)) * (RS * 2) + koff;
                ldsm4(a[mt], sbA + roff);
            }
            uint32_t b[NT][2];
#pragma unroll
            for (int g = 0; g < NT / 2; g++) {
                uint32_t roff = (uint32_t)(wc * 64 + g * 16 + (lane & 15)) * (RS * 2) + koff;
                uint32_t r[4];
                ldsm4(r, sbW + roff);
                b[2 * g][0] = r[0]; b[2 * g][1] = r[2];
                b[2 * g + 1][0] = r[1]; b[2 * g + 1][1] = r[3];
            }
#pragma unroll
            for (int mt = 0; mt < 2; mt++)
#pragma unroll
                for (int nt = 0; nt < NT; nt++)
                    mma16816f(acc[mt][nt], a[mt], b[nt]);
        }
        __syncthreads();
    }

#pragma unroll
    for (int nt = 0; nt < NT; nt++) {
        int col = wc * 64 + nt * 8 + (lane & 3) * 2;
#pragma unroll
        for (int mt = 0; mt < 2; mt++) {
            int r0 = rowBase + wr * 32 + mt * 16 + (lane >> 2);
            if (r0 < N_NODES)
                *reinterpret_cast<__half2*>(zout + (size_t)r0 * 128 + col) =
                    __float22half2_rn(make_float2(acc[mt][nt][0], acc[mt][nt][1]));
            if (r0 + 8 < N_NODES)
                *reinterpret_cast<__half2*>(zout + (size_t)(r0 + 8) * 128 + col) =
                    __float22half2_rn(make_float2(acc[mt][nt][2], acc[mt][nt][3]));
        }
    }
}

// ---------------- final: out = log_softmax(mean(z[src]) + s + b2) -----------
// zs rows (fp16): [z (cols 0..63) | s (cols 64..127)]; warp per node.
__global__ __launch_bounds__(256)
void k_final(const __half* __restrict__ zs, const int* __restrict__ csr,
             const int* __restrict__ row_ptr, const float* __restrict__ b2,
             float* __restrict__ out) {
    int w = (blockIdx.x * blockDim.x + threadIdx.x) >> 5;
    if (w >= N_NODES) return;
    int lane = threadIdx.x & 31;
    int beg = __ldg(row_ptr + w);
    int end = __ldg(row_ptr + w + 1);
    float2 a0 = make_float2(0.f, 0.f), a1 = make_float2(0.f, 0.f);
    int i = beg;
    for (; i + 1 < end; i += 2) {
        int s0 = __ldg(csr + i);
        int s1 = __ldg(csr + i + 1);
        float2 v0 = __half22float2(__ldg(reinterpret_cast<const __half2*>(zs + (size_t)s0 * 128) + lane));
        float2 v1 = __half22float2(__ldg(reinterpret_cast<const __half2*>(zs + (size_t)s1 * 128) + lane));
        a0.x += v0.x; a0.y += v0.y;
        a1.x += v1.x; a1.y += v1.y;
    }
    if (i < end) {
        int s0 = __ldg(csr + i);
        float2 v0 = __half22float2(__ldg(reinterpret_cast<const __half2*>(zs + (size_t)s0 * 128) + lane));
        a0.x += v0.x; a0.y += v0.y;
    }
    float inv = 1.f / (float)max(end - beg, 1);
    float2 sv = __half22float2(__ldg(reinterpret_cast<const __half2*>(zs + (size_t)w * 128 + 64) + lane));
    float2 bb = __ldg(reinterpret_cast<const float2*>(b2) + lane);
    float v0 = (a0.x + a1.x) * inv + sv.x + bb.x;
    float v1 = (a0.y + a1.y) * inv + sv.y + bb.y;
    float m = fmaxf(v0, v1);
#pragma unroll
    for (int o = 16; o > 0; o >>= 1) m = fmaxf(m, __shfl_xor_sync(0xffffffffu, m, o));
    float e = expf(v0 - m) + expf(v1 - m);
#pragma unroll
    for (int o = 16; o > 0; o >>= 1) e += __shfl_xor_sync(0xffffffffu, e, o);
    float l = m + logf(e);
    *(reinterpret_cast<float2*>(out + (size_t)w * D_OUT) + lane) = make_float2(v0 - l, v1 - l);
}

// ---------------- launch ----------------------------------------------------
extern "C" void kernel_launch(void* const* d_in, const int* in_sizes, int n_in,
                              void* d_out, int out_size) {
    const float* x   = (const float*)d_in[0];
    const int* ei    = (const int*)d_in[1];
    const float* Wl0 = (const float*)d_in[2];
    const float* Wr0 = (const float*)d_in[3];
    const float* b0  = (const float*)d_in[4];
    const float* g0  = (const float*)d_in[5];
    const float* be0 = (const float*)d_in[6];
    const float* Wl1 = (const float*)d_in[7];
    const float* Wr1 = (const float*)d_in[8];
    const float* b1  = (const float*)d_in[9];
    const float* g1  = (const float*)d_in[10];
    const float* be1 = (const float*)d_in[11];
    const float* Wl2 = (const float*)d_in[12];
    const float* Wr2 = (const float*)d_in[13];
    const float* b2  = (const float*)d_in[14];
    float* out = (float*)d_out;

    const int E = in_sizes[1] / 2;
    const int* src = ei;
    const int* dst = ei + E;

    __half *xh, *M, *W, *h0, *h1;
    float *sum0, *sq0, *sum1, *sq1;
    int *cnti, *rowptr, *rank, *csr;
    cudaGetSymbolAddress((void**)&xh, g_xh);
    cudaGetSymbolAddress((void**)&M, g_M);
    cudaGetSymbolAddress((void**)&W, g_W);
    cudaGetSymbolAddress((void**)&h0, g_h0);
    cudaGetSymbolAddress((void**)&h1, g_h1);
    cudaGetSymbolAddress((void**)&cnti, g_cnti);
    cudaGetSymbolAddress((void**)&rowptr, g_rowptr);
    cudaGetSymbolAddress((void**)&rank, g_rank);
    cudaGetSymbolAddress((void**)&csr, g_csr);
    cudaGetSymbolAddress((void**)&sum0, g_sum0);
    cudaGetSymbolAddress((void**)&sq0, g_sq0);
    cudaGetSymbolAddress((void**)&sum1, g_sum1);
    cudaGetSymbolAddress((void**)&sq1, g_sq1);

    constexpr int RS = 72;
    const int SMEM = (128 + 128) * RS * 2;  // 36864 bytes
    cudaFuncSetAttribute((const void*)k_mma_gemm<false>, cudaFuncAttributeMaxDynamicSharedMemorySize, SMEM);
    cudaFuncSetAttribute((const void*)k_mma_gemm<true>,  cudaFuncAttributeMaxDynamicSharedMemorySize, SMEM);
    cudaFuncSetAttribute((const void*)k_gemm_l2, cudaFuncAttributeMaxDynamicSharedMemorySize, SMEM);

    const int aggBlocks  = (N_NODES * 32 + 255) / 256;
    const int gemmBlocks = (N_NODES + 127) / 128;

    __half* W0 = W;
    __half* W1 = W + 128 * 256;
    __half* W2 = W + 256 * 256;

    // ---- prep: weights + x->fp16 + CSR ----
    k_prep<<<512, 256>>>(dst, E, cnti, rank, x, xh,
                         Wl0, Wr0, Wl1, Wr1, Wl2, Wr2, W);
    k_scan<<<1, 1024>>>(cnti, rowptr);
    k_fill<<<512, 256>>>(src, dst, E, rank, rowptr, csr);

    // ---- layer 0 ----
    k_aggregate<false><<<aggBlocks, 256>>>(xh, csr, rowptr, M,
                                           nullptr, nullptr, nullptr, nullptr, sum0, sq0);
    k_mma_gemm<false><<<gemmBlocks, 256, SMEM>>>(M, xh,
                                                 nullptr, nullptr, nullptr, nullptr,
                                                 W0, b0, h0, sum0, sq0);

    // ---- layer 1 (BN0+ReLU fused into aggregation and GEMM self-half) ----
    k_aggregate<true><<<aggBlocks, 256>>>(h0, csr, rowptr, M,
                                          sum0, sq0, g0, be0, sum1, sq1);
    k_mma_gemm<true><<<gemmBlocks, 256, SMEM>>>(M, h0,
                                                sum0, sq0, g0, be0,
                                                W1, b1, h1, sum1, sq1);

    // ---- layer 2 (commuted: GEMM first with BN1 inline, then fp16 gather) ----
    k_gemm_l2<<<gemmBlocks, 256, SMEM>>>(h1, sum1, sq1, g1, be1, W2, h0);
    k_final<<<aggBlocks, 256>>>(h0, csr, rowptr, b2, out);
}

// round 12
// speedup vs baseline: 1.3875x; 1.1265x over previous
#include <cuda_runtime.h>
#include <cuda_fp16.h>
#include <cstdint>

#define N_NODES 50000
#define E_MAX   800000
#define D 128
#define D_OUT 64
#define BN_EPS 1e-5f
#define WTOT (2 * 128 * 256 + 128 * 128)

// ---------------- scratch (device globals; no allocation allowed) ----------
__device__ __half g_xh[(size_t)N_NODES * D];   // fp16 copy of x
__device__ __half g_M[(size_t)N_NODES * D];    // neighbor mean (fp16)
__device__ __half g_W[WTOT];                   // fp16 weights (all layers, transposed)
__device__ __half g_h0[(size_t)N_NODES * D];   // layer0 out; later reused for [z2|s2]
__device__ __half g_h1[(size_t)N_NODES * D];
__device__ int    g_cnti[N_NODES];
__device__ int    g_rowptr[N_NODES + 1];
__device__ int    g_rank[E_MAX];
__device__ int    g_csr[E_MAX];
__device__ float  g_sum0[D];
__device__ float  g_sq0[D];
__device__ float  g_sum1[D];
__device__ float  g_sq1[D];

// ---------------- helpers ----------------------------------------------------
__device__ __forceinline__ uint32_t smem_u32(const void* p) {
    return (uint32_t)__cvta_generic_to_shared(p);
}

__device__ __forceinline__ void ldsm4(uint32_t* r, uint32_t a) {
    asm volatile("ldmatrix.sync.aligned.m8n8.x4.shared.b16 {%0,%1,%2,%3}, [%4];"
                 : "=r"(r[0]), "=r"(r[1]), "=r"(r[2]), "=r"(r[3]) : "r"(a));
}

__device__ __forceinline__ void mma16816f(float* d, const uint32_t* a, const uint32_t* b) {
    asm volatile("mma.sync.aligned.m16n8k16.row.col.f32.f16.f16.f32 "
                 "{%0,%1,%2,%3}, {%4,%5,%6,%7}, {%8,%9}, {%0,%1,%2,%3};"
                 : "+f"(d[0]), "+f"(d[1]), "+f"(d[2]), "+f"(d[3])
                 : "r"(a[0]), "r"(a[1]), "r"(a[2]), "r"(a[3]), "r"(b[0]), "r"(b[1]));
}

// ---------------- prep: weights->fp16, x->fp16, degree hist + ranks ---------
__global__ void k_prep(const int* __restrict__ dst, int E,
                       int* __restrict__ cnt, int* __restrict__ rank,
                       const float* __restrict__ x, __half* __restrict__ xh,
                       const float* __restrict__ Wl0, const float* __restrict__ Wr0,
                       const float* __restrict__ Wl1, const float* __restrict__ Wr1,
                       const float* __restrict__ Wl2, const float* __restrict__ Wr2,
                       __half* __restrict__ W) {
    int idx = blockIdx.x * blockDim.x + threadIdx.x;
    int stride = gridDim.x * blockDim.x;

    if (idx < WTOT) {
        const int T01 = 128 * 256;
        float v;
        if (idx < T01) {
            int n = idx >> 8, k = idx & 255;
            v = (k < 128) ? __ldg(Wl0 + k * 128 + n) : __ldg(Wr0 + (k - 128) * 128 + n);
        } else if (idx < 2 * T01) {
            int l = idx - T01;
            int n = l >> 8, k = l & 255;
            v = (k < 128) ? __ldg(Wl1 + k * 128 + n) : __ldg(Wr1 + (k - 128) * 128 + n);
        } else {
            int l = idx - 2 * T01;
            int n = l >> 7, k = l & 127;
            v = (n < 64) ? __ldg(Wl2 + k * 64 + n) : __ldg(Wr2 + k * 64 + (n - 64));
        }
        W[idx] = __float2half_rn(v);
    }

    // x -> fp16 (8 elements per iteration)
    const int X8 = N_NODES * D / 8;
    for (int i = idx; i < X8; i += stride) {
        float4 u0 = __ldg(reinterpret_cast<const float4*>(x) + i * 2);
        float4 u1 = __ldg(reinterpret_cast<const float4*>(x) + i * 2 + 1);
        __half2 h[4];
        h[0] = __float22half2_rn(make_float2(u0.x, u0.y));
        h[1] = __float22half2_rn(make_float2(u0.z, u0.w));
        h[2] = __float22half2_rn(make_float2(u1.x, u1.y));
        h[3] = __float22half2_rn(make_float2(u1.z, u1.w));
        reinterpret_cast<uint4*>(xh)[i] = *reinterpret_cast<uint4*>(h);
    }

    int nQ = E >> 2;
    for (int q = idx; q < nQ; q += stride) {
        int4 d = __ldg(reinterpret_cast<const int4*>(dst) + q);
        int4 r;
        r.x = atomicAdd(&cnt[d.x], 1);
        r.y = atomicAdd(&cnt[d.y], 1);
        r.z = atomicAdd(&cnt[d.z], 1);
        r.w = atomicAdd(&cnt[d.w], 1);
        *(reinterpret_cast<int4*>(rank) + q) = r;
    }
    for (int e = nQ * 4 + idx; e < E; e += stride)
        rank[e] = atomicAdd(&cnt[__ldg(dst + e)], 1);
}

// single block, 1024 threads: exclusive scan; self-zeroes cnt for next replay
__global__ void k_scan(int* __restrict__ cnt, int* __restrict__ row_ptr) {
    constexpr int SEG = (N_NODES + 1023) / 1024;
    int t = threadIdx.x;
    int beg = t * SEG;
    int end = min(beg + SEG, N_NODES);
    int s = 0;
    for (int i = beg; i < end; i++) s += cnt[i];
    __shared__ int sh[1024];
    sh[t] = s;
    __syncthreads();
    for (int off = 1; off < 1024; off <<= 1) {
        int v = (t >= off) ? sh[t - off] : 0;
        __syncthreads();
        sh[t] += v;
        __syncthreads();
    }
    int pos = sh[t] - s;
    for (int i = beg; i < end; i++) {
        int c = cnt[i];
        row_ptr[i] = pos;
        pos += c;
        cnt[i] = 0;
    }
    if (beg < N_NODES && end == N_NODES) row_ptr[N_NODES] = pos;
}

// atomic-free fill using precomputed ranks
__global__ void k_fill(const int* __restrict__ src, const int* __restrict__ dst,
                       int E, const int* __restrict__ rank,
                       const int* __restrict__ row_ptr, int* __restrict__ csr) {
    int i = blockIdx.x * blockDim.x + threadIdx.x;
    int stride = gridDim.x * blockDim.x;
    int nQ = E >> 2;
    for (int q = i; q < nQ; q += stride) {
        int4 d = __ldg(reinterpret_cast<const int4*>(dst) + q);
        int4 s = __ldg(reinterpret_cast<const int4*>(src) + q);
        int4 r = __ldg(reinterpret_cast<const int4*>(rank) + q);
        csr[__ldg(row_ptr + d.x) + r.x] = s.x;
        csr[__ldg(row_ptr + d.y) + r.y] = s.y;
        csr[__ldg(row_ptr + d.z) + r.z] = s.z;
        csr[__ldg(row_ptr + d.w) + r.w] = s.w;
    }
    for (int e = nQ * 4 + i; e < E; e += stride)
        csr[__ldg(row_ptr + __ldg(dst + e)) + __ldg(rank + e)] = __ldg(src + e);
}

// ---------------- aggregation: fp16 gather (pairwise HADD2) -> fp16 mean ----
// One warp per node; block 0 zeroes the given stats buffers.
__global__ __launch_bounds__(256)
void k_aggregate(const __half* __restrict__ xin, const int* __restrict__ csr,
                 const int* __restrict__ row_ptr, __half* __restrict__ M,
                 float* __restrict__ zSum, float* __restrict__ zSq) {
    int tid = threadIdx.x;
    if (blockIdx.x == 0 && tid < 128) { zSum[tid] = 0.f; zSq[tid] = 0.f; }

    int w = (blockIdx.x * blockDim.x + tid) >> 5;
    if (w >= N_NODES) return;
    int lane = tid & 31;

    int beg = __ldg(row_ptr + w);
    int end = __ldg(row_ptr + w + 1);
    float4 acc = make_float4(0.f, 0.f, 0.f, 0.f);

    int i = beg;
    for (; i + 1 < end; i += 2) {
        int s0 = __ldg(csr + i);
        int s1 = __ldg(csr + i + 1);
        uint2 u0 = __ldg(reinterpret_cast<const uint2*>(xin + (size_t)s0 * D) + lane);
        uint2 u1 = __ldg(reinterpret_cast<const uint2*>(xin + (size_t)s1 * D) + lane);
        __half2 p0 = __hadd2(*reinterpret_cast<__half2*>(&u0.x), *reinterpret_cast<__half2*>(&u1.x));
        __half2 p1 = __hadd2(*reinterpret_cast<__half2*>(&u0.y), *reinterpret_cast<__half2*>(&u1.y));
        float2 f0 = __half22float2(p0);
        float2 f1 = __half22float2(p1);
        acc.x += f0.x; acc.y += f0.y; acc.z += f1.x; acc.w += f1.y;
    }
    if (i < end) {
        int s0 = __ldg(csr + i);
        uint2 u0 = __ldg(reinterpret_cast<const uint2*>(xin + (size_t)s0 * D) + lane);
        float2 f0 = __half22float2(*reinterpret_cast<__half2*>(&u0.x));
        float2 f1 = __half22float2(*reinterpret_cast<__half2*>(&u0.y));
        acc.x += f0.x; acc.y += f0.y; acc.z += f1.x; acc.w += f1.y;
    }

    float inv = 1.f / (float)max(end - beg, 1);
    __half2 o[2];
    o[0] = __float22half2_rn(make_float2(acc.x * inv, acc.y * inv));
    o[1] = __float22half2_rn(make_float2(acc.z * inv, acc.w * inv));
    *reinterpret_cast<uint2*>(M + (size_t)w * D + lane * 4) = *reinterpret_cast<uint2*>(o);
}

// ---------------- BN+ReLU in place on fp16 h ---------------------------------
__global__ __launch_bounds__(256)
void k_bn_apply(__half* __restrict__ h,
                const float* __restrict__ stSum, const float* __restrict__ stSq,
                const float* __restrict__ gamma, const float* __restrict__ beta) {
    __shared__ float ssc[128], ssh[128];
    int tid = threadIdx.x;
    if (tid < 128) {
        float mu = __ldg(stSum + tid) / (float)N_NODES;
        float var = __ldg(stSq + tid) / (float)N_NODES - mu * mu;
        float sc = __ldg(gamma + tid) * rsqrtf(var + BN_EPS);
        ssc[tid] = sc;
        ssh[tid] = __ldg(beta + tid) - mu * sc;
    }
    __syncthreads();

    const int T8 = N_NODES * D / 8;
    for (int i = blockIdx.x * blockDim.x + tid; i < T8; i += gridDim.x * blockDim.x) {
        int c8 = (i & 15) * 8;
        uint4 u = *(reinterpret_cast<uint4*>(h) + i);
        __half2* hp = reinterpret_cast<__half2*>(&u);
#pragma unroll
        for (int j = 0; j < 4; j++) {
            float2 f = __half22float2(hp[j]);
            f.x = fmaxf(fmaf(f.x, ssc[c8 + 2 * j], ssh[c8 + 2 * j]), 0.f);
            f.y = fmaxf(fmaf(f.y, ssc[c8 + 2 * j + 1], ssh[c8 + 2 * j + 1]), 0.f);
            hp[j] = __float22half2_rn(f);
        }
        *(reinterpret_cast<uint4*>(h) + i) = u;
    }
}

// ---------------- fp16 HMMA GEMM layers 0/1 (K=256, N=128) ------------------
// A = [mean (fp16) | self (fp16, already BN'd)]; out = A@W^T + b (fp16 store)
// Fused BN column-stat accumulation (fp32) into stOut.
__global__ __launch_bounds__(256)
void k_mma_gemm(const __half* __restrict__ M, const __half* __restrict__ selfSrc,
                const __half* __restrict__ W, const float* __restrict__ bias,
                __half* __restrict__ out,
                float* __restrict__ stOutSum, float* __restrict__ stOutSq) {
    constexpr int RS = 72;
    constexpr int NT = 8;
    extern __shared__ __half sm[];
    __half* sA = sm;
    __half* sW = sm + 128 * RS;

    __shared__ float ssum[128];
    __shared__ float ssq[128];

    const int tid = threadIdx.x;
    const int lane = tid & 31;
    const int warp = tid >> 5;
    const int wr = warp & 3;
    const int wc = warp >> 2;
    const int rowBase = blockIdx.x * 128;

    if (tid < 128) { ssum[tid] = 0.f; ssq[tid] = 0.f; }

    const uint32_t sbA = smem_u32(sA);
    const uint32_t sbW = smem_u32(sW);

    float acc[2][NT][4];
#pragma unroll
    for (int mt = 0; mt < 2; mt++)
#pragma unroll
        for (int nt = 0; nt < NT; nt++)
#pragma unroll
            for (int j = 0; j < 4; j++) acc[mt][nt][j] = 0.f;

    for (int stage = 0; stage < 4; stage++) {
        const __half* Asrc = (stage < 2) ? M : selfSrc;
        const int colBase = (stage & 1) * 64;
#pragma unroll
        for (int t = 0; t < 4; t++) {
            int idx = tid + t * 256;
            int r = idx >> 3, c = idx & 7;
            int row = rowBase + r;
            uint4 u = make_uint4(0, 0, 0, 0);
            if (row < N_NODES)
                u = __ldg(reinterpret_cast<const uint4*>(Asrc + (size_t)row * D + colBase) + c);
            *reinterpret_cast<uint4*>(sA + r * RS + c * 8) = u;
        }
#pragma unroll
        for (int t = 0; t < 4; t++) {
            int idx = tid + t * 256;
            int n = idx >> 3, c = idx & 7;
            uint4 v = __ldg(reinterpret_cast<const uint4*>(W + (size_t)n * 256 + stage * 64) + c);
            *reinterpret_cast<uint4*>(sW + n * RS + c * 8) = v;
        }
        __syncthreads();

#pragma unroll
        for (int ks = 0; ks < 4; ks++) {
            const uint32_t koff = (uint32_t)(ks * 16 + (lane >> 4) * 8) * 2;
            uint32_t a[2][4];
#pragma unroll
            for (int mt = 0; mt < 2; mt++) {
                uint32_t roff = (uint32_t)(wr * 32 + mt * 16 + (lane & 15)) * (RS * 2) + koff;
                ldsm4(a[mt], sbA + roff);
            }
            uint32_t b[NT][2];
#pragma unroll
            for (int g = 0; g < NT / 2; g++) {
                uint32_t roff = (uint32_t)(wc * 64 + g * 16 + (lane & 15)) * (RS * 2) + koff;
                uint32_t r[4];
                ldsm4(r, sbW + roff);
                b[2 * g][0] = r[0]; b[2 * g][1] = r[2];
                b[2 * g + 1][0] = r[1]; b[2 * g + 1][1] = r[3];
            }
#pragma unroll
            for (int mt = 0; mt < 2; mt++)
#pragma unroll
                for (int nt = 0; nt < NT; nt++)
                    mma16816f(acc[mt][nt], a[mt], b[nt]);
        }
        __syncthreads();
    }

#pragma unroll
    for (int nt = 0; nt < NT; nt++) {
        int col = wc * 64 + nt * 8 + (lane & 3) * 2;
        float2 bb = *reinterpret_cast<const float2*>(bias + col);
        float s0 = 0.f, s1 = 0.f, q0 = 0.f, q1 = 0.f;
#pragma unroll
        for (int mt = 0; mt < 2; mt++) {
            int r0 = rowBase + wr * 32 + mt * 16 + (lane >> 2);
            float v0 = acc[mt][nt][0] + bb.x, v1 = acc[mt][nt][1] + bb.y;
            float v2 = acc[mt][nt][2] + bb.x, v3 = acc[mt][nt][3] + bb.y;
            if (r0 < N_NODES) {
                *reinterpret_cast<__half2*>(out + (size_t)r0 * 128 + col) =
                    __float22half2_rn(make_float2(v0, v1));
                s0 += v0; s1 += v1; q0 += v0 * v0; q1 += v1 * v1;
            }
            if (r0 + 8 < N_NODES) {
                *reinterpret_cast<__half2*>(out + (size_t)(r0 + 8) * 128 + col) =
                    __float22half2_rn(make_float2(v2, v3));
                s0 += v2; s1 += v3; q0 += v2 * v2; q1 += v3 * v3;
            }
        }
#pragma unroll
        for (int off = 4; off < 32; off <<= 1) {
            s0 += __shfl_down_sync(0xffffffffu, s0, off);
            s1 += __shfl_down_sync(0xffffffffu, s1, off);
            q0 += __shfl_down_sync(0xffffffffu, q0, off);
            q1 += __shfl_down_sync(0xffffffffu, q1, off);
        }
        if ((lane >> 2) == 0) {
            atomicAdd(&ssum[col], s0); atomicAdd(&ssum[col + 1], s1);
            atomicAdd(&ssq[col], q0);  atomicAdd(&ssq[col + 1], q1);
        }
    }
    __syncthreads();
    if (tid < 128) {
        atomicAdd(&stOutSum[tid], ssum[tid]);
        atomicAdd(&stOutSq[tid], ssq[tid]);
    }
}

// ---------------- layer-2 GEMM: [z|s] = h1bn @ [Wl2|Wr2]^T (fp16) -----------
__global__ __launch_bounds__(256)
void k_gemm_l2(const __half* __restrict__ hin, const __half* __restrict__ W,
               __half* __restrict__ zout) {
    constexpr int RS = 72;
    constexpr int NT = 8;
    extern __shared__ __half sm[];
    __half* sA = sm;
    __half* sW = sm + 128 * RS;

    const int tid = threadIdx.x;
    const int lane = tid & 31;
    const int warp = tid >> 5;
    const int wr = warp & 3;
    const int wc = warp >> 2;
    const int rowBase = blockIdx.x * 128;

    const uint32_t sbA = smem_u32(sA);
    const uint32_t sbW = smem_u32(sW);

    float acc[2][NT][4];
#pragma unroll
    for (int mt = 0; mt < 2; mt++)
#pragma unroll
        for (int nt = 0; nt < NT; nt++)
#pragma unroll
            for (int j = 0; j < 4; j++) acc[mt][nt][j] = 0.f;

    for (int stage = 0; stage < 2; stage++) {
#pragma unroll
        for (int t = 0; t < 4; t++) {
            int idx = tid + t * 256;
            int r = idx >> 3, c = idx & 7;
            int row = rowBase + r;
            uint4 u = make_uint4(0, 0, 0, 0);
            if (row < N_NODES)
                u = __ldg(reinterpret_cast<const uint4*>(hin + (size_t)row * D + stage * 64) + c);
            *reinterpret_cast<uint4*>(sA + r * RS + c * 8) = u;
        }
#pragma unroll
        for (int t = 0; t < 4; t++) {
            int idx = tid + t * 256;
            int n = idx >> 3, c = idx & 7;
            uint4 v = __ldg(reinterpret_cast<const uint4*>(W + (size_t)n * 128 + stage * 64) + c);
            *reinterpret_cast<uint4*>(sW + n * RS + c * 8) = v;
        }
        __syncthreads();

#pragma unroll
        for (int ks = 0; ks < 4; ks++) {
            const uint32_t koff = (uint32_t)(ks * 16 + (lane >> 4) * 8) * 2;
            uint32_t a[2][4];
#pragma unroll
            for (int mt = 0; mt < 2; mt++) {
                uint32_t roff = (uint32_t)(wr * 32 + mt * 16 + (lane & 15)) * (RS * 2) + koff;
                ldsm4(a[mt], sbA + roff);
            }
            uint32_t b[NT][2];
#pragma unroll
            for (int g = 0; g < NT / 2; g++) {
                uint32_t roff = (uint32_t)(wc * 64 + g * 16 + (lane & 15)) * (RS * 2) + koff;
                uint32_t r[4];
                ldsm4(r, sbW + roff);
                b[2 * g][0] = r[0]; b[2 * g][1] = r[2];
                b[2 * g + 1][0] = r[1]; b[2 * g + 1][1] = r[3];
            }
#pragma unroll
            for (int mt = 0; mt < 2; mt++)
#pragma unroll
                for (int nt = 0; nt < NT; nt++)
                    mma16816f(acc[mt][nt], a[mt], b[nt]);
        }
        __syncthreads();
    }

#pragma unroll
    for (int nt = 0; nt < NT; nt++) {
        int col = wc * 64 + nt * 8 + (lane & 3) * 2;
#pragma unroll
        for (int mt = 0; mt < 2; mt++) {
            int r0 = rowBase + wr * 32 + mt * 16 + (lane >> 2);
            if (r0 < N_NODES)
                *reinterpret_cast<__half2*>(zout + (size_t)r0 * 128 + col) =
                    __float22half2_rn(make_float2(acc[mt][nt][0], acc[mt][nt][1]));
            if (r0 + 8 < N_NODES)
                *reinterpret_cast<__half2*>(zout + (size_t)(r0 + 8) * 128 + col) =
                    __float22half2_rn(make_float2(acc[mt][nt][2], acc[mt][nt][3]));
        }
    }
}

// ---------------- final: out = log_softmax(mean(z[src]) + s + b2) -----------
// zs rows (fp16): [z (cols 0..63) | s (cols 64..127)]; warp per node.
__global__ __launch_bounds__(256)
void k_final(const __half* __restrict__ zs, const int* __restrict__ csr,
             const int* __restrict__ row_ptr, const float* __restrict__ b2,
             float* __restrict__ out) {
    int w = (blockIdx.x * blockDim.x + threadIdx.x) >> 5;
    if (w >= N_NODES) return;
    int lane = threadIdx.x & 31;
    int beg = __ldg(row_ptr + w);
    int end = __ldg(row_ptr + w + 1);
    float2 a = make_float2(0.f, 0.f);
    int i = beg;
    for (; i + 1 < end; i += 2) {
        int s0 = __ldg(csr + i);
        int s1 = __ldg(csr + i + 1);
        __half2 u0 = __ldg(reinterpret_cast<const __half2*>(zs + (size_t)s0 * 128) + lane);
        __half2 u1 = __ldg(reinterpret_cast<const __half2*>(zs + (size_t)s1 * 128) + lane);
        float2 f = __half22float2(__hadd2(u0, u1));
        a.x += f.x; a.y += f.y;
    }
    if (i < end) {
        int s0 = __ldg(csr + i);
        float2 f = __half22float2(__ldg(reinterpret_cast<const __half2*>(zs + (size_t)s0 * 128) + lane));
        a.x += f.x; a.y += f.y;
    }
    float inv = 1.f / (float)max(end - beg, 1);
    float2 sv = __half22float2(__ldg(reinterpret_cast<const __half2*>(zs + (size_t)w * 128 + 64) + lane));
    float2 bb = __ldg(reinterpret_cast<const float2*>(b2) + lane);
    float v0 = a.x * inv + sv.x + bb.x;
    float v1 = a.y * inv + sv.y + bb.y;
    float m = fmaxf(v0, v1);
#pragma unroll
    for (int o = 16; o > 0; o >>= 1) m = fmaxf(m, __shfl_xor_sync(0xffffffffu, m, o));
    float e = expf(v0 - m) + expf(v1 - m);
#pragma unroll
    for (int o = 16; o > 0; o >>= 1) e += __shfl_xor_sync(0xffffffffu, e, o);
    float l = m + logf(e);
    *(reinterpret_cast<float2*>(out + (size_t)w * D_OUT) + lane) = make_float2(v0 - l, v1 - l);
}

// ---------------- launch ----------------------------------------------------
extern "C" void kernel_launch(void* const* d_in, const int* in_sizes, int n_in,
                              void* d_out, int out_size) {
    const float* x   = (const float*)d_in[0];
    const int* ei    = (const int*)d_in[1];
    const float* Wl0 = (const float*)d_in[2];
    const float* Wr0 = (const float*)d_in[3];
    const float* b0  = (const float*)d_in[4];
    const float* g0  = (const float*)d_in[5];
    const float* be0 = (const float*)d_in[6];
    const float* Wl1 = (const float*)d_in[7];
    const float* Wr1 = (const float*)d_in[8];
    const float* b1  = (const float*)d_in[9];
    const float* g1  = (const float*)d_in[10];
    const float* be1 = (const float*)d_in[11];
    const float* Wl2 = (const float*)d_in[12];
    const float* Wr2 = (const float*)d_in[13];
    const float* b2  = (const float*)d_in[14];
    float* out = (float*)d_out;

    const int E = in_sizes[1] / 2;
    const int* src = ei;
    const int* dst = ei + E;

    __half *xh, *M, *W, *h0, *h1;
    float *sum0, *sq0, *sum1, *sq1;
    int *cnti, *rowptr, *rank, *csr;
    cudaGetSymbolAddress((void**)&xh, g_xh);
    cudaGetSymbolAddress((void**)&M, g_M);
    cudaGetSymbolAddress((void**)&W, g_W);
    cudaGetSymbolAddress((void**)&h0, g_h0);
    cudaGetSymbolAddress((void**)&h1, g_h1);
    cudaGetSymbolAddress((void**)&cnti, g_cnti);
    cudaGetSymbolAddress((void**)&rowptr, g_rowptr);
    cudaGetSymbolAddress((void**)&rank, g_rank);
    cudaGetSymbolAddress((void**)&csr, g_csr);
    cudaGetSymbolAddress((void**)&sum0, g_sum0);
    cudaGetSymbolAddress((void**)&sq0, g_sq0);
    cudaGetSymbolAddress((void**)&sum1, g_sum1);
    cudaGetSymbolAddress((void**)&sq1, g_sq1);

    constexpr int RS = 72;
    const int SMEM = (128 + 128) * RS * 2;  // 36864 bytes
    cudaFuncSetAttribute((const void*)k_mma_gemm, cudaFuncAttributeMaxDynamicSharedMemorySize, SMEM);
    cudaFuncSetAttribute((const void*)k_gemm_l2, cudaFuncAttributeMaxDynamicSharedMemorySize, SMEM);

    const int aggBlocks  = (N_NODES * 32 + 255) / 256;
    const int gemmBlocks = (N_NODES + 127) / 128;

    __half* W0 = W;
    __half* W1 = W + 128 * 256;
    __half* W2 = W + 256 * 256;

    // ---- prep: weights + x->fp16 + CSR ----
    k_prep<<<512, 256>>>(dst, E, cnti, rank, x, xh,
                         Wl0, Wr0, Wl1, Wr1, Wl2, Wr2, W);
    k_scan<<<1, 1024>>>(cnti, rowptr);
    k_fill<<<512, 256>>>(src, dst, E, rank, rowptr, csr);

    // ---- layer 0 ----
    k_aggregate<<<aggBlocks, 256>>>(xh, csr, rowptr, M, sum0, sq0);
    k_mma_gemm<<<gemmBlocks, 256, SMEM>>>(M, xh, W0, b0, h0, sum0, sq0);
    k_bn_apply<<<1024, 256>>>(h0, sum0, sq0, g0, be0);

    // ---- layer 1 ----
    k_aggregate<<<aggBlocks, 256>>>(h0, csr, rowptr, M, sum1, sq1);
    k_mma_gemm<<<gemmBlocks, 256, SMEM>>>(M, h0, W1, b1, h1, sum1, sq1);
    k_bn_apply<<<1024, 256>>>(h1, sum1, sq1, g1, be1);

    // ---- layer 2 (commuted: GEMM first, then fp16 gather + log-softmax) ----
    k_gemm_l2<<<gemmBlocks, 256, SMEM>>>(h1, W2, h0);
    k_final<<<aggBlocks, 256>>>(h0, csr, rowptr, b2, out);
}

// round 13
// speedup vs baseline: 1.4004x; 1.0093x over previous
#include <cuda_runtime.h>
#include <cuda_fp16.h>
#include <cstdint>

#define N_NODES 50000
#define E_MAX   800000
#define D 128
#define D_OUT 64
#define BN_EPS 1e-5f
#define WTOT (2 * 128 * 256 + 128 * 128)

// ---------------- scratch (device globals; no allocation allowed) ----------
__device__ __half g_xh[(size_t)N_NODES * D];   // fp16 copy of x
__device__ __half g_M[(size_t)N_NODES * D];    // neighbor mean (fp16)
__device__ __half g_W[WTOT];                   // fp16 weights (all layers, transposed)
__device__ __half g_h0[(size_t)N_NODES * D];   // layer0 out; later reused for [z2|s2]
__device__ __half g_h1[(size_t)N_NODES * D];
__device__ int    g_cnti[N_NODES];
__device__ int    g_rowptr[N_NODES + 1];
__device__ int    g_rank[E_MAX];
__device__ int    g_csr[E_MAX];
__device__ float  g_sum0[D];
__device__ float  g_sq0[D];
__device__ float  g_sum1[D];
__device__ float  g_sq1[D];

// ---------------- helpers ----------------------------------------------------
__device__ __forceinline__ uint32_t smem_u32(const void* p) {
    return (uint32_t)__cvta_generic_to_shared(p);
}

__device__ __forceinline__ void ldsm4(uint32_t* r, uint32_t a) {
    asm volatile("ldmatrix.sync.aligned.m8n8.x4.shared.b16 {%0,%1,%2,%3}, [%4];"
                 : "=r"(r[0]), "=r"(r[1]), "=r"(r[2]), "=r"(r[3]) : "r"(a));
}

__device__ __forceinline__ void mma16816f(float* d, const uint32_t* a, const uint32_t* b) {
    asm volatile("mma.sync.aligned.m16n8k16.row.col.f32.f16.f16.f32 "
                 "{%0,%1,%2,%3}, {%4,%5,%6,%7}, {%8,%9}, {%0,%1,%2,%3};"
                 : "+f"(d[0]), "+f"(d[1]), "+f"(d[2]), "+f"(d[3])
                 : "r"(a[0]), "r"(a[1]), "r"(a[2]), "r"(a[3]), "r"(b[0]), "r"(b[1]));
}

__device__ __forceinline__ void cp_async16(uint32_t sa, const void* g, int sz) {
    asm volatile("cp.async.cg.shared.global [%0], [%1], 16, %2;"
                 :: "r"(sa), "l"(g), "r"(sz) : "memory");
}
__device__ __forceinline__ void cp_commit() {
    asm volatile("cp.async.commit_group;" ::: "memory");
}
__device__ __forceinline__ void cp_wait0() {
    asm volatile("cp.async.wait_group 0;" ::: "memory");
}

// ---------------- prep: weights->fp16, x->fp16, degree hist + ranks ---------
__global__ void k_prep(const int* __restrict__ dst, int E,
                       int* __restrict__ cnt, int* __restrict__ rank,
                       const float* __restrict__ x, __half* __restrict__ xh,
                       const float* __restrict__ Wl0, const float* __restrict__ Wr0,
                       const float* __restrict__ Wl1, const float* __restrict__ Wr1,
                       const float* __restrict__ Wl2, const float* __restrict__ Wr2,
                       __half* __restrict__ W) {
    int idx = blockIdx.x * blockDim.x + threadIdx.x;
    int stride = gridDim.x * blockDim.x;

    if (idx < WTOT) {
        const int T01 = 128 * 256;
        float v;
        if (idx < T01) {
            int n = idx >> 8, k = idx & 255;
            v = (k < 128) ? __ldg(Wl0 + k * 128 + n) : __ldg(Wr0 + (k - 128) * 128 + n);
        } else if (idx < 2 * T01) {
            int l = idx - T01;
            int n = l >> 8, k = l & 255;
            v = (k < 128) ? __ldg(Wl1 + k * 128 + n) : __ldg(Wr1 + (k - 128) * 128 + n);
        } else {
            int l = idx - 2 * T01;
            int n = l >> 7, k = l & 127;
            v = (n < 64) ? __ldg(Wl2 + k * 64 + n) : __ldg(Wr2 + k * 64 + (n - 64));
        }
        W[idx] = __float2half_rn(v);
    }

    // x -> fp16 (8 elements per iteration)
    const int X8 = N_NODES * D / 8;
    for (int i = idx; i < X8; i += stride) {
        float4 u0 = __ldg(reinterpret_cast<const float4*>(x) + i * 2);
        float4 u1 = __ldg(reinterpret_cast<const float4*>(x) + i * 2 + 1);
        __half2 h[4];
        h[0] = __float22half2_rn(make_float2(u0.x, u0.y));
        h[1] = __float22half2_rn(make_float2(u0.z, u0.w));
        h[2] = __float22half2_rn(make_float2(u1.x, u1.y));
        h[3] = __float22half2_rn(make_float2(u1.z, u1.w));
        reinterpret_cast<uint4*>(xh)[i] = *reinterpret_cast<uint4*>(h);
    }

    int nQ = E >> 2;
    for (int q = idx; q < nQ; q += stride) {
        int4 d = __ldg(reinterpret_cast<const int4*>(dst) + q);
        int4 r;
        r.x = atomicAdd(&cnt[d.x], 1);
        r.y = atomicAdd(&cnt[d.y], 1);
        r.z = atomicAdd(&cnt[d.z], 1);
        r.w = atomicAdd(&cnt[d.w], 1);
        *(reinterpret_cast<int4*>(rank) + q) = r;
    }
    for (int e = nQ * 4 + idx; e < E; e += stride)
        rank[e] = atomicAdd(&cnt[__ldg(dst + e)], 1);
}

// single block, 1024 threads: exclusive scan; self-zeroes cnt for next replay
__global__ void k_scan(int* __restrict__ cnt, int* __restrict__ row_ptr) {
    constexpr int SEG = (N_NODES + 1023) / 1024;
    int t = threadIdx.x;
    int beg = t * SEG;
    int end = min(beg + SEG, N_NODES);
    int s = 0;
    for (int i = beg; i < end; i++) s += cnt[i];
    __shared__ int sh[1024];
    sh[t] = s;
    __syncthreads();
    for (int off = 1; off < 1024; off <<= 1) {
        int v = (t >= off) ? sh[t - off] : 0;
        __syncthreads();
        sh[t] += v;
        __syncthreads();
    }
    int pos = sh[t] - s;
    for (int i = beg; i < end; i++) {
        int c = cnt[i];
        row_ptr[i] = pos;
        pos += c;
        cnt[i] = 0;
    }
    if (beg < N_NODES && end == N_NODES) row_ptr[N_NODES] = pos;
}

// atomic-free fill using precomputed ranks
__global__ void k_fill(const int* __restrict__ src, const int* __restrict__ dst,
                       int E, const int* __restrict__ rank,
                       const int* __restrict__ row_ptr, int* __restrict__ csr) {
    int i = blockIdx.x * blockDim.x + threadIdx.x;
    int stride = gridDim.x * blockDim.x;
    int nQ = E >> 2;
    for (int q = i; q < nQ; q += stride) {
        int4 d = __ldg(reinterpret_cast<const int4*>(dst) + q);
        int4 s = __ldg(reinterpret_cast<const int4*>(src) + q);
        int4 r = __ldg(reinterpret_cast<const int4*>(rank) + q);
        csr[__ldg(row_ptr + d.x) + r.x] = s.x;
        csr[__ldg(row_ptr + d.y) + r.y] = s.y;
        csr[__ldg(row_ptr + d.z) + r.z] = s.z;
        csr[__ldg(row_ptr + d.w) + r.w] = s.w;
    }
    for (int e = nQ * 4 + i; e < E; e += stride)
        csr[__ldg(row_ptr + __ldg(dst + e)) + __ldg(rank + e)] = __ldg(src + e);
}

// ---------------- aggregation: fp16 gather (pairwise HADD2, idx prefetch) ---
// One warp per node; block 0 zeroes the given stats buffers.
__global__ __launch_bounds__(256)
void k_aggregate(const __half* __restrict__ xin, const int* __restrict__ csr,
                 const int* __restrict__ row_ptr, __half* __restrict__ M,
                 float* __restrict__ zSum, float* __restrict__ zSq) {
    int tid = threadIdx.x;
    if (blockIdx.x == 0 && tid < 128) { zSum[tid] = 0.f; zSq[tid] = 0.f; }

    int w = (blockIdx.x * blockDim.x + tid) >> 5;
    if (w >= N_NODES) return;
    int lane = tid & 31;

    int beg = __ldg(row_ptr + w);
    int end = __ldg(row_ptr + w + 1);
    float4 acc = make_float4(0.f, 0.f, 0.f, 0.f);

    int p0 = 0, p1 = 0;
    if (beg + 1 < end) { p0 = __ldg(csr + beg); p1 = __ldg(csr + beg + 1); }
    int i = beg;
    for (; i + 1 < end; i += 2) {
        int s0 = p0, s1 = p1;
        if (i + 3 < end) { p0 = __ldg(csr + i + 2); p1 = __ldg(csr + i + 3); }
        uint2 u0 = __ldg(reinterpret_cast<const uint2*>(xin + (size_t)s0 * D) + lane);
        uint2 u1 = __ldg(reinterpret_cast<const uint2*>(xin + (size_t)s1 * D) + lane);
        __half2 q0 = __hadd2(*reinterpret_cast<__half2*>(&u0.x), *reinterpret_cast<__half2*>(&u1.x));
        __half2 q1 = __hadd2(*reinterpret_cast<__half2*>(&u0.y), *reinterpret_cast<__half2*>(&u1.y));
        float2 f0 = __half22float2(q0);
        float2 f1 = __half22float2(q1);
        acc.x += f0.x; acc.y += f0.y; acc.z += f1.x; acc.w += f1.y;
    }
    if (i < end) {
        int s0 = __ldg(csr + i);
        uint2 u0 = __ldg(reinterpret_cast<const uint2*>(xin + (size_t)s0 * D) + lane);
        float2 f0 = __half22float2(*reinterpret_cast<__half2*>(&u0.x));
        float2 f1 = __half22float2(*reinterpret_cast<__half2*>(&u0.y));
        acc.x += f0.x; acc.y += f0.y; acc.z += f1.x; acc.w += f1.y;
    }

    float inv = 1.f / (float)max(end - beg, 1);
    __half2 o[2];
    o[0] = __float22half2_rn(make_float2(acc.x * inv, acc.y * inv));
    o[1] = __float22half2_rn(make_float2(acc.z * inv, acc.w * inv));
    *reinterpret_cast<uint2*>(M + (size_t)w * D + lane * 4) = *reinterpret_cast<uint2*>(o);
}

// ---------------- BN+ReLU in place on fp16 h ---------------------------------
__global__ __launch_bounds__(256)
void k_bn_apply(__half* __restrict__ h,
                const float* __restrict__ stSum, const float* __restrict__ stSq,
                const float* __restrict__ gamma, const float* __restrict__ beta) {
    __shared__ float ssc[128], ssh[128];
    int tid = threadIdx.x;
    if (tid < 128) {
        float mu = __ldg(stSum + tid) / (float)N_NODES;
        float var = __ldg(stSq + tid) / (float)N_NODES - mu * mu;
        float sc = __ldg(gamma + tid) * rsqrtf(var + BN_EPS);
        ssc[tid] = sc;
        ssh[tid] = __ldg(beta + tid) - mu * sc;
    }
    __syncthreads();

    const int T8 = N_NODES * D / 8;
    for (int i = blockIdx.x * blockDim.x + tid; i < T8; i += gridDim.x * blockDim.x) {
        int c8 = (i & 15) * 8;
        uint4 u = *(reinterpret_cast<uint4*>(h) + i);
        __half2* hp = reinterpret_cast<__half2*>(&u);
#pragma unroll
        for (int j = 0; j < 4; j++) {
            float2 f = __half22float2(hp[j]);
            f.x = fmaxf(fmaf(f.x, ssc[c8 + 2 * j], ssh[c8 + 2 * j]), 0.f);
            f.y = fmaxf(fmaf(f.y, ssc[c8 + 2 * j + 1], ssh[c8 + 2 * j + 1]), 0.f);
            hp[j] = __float22half2_rn(f);
        }
        *(reinterpret_cast<uint4*>(h) + i) = u;
    }
}

// ---------------- fp16 HMMA GEMM layers 0/1 (K=256, N=128), cp.async 2-buf --
// A = [mean (fp16) | self (fp16, already BN'd)]; out = A@W^T + b (fp16 store)
// Fused BN column-stat accumulation (fp32) into stOut.
__global__ __launch_bounds__(256)
void k_mma_gemm(const __half* __restrict__ M, const __half* __restrict__ selfSrc,
                const __half* __restrict__ W, const float* __restrict__ bias,
                __half* __restrict__ out,
                float* __restrict__ stOutSum, float* __restrict__ stOutSq) {
    constexpr int RS = 72;
    constexpr int NT = 8;
    constexpr int BUF = 128 * RS;          // halves per A (or W) section
    extern __shared__ __half sm[];

    __shared__ float ssum[128];
    __shared__ float ssq[128];

    const int tid = threadIdx.x;
    const int lane = tid & 31;
    const int warp = tid >> 5;
    const int wr = warp & 3;
    const int wc = warp >> 2;
    const int rowBase = blockIdx.x * 128;

    if (tid < 128) { ssum[tid] = 0.f; ssq[tid] = 0.f; }

    float acc[2][NT][4];
#pragma unroll
    for (int mt = 0; mt < 2; mt++)
#pragma unroll
        for (int nt = 0; nt < NT; nt++)
#pragma unroll
            for (int j = 0; j < 4; j++) acc[mt][nt][j] = 0.f;

    // async stage issue: A (128x64) and W (128x64) into buffer b
    auto issue = [&](int stage, int b) {
        const __half* Asrc = (stage < 2) ? M : selfSrc;
        const int colBase = (stage & 1) * 64;
        __half* sA = sm + b * 2 * BUF;
        __half* sW = sA + BUF;
#pragma unroll
        for (int t = 0; t < 4; t++) {
            int idx = tid + t * 256;
            int r = idx >> 3, c = idx & 7;
            int row = rowBase + r;
            int ok = (row < N_NODES) ? 16 : 0;
            int srow = (row < N_NODES) ? row : 0;
            cp_async16(smem_u32(sA + r * RS + c * 8),
                       Asrc + (size_t)srow * D + colBase + c * 8, ok);
        }
#pragma unroll
        for (int t = 0; t < 4; t++) {
            int idx = tid + t * 256;
            int n = idx >> 3, c = idx & 7;
            cp_async16(smem_u32(sW + n * RS + c * 8),
                       W + (size_t)n * 256 + stage * 64 + c * 8, 16);
        }
        cp_commit();
    };

    issue(0, 0);

    for (int stage = 0; stage < 4; stage++) {
        cp_wait0();
        __syncthreads();
        if (stage + 1 < 4) issue(stage + 1, (stage + 1) & 1);

        const uint32_t sbA = smem_u32(sm + (stage & 1) * 2 * BUF);
        const uint32_t sbW = sbA + BUF * 2;

#pragma unroll
        for (int ks = 0; ks < 4; ks++) {
            const uint32_t koff = (uint32_t)(ks * 16 + (lane >> 4) * 8) * 2;
            uint32_t a[2][4];
#pragma unroll
            for (int mt = 0; mt < 2; mt++) {
                uint32_t roff = (uint32_t)(wr * 32 + mt * 16 + (lane & 15)) * (RS * 2) + koff;
                ldsm4(a[mt], sbA + roff);
            }
            uint32_t b[NT][2];
#pragma unroll
            for (int g = 0; g < NT / 2; g++) {
                uint32_t roff = (uint32_t)(wc * 64 + g * 16 + (lane & 15)) * (RS * 2) + koff;
                uint32_t r[4];
                ldsm4(r, sbW + roff);
                b[2 * g][0] = r[0]; b[2 * g][1] = r[2];
                b[2 * g + 1][0] = r[1]; b[2 * g + 1][1] = r[3];
            }
#pragma unroll
            for (int mt = 0; mt < 2; mt++)
#pragma unroll
                for (int nt = 0; nt < NT; nt++)
                    mma16816f(acc[mt][nt], a[mt], b[nt]);
        }
        __syncthreads();
    }

#pragma unroll
    for (int nt = 0; nt < NT; nt++) {
        int col = wc * 64 + nt * 8 + (lane & 3) * 2;
        float2 bb = *reinterpret_cast<const float2*>(bias + col);
        float s0 = 0.f, s1 = 0.f, q0 = 0.f, q1 = 0.f;
#pragma unroll
        for (int mt = 0; mt < 2; mt++) {
            int r0 = rowBase + wr * 32 + mt * 16 + (lane >> 2);
            float v0 = acc[mt][nt][0] + bb.x, v1 = acc[mt][nt][1] + bb.y;
            float v2 = acc[mt][nt][2] + bb.x, v3 = acc[mt][nt][3] + bb.y;
            if (r0 < N_NODES) {
                *reinterpret_cast<__half2*>(out + (size_t)r0 * 128 + col) =
                    __float22half2_rn(make_float2(v0, v1));
                s0 += v0; s1 += v1; q0 += v0 * v0; q1 += v1 * v1;
            }
            if (r0 + 8 < N_NODES) {
                *reinterpret_cast<__half2*>(out + (size_t)(r0 + 8) * 128 + col) =
                    __float22half2_rn(make_float2(v2, v3));
                s0 += v2; s1 += v3; q0 += v2 * v2; q1 += v3 * v3;
            }
        }
#pragma unroll
        for (int off = 4; off < 32; off <<= 1) {
            s0 += __shfl_down_sync(0xffffffffu, s0, off);
            s1 += __shfl_down_sync(0xffffffffu, s1, off);
            q0 += __shfl_down_sync(0xffffffffu, q0, off);
            q1 += __shfl_down_sync(0xffffffffu, q1, off);
        }
        if ((lane >> 2) == 0) {
            atomicAdd(&ssum[col], s0); atomicAdd(&ssum[col + 1], s1);
            atomicAdd(&ssq[col], q0);  atomicAdd(&ssq[col + 1], q1);
        }
    }
    __syncthreads();
    if (tid < 128) {
        atomicAdd(&stOutSum[tid], ssum[tid]);
        atomicAdd(&stOutSq[tid], ssq[tid]);
    }
}

// ---------------- layer-2 GEMM: [z|s] = h1bn @ [Wl2|Wr2]^T (fp16, cp.async) -
__global__ __launch_bounds__(256)
void k_gemm_l2(const __half* __restrict__ hin, const __half* __restrict__ W,
               __half* __restrict__ zout) {
    constexpr int RS = 72;
    constexpr int NT = 8;
    constexpr int BUF = 128 * RS;
    extern __shared__ __half sm[];

    const int tid = threadIdx.x;
    const int lane = tid & 31;
    const int warp = tid >> 5;
    const int wr = warp & 3;
    const int wc = warp >> 2;
    const int rowBase = blockIdx.x * 128;

    float acc[2][NT][4];
#pragma unroll
    for (int mt = 0; mt < 2; mt++)
#pragma unroll
        for (int nt = 0; nt < NT; nt++)
#pragma unroll
            for (int j = 0; j < 4; j++) acc[mt][nt][j] = 0.f;

    auto issue = [&](int stage, int b) {
        __half* sA = sm + b * 2 * BUF;
        __half* sW = sA + BUF;
#pragma unroll
        for (int t = 0; t < 4; t++) {
            int idx = tid + t * 256;
            int r = idx >> 3, c = idx & 7;
            int row = rowBase + r;
            int ok = (row < N_NODES) ? 16 : 0;
            int srow = (row < N_NODES) ? row : 0;
            cp_async16(smem_u32(sA + r * RS + c * 8),
                       hin + (size_t)srow * D + stage * 64 + c * 8, ok);
        }
#pragma unroll
        for (int t = 0; t < 4; t++) {
            int idx = tid + t * 256;
            int n = idx >> 3, c = idx & 7;
            cp_async16(smem_u32(sW + n * RS + c * 8),
                       W + (size_t)n * 128 + stage * 64 + c * 8, 16);
        }
        cp_commit();
    };

    issue(0, 0);

    for (int stage = 0; stage < 2; stage++) {
        cp_wait0();
        __syncthreads();
        if (stage + 1 < 2) issue(stage + 1, 1);

        const uint32_t sbA = smem_u32(sm + (stage & 1) * 2 * BUF);
        const uint32_t sbW = sbA + BUF * 2;

#pragma unroll
        for (int ks = 0; ks < 4; ks++) {
            const uint32_t koff = (uint32_t)(ks * 16 + (lane >> 4) * 8) * 2;
            uint32_t a[2][4];
#pragma unroll
            for (int mt = 0; mt < 2; mt++) {
                uint32_t roff = (uint32_t)(wr * 32 + mt * 16 + (lane & 15)) * (RS * 2) + koff;
                ldsm4(a[mt], sbA + roff);
            }
            uint32_t b[NT][2];
#pragma unroll
            for (int g = 0; g < NT / 2; g++) {
                uint32_t roff = (uint32_t)(wc * 64 + g * 16 + (lane & 15)) * (RS * 2) + koff;
                uint32_t r[4];
                ldsm4(r, sbW + roff);
                b[2 * g][0] = r[0]; b[2 * g][1] = r[2];
                b[2 * g + 1][0] = r[1]; b[2 * g + 1][1] = r[3];
            }
#pragma unroll
            for (int mt = 0; mt < 2; mt++)
#pragma unroll
                for (int nt = 0; nt < NT; nt++)
                    mma16816f(acc[mt][nt], a[mt], b[nt]);
        }
        __syncthreads();
    }

#pragma unroll
    for (int nt = 0; nt < NT; nt++) {
        int col = wc * 64 + nt * 8 + (lane & 3) * 2;
#pragma unroll
        for (int mt = 0; mt < 2; mt++) {
            int r0 = rowBase + wr * 32 + mt * 16 + (lane >> 2);
            if (r0 < N_NODES)
                *reinterpret_cast<__half2*>(zout + (size_t)r0 * 128 + col) =
                    __float22half2_rn(make_float2(acc[mt][nt][0], acc[mt][nt][1]));
            if (r0 + 8 < N_NODES)
                *reinterpret_cast<__half2*>(zout + (size_t)(r0 + 8) * 128 + col) =
                    __float22half2_rn(make_float2(acc[mt][nt][2], acc[mt][nt][3]));
        }
    }
}

// ---------------- final: out = log_softmax(mean(z[src]) + s + b2) -----------
// zs rows (fp16): [z (cols 0..63) | s (cols 64..127)]; warp per node.
__global__ __launch_bounds__(256)
void k_final(const __half* __restrict__ zs, const int* __restrict__ csr,
             const int* __restrict__ row_ptr, const float* __restrict__ b2,
             float* __restrict__ out) {
    int w = (blockIdx.x * blockDim.x + threadIdx.x) >> 5;
    if (w >= N_NODES) return;
    int lane = threadIdx.x & 31;
    int beg = __ldg(row_ptr + w);
    int end = __ldg(row_ptr + w + 1);
    float2 a = make_float2(0.f, 0.f);

    int p0 = 0, p1 = 0;
    if (beg + 1 < end) { p0 = __ldg(csr + beg); p1 = __ldg(csr + beg + 1); }
    int i = beg;
    for (; i + 1 < end; i += 2) {
        int s0 = p0, s1 = p1;
        if (i + 3 < end) { p0 = __ldg(csr + i + 2); p1 = __ldg(csr + i + 3); }
        __half2 u0 = __ldg(reinterpret_cast<const __half2*>(zs + (size_t)s0 * 128) + lane);
        __half2 u1 = __ldg(reinterpret_cast<const __half2*>(zs + (size_t)s1 * 128) + lane);
        float2 f = __half22float2(__hadd2(u0, u1));
        a.x += f.x; a.y += f.y;
    }
    if (i < end) {
        int s0 = __ldg(csr + i);
        float2 f = __half22float2(__ldg(reinterpret_cast<const __half2*>(zs + (size_t)s0 * 128) + lane));
        a.x += f.x; a.y += f.y;
    }
    float inv = 1.f / (float)max(end - beg, 1);
    float2 sv = __half22float2(__ldg(reinterpret_cast<const __half2*>(zs + (size_t)w * 128 + 64) + lane));
    float2 bb = __ldg(reinterpret_cast<const float2*>(b2) + lane);
    float v0 = a.x * inv + sv.x + bb.x;
    float v1 = a.y * inv + sv.y + bb.y;
    float m = fmaxf(v0, v1);
#pragma unroll
    for (int o = 16; o > 0; o >>= 1) m = fmaxf(m, __shfl_xor_sync(0xffffffffu, m, o));
    float e = expf(v0 - m) + expf(v1 - m);
#pragma unroll
    for (int o = 16; o > 0; o >>= 1) e += __shfl_xor_sync(0xffffffffu, e, o);
    float l = m + logf(e);
    *(reinterpret_cast<float2*>(out + (size_t)w * D_OUT) + lane) = make_float2(v0 - l, v1 - l);
}

// ---------------- launch ----------------------------------------------------
extern "C" void kernel_launch(void* const* d_in, const int* in_sizes, int n_in,
                              void* d_out, int out_size) {
    const float* x   = (const float*)d_in[0];
    const int* ei    = (const int*)d_in[1];
    const float* Wl0 = (const float*)d_in[2];
    const float* Wr0 = (const float*)d_in[3];
    const float* b0  = (const float*)d_in[4];
    const float* g0  = (const float*)d_in[5];
    const float* be0 = (const float*)d_in[6];
    const float* Wl1 = (const float*)d_in[7];
    const float* Wr1 = (const float*)d_in[8];
    const float* b1  = (const float*)d_in[9];
    const float* g1  = (const float*)d_in[10];
    const float* be1 = (const float*)d_in[11];
    const float* Wl2 = (const float*)d_in[12];
    const float* Wr2 = (const float*)d_in[13];
    const float* b2  = (const float*)d_in[14];
    float* out = (float*)d_out;

    const int E = in_sizes[1] / 2;
    const int* src = ei;
    const int* dst = ei + E;

    __half *xh, *M, *W, *h0, *h1;
    float *sum0, *sq0, *sum1, *sq1;
    int *cnti, *rowptr, *rank, *csr;
    cudaGetSymbolAddress((void**)&xh, g_xh);
    cudaGetSymbolAddress((void**)&M, g_M);
    cudaGetSymbolAddress((void**)&W, g_W);
    cudaGetSymbolAddress((void**)&h0, g_h0);
    cudaGetSymbolAddress((void**)&h1, g_h1);
    cudaGetSymbolAddress((void**)&cnti, g_cnti);
    cudaGetSymbolAddress((void**)&rowptr, g_rowptr);
    cudaGetSymbolAddress((void**)&rank, g_rank);
    cudaGetSymbolAddress((void**)&csr, g_csr);
    cudaGetSymbolAddress((void**)&sum0, g_sum0);
    cudaGetSymbolAddress((void**)&sq0, g_sq0);
    cudaGetSymbolAddress((void**)&sum1, g_sum1);
    cudaGetSymbolAddress((void**)&sq1, g_sq1);

    constexpr int RS = 72;
    const int SMEM = 4 * 128 * RS * 2;  // 73728 bytes: 2 buffers x (A + W)
    cudaFuncSetAttribute((const void*)k_mma_gemm, cudaFuncAttributeMaxDynamicSharedMemorySize, SMEM);
    cudaFuncSetAttribute((const void*)k_gemm_l2, cudaFuncAttributeMaxDynamicSharedMemorySize, SMEM);

    const int aggBlocks  = (N_NODES * 32 + 255) / 256;
    const int gemmBlocks = (N_NODES + 127) / 128;

    __half* W0 = W;
    __half* W1 = W + 128 * 256;
    __half* W2 = W + 256 * 256;

    // ---- prep: weights + x->fp16 + CSR ----
    k_prep<<<512, 256>>>(dst, E, cnti, rank, x, xh,
                         Wl0, Wr0, Wl1, Wr1, Wl2, Wr2, W);
    k_scan<<<1, 1024>>>(cnti, rowptr);
    k_fill<<<512, 256>>>(src, dst, E, rank, rowptr, csr);

    // ---- layer 0 ----
    k_aggregate<<<aggBlocks, 256>>>(xh, csr, rowptr, M, sum0, sq0);
    k_mma_gemm<<<gemmBlocks, 256, SMEM>>>(M, xh, W0, b0, h0, sum0, sq0);
    k_bn_apply<<<1024, 256>>>(h0, sum0, sq0, g0, be0);

    // ---- layer 1 ----
    k_aggregate<<<aggBlocks, 256>>>(h0, csr, rowptr, M, sum1, sq1);
    k_mma_gemm<<<gemmBlocks, 256, SMEM>>>(M, h0, W1, b1, h1, sum1, sq1);
    k_bn_apply<<<1024, 256>>>(h1, sum1, sq1, g1, be1);

    // ---- layer 2 (commuted: GEMM first, then fp16 gather + log-softmax) ----
    k_gemm_l2<<<gemmBlocks, 256, SMEM>>>(h1, W2, h0);
    k_final<<<aggBlocks, 256>>>(h0, csr, rowptr, b2, out);
}

// round 14
// speedup vs baseline: 1.4071x; 1.0048x over previous
#include <cuda_runtime.h>
#include <cuda_fp16.h>
#include <cstdint>

#define N_NODES 50000
#define E_MAX   800000
#define D 128
#define D_OUT 64
#define BN_EPS 1e-5f
#define WTOT (2 * 128 * 256 + 128 * 128)

// ---------------- scratch (device globals; no allocation allowed) ----------
__device__ __half g_xh[(size_t)N_NODES * D];   // fp16 copy of x
__device__ __half g_M[(size_t)N_NODES * D];    // neighbor mean (fp16)
__device__ __half g_W[WTOT];                   // fp16 weights (all layers, transposed)
__device__ __half g_h0[(size_t)N_NODES * D];   // layer0 out; later reused for [z2|s2]
__device__ __half g_h1[(size_t)N_NODES * D];
__device__ int    g_cnti[N_NODES];
__device__ int    g_rowptr[N_NODES + 1];
__device__ int    g_rank[E_MAX];
__device__ int    g_csr[E_MAX];
__device__ float  g_sum0[D];
__device__ float  g_sq0[D];
__device__ float  g_sum1[D];
__device__ float  g_sq1[D];

// ---------------- helpers ----------------------------------------------------
__device__ __forceinline__ uint32_t smem_u32(const void* p) {
    return (uint32_t)__cvta_generic_to_shared(p);
}

__device__ __forceinline__ void ldsm4(uint32_t* r, uint32_t a) {
    asm volatile("ldmatrix.sync.aligned.m8n8.x4.shared.b16 {%0,%1,%2,%3}, [%4];"
                 : "=r"(r[0]), "=r"(r[1]), "=r"(r[2]), "=r"(r[3]) : "r"(a));
}

__device__ __forceinline__ void mma16816f(float* d, const uint32_t* a, const uint32_t* b) {
    asm volatile("mma.sync.aligned.m16n8k16.row.col.f32.f16.f16.f32 "
                 "{%0,%1,%2,%3}, {%4,%5,%6,%7}, {%8,%9}, {%0,%1,%2,%3};"
                 : "+f"(d[0]), "+f"(d[1]), "+f"(d[2]), "+f"(d[3])
                 : "r"(a[0]), "r"(a[1]), "r"(a[2]), "r"(a[3]), "r"(b[0]), "r"(b[1]));
}

__device__ __forceinline__ void cp_async16(uint32_t sa, const void* g, int sz) {
    asm volatile("cp.async.cg.shared.global [%0], [%1], 16, %2;"
                 :: "r"(sa), "l"(g), "r"(sz) : "memory");
}
__device__ __forceinline__ void cp_commit() {
    asm volatile("cp.async.commit_group;" ::: "memory");
}
__device__ __forceinline__ void cp_wait0() {
    asm volatile("cp.async.wait_group 0;" ::: "memory");
}

// ---------------- prep: weights->fp16, x->fp16, degree hist + ranks ---------
__global__ void k_prep(const int* __restrict__ dst, int E,
                       int* __restrict__ cnt, int* __restrict__ rank,
                       const float* __restrict__ x, __half* __restrict__ xh,
                       const float* __restrict__ Wl0, const float* __restrict__ Wr0,
                       const float* __restrict__ Wl1, const float* __restrict__ Wr1,
                       const float* __restrict__ Wl2, const float* __restrict__ Wr2,
                       __half* __restrict__ W) {
    int idx = blockIdx.x * blockDim.x + threadIdx.x;
    int stride = gridDim.x * blockDim.x;

    if (idx < WTOT) {
        const int T01 = 128 * 256;
        float v;
        if (idx < T01) {
            int n = idx >> 8, k = idx & 255;
            v = (k < 128) ? __ldg(Wl0 + k * 128 + n) : __ldg(Wr0 + (k - 128) * 128 + n);
        } else if (idx < 2 * T01) {
            int l = idx - T01;
            int n = l >> 8, k = l & 255;
            v = (k < 128) ? __ldg(Wl1 + k * 128 + n) : __ldg(Wr1 + (k - 128) * 128 + n);
        } else {
            int l = idx - 2 * T01;
            int n = l >> 7, k = l & 127;
            v = (n < 64) ? __ldg(Wl2 + k * 64 + n) : __ldg(Wr2 + k * 64 + (n - 64));
        }
        W[idx] = __float2half_rn(v);
    }

    // x -> fp16 (8 elements per iteration)
    const int X8 = N_NODES * D / 8;
    for (int i = idx; i < X8; i += stride) {
        float4 u0 = __ldg(reinterpret_cast<const float4*>(x) + i * 2);
        float4 u1 = __ldg(reinterpret_cast<const float4*>(x) + i * 2 + 1);
        __half2 h[4];
        h[0] = __float22half2_rn(make_float2(u0.x, u0.y));
        h[1] = __float22half2_rn(make_float2(u0.z, u0.w));
        h[2] = __float22half2_rn(make_float2(u1.x, u1.y));
        h[3] = __float22half2_rn(make_float2(u1.z, u1.w));
        reinterpret_cast<uint4*>(xh)[i] = *reinterpret_cast<uint4*>(h);
    }

    int nQ = E >> 2;
    for (int q = idx; q < nQ; q += stride) {
        int4 d = __ldg(reinterpret_cast<const int4*>(dst) + q);
        int4 r;
        r.x = atomicAdd(&cnt[d.x], 1);
        r.y = atomicAdd(&cnt[d.y], 1);
        r.z = atomicAdd(&cnt[d.z], 1);
        r.w = atomicAdd(&cnt[d.w], 1);
        *(reinterpret_cast<int4*>(rank) + q) = r;
    }
    for (int e = nQ * 4 + idx; e < E; e += stride)
        rank[e] = atomicAdd(&cnt[__ldg(dst + e)], 1);
}

// single block, 1024 threads: exclusive scan; self-zeroes cnt for next replay
__global__ void k_scan(int* __restrict__ cnt, int* __restrict__ row_ptr) {
    constexpr int SEG = (N_NODES + 1023) / 1024;
    int t = threadIdx.x;
    int beg = t * SEG;
    int end = min(beg + SEG, N_NODES);
    int s = 0;
    for (int i = beg; i < end; i++) s += cnt[i];
    __shared__ int sh[1024];
    sh[t] = s;
    __syncthreads();
    for (int off = 1; off < 1024; off <<= 1) {
        int v = (t >= off) ? sh[t - off] : 0;
        __syncthreads();
        sh[t] += v;
        __syncthreads();
    }
    int pos = sh[t] - s;
    for (int i = beg; i < end; i++) {
        int c = cnt[i];
        row_ptr[i] = pos;
        pos += c;
        cnt[i] = 0;
    }
    if (beg < N_NODES && end == N_NODES) row_ptr[N_NODES] = pos;
}

// atomic-free fill using precomputed ranks
__global__ void k_fill(const int* __restrict__ src, const int* __restrict__ dst,
                       int E, const int* __restrict__ rank,
                       const int* __restrict__ row_ptr, int* __restrict__ csr) {
    int i = blockIdx.x * blockDim.x + threadIdx.x;
    int stride = gridDim.x * blockDim.x;
    int nQ = E >> 2;
    for (int q = i; q < nQ; q += stride) {
        int4 d = __ldg(reinterpret_cast<const int4*>(dst) + q);
        int4 s = __ldg(reinterpret_cast<const int4*>(src) + q);
        int4 r = __ldg(reinterpret_cast<const int4*>(rank) + q);
        csr[__ldg(row_ptr + d.x) + r.x] = s.x;
        csr[__ldg(row_ptr + d.y) + r.y] = s.y;
        csr[__ldg(row_ptr + d.z) + r.z] = s.z;
        csr[__ldg(row_ptr + d.w) + r.w] = s.w;
    }
    for (int e = nQ * 4 + i; e < E; e += stride)
        csr[__ldg(row_ptr + __ldg(dst + e)) + __ldg(rank + e)] = __ldg(src + e);
}

// ---------------- aggregation: fp16 gather, 4-edge fp16 tree reduction ------
// One warp per node; block 0 zeroes the given stats buffers.
__global__ __launch_bounds__(256)
void k_aggregate(const __half* __restrict__ xin, const int* __restrict__ csr,
                 const int* __restrict__ row_ptr, __half* __restrict__ M,
                 float* __restrict__ zSum, float* __restrict__ zSq) {
    int tid = threadIdx.x;
    if (blockIdx.x == 0 && tid < 128) { zSum[tid] = 0.f; zSq[tid] = 0.f; }

    int w = (blockIdx.x * blockDim.x + tid) >> 5;
    if (w >= N_NODES) return;
    int lane = tid & 31;

    int beg = __ldg(row_ptr + w);
    int end = __ldg(row_ptr + w + 1);
    float4 acc = make_float4(0.f, 0.f, 0.f, 0.f);

    int i = beg;
    for (; i + 3 < end; i += 4) {
        int s0 = __ldg(csr + i);
        int s1 = __ldg(csr + i + 1);
        int s2 = __ldg(csr + i + 2);
        int s3 = __ldg(csr + i + 3);
        uint2 u0 = __ldg(reinterpret_cast<const uint2*>(xin + (size_t)s0 * D) + lane);
        uint2 u1 = __ldg(reinterpret_cast<const uint2*>(xin + (size_t)s1 * D) + lane);
        uint2 u2 = __ldg(reinterpret_cast<const uint2*>(xin + (size_t)s2 * D) + lane);
        uint2 u3 = __ldg(reinterpret_cast<const uint2*>(xin + (size_t)s3 * D) + lane);
        __half2 a_lo = __hadd2(*reinterpret_cast<__half2*>(&u0.x), *reinterpret_cast<__half2*>(&u1.x));
        __half2 a_hi = __hadd2(*reinterpret_cast<__half2*>(&u0.y), *reinterpret_cast<__half2*>(&u1.y));
        __half2 b_lo = __hadd2(*reinterpret_cast<__half2*>(&u2.x), *reinterpret_cast<__half2*>(&u3.x));
        __half2 b_hi = __hadd2(*reinterpret_cast<__half2*>(&u2.y), *reinterpret_cast<__half2*>(&u3.y));
        __half2 t_lo = __hadd2(a_lo, b_lo);
        __half2 t_hi = __hadd2(a_hi, b_hi);
        float2 f0 = __half22float2(t_lo);
        float2 f1 = __half22float2(t_hi);
        acc.x += f0.x; acc.y += f0.y; acc.z += f1.x; acc.w += f1.y;
    }
    for (; i < end; i++) {
        int s0 = __ldg(csr + i);
        uint2 u0 = __ldg(reinterpret_cast<const uint2*>(xin + (size_t)s0 * D) + lane);
        float2 f0 = __half22float2(*reinterpret_cast<__half2*>(&u0.x));
        float2 f1 = __half22float2(*reinterpret_cast<__half2*>(&u0.y));
        acc.x += f0.x; acc.y += f0.y; acc.z += f1.x; acc.w += f1.y;
    }

    float inv = 1.f / (float)max(end - beg, 1);
    __half2 o[2];
    o[0] = __float22half2_rn(make_float2(acc.x * inv, acc.y * inv));
    o[1] = __float22half2_rn(make_float2(acc.z * inv, acc.w * inv));
    *reinterpret_cast<uint2*>(M + (size_t)w * D + lane * 4) = *reinterpret_cast<uint2*>(o);
}

// ---------------- BN+ReLU in place on fp16 h ---------------------------------
__global__ __launch_bounds__(256)
void k_bn_apply(__half* __restrict__ h,
                const float* __restrict__ stSum, const float* __restrict__ stSq,
                const float* __restrict__ gamma, const float* __restrict__ beta) {
    __shared__ float ssc[128], ssh[128];
    int tid = threadIdx.x;
    if (tid < 128) {
        float mu = __ldg(stSum + tid) / (float)N_NODES;
        float var = __ldg(stSq + tid) / (float)N_NODES - mu * mu;
        float sc = __ldg(gamma + tid) * rsqrtf(var + BN_EPS);
        ssc[tid] = sc;
        ssh[tid] = __ldg(beta + tid) - mu * sc;
    }
    __syncthreads();

    const int T8 = N_NODES * D / 8;
    for (int i = blockIdx.x * blockDim.x + tid; i < T8; i += gridDim.x * blockDim.x) {
        int c8 = (i & 15) * 8;
        uint4 u = *(reinterpret_cast<uint4*>(h) + i);
        __half2* hp = reinterpret_cast<__half2*>(&u);
#pragma unroll
        for (int j = 0; j < 4; j++) {
            float2 f = __half22float2(hp[j]);
            f.x = fmaxf(fmaf(f.x, ssc[c8 + 2 * j], ssh[c8 + 2 * j]), 0.f);
            f.y = fmaxf(fmaf(f.y, ssc[c8 + 2 * j + 1], ssh[c8 + 2 * j + 1]), 0.f);
            hp[j] = __float22half2_rn(f);
        }
        *(reinterpret_cast<uint4*>(h) + i) = u;
    }
}

// ---------------- fp16 HMMA GEMM layers 0/1 (K=256, N=128), cp.async 2-buf --
// A = [mean (fp16) | self (fp16, already BN'd)]; out = A@W^T + b (fp16 store)
// Fused BN column-stat accumulation (fp32) into stOut.
__global__ __launch_bounds__(256)
void k_mma_gemm(const __half* __restrict__ M, const __half* __restrict__ selfSrc,
                const __half* __restrict__ W, const float* __restrict__ bias,
                __half* __restrict__ out,
                float* __restrict__ stOutSum, float* __restrict__ stOutSq) {
    constexpr int RS = 72;
    constexpr int NT = 8;
    constexpr int BUF = 128 * RS;          // halves per A (or W) section
    extern __shared__ __half sm[];

    __shared__ float ssum[128];
    __shared__ float ssq[128];

    const int tid = threadIdx.x;
    const int lane = tid & 31;
    const int warp = tid >> 5;
    const int wr = warp & 3;
    const int wc = warp >> 2;
    const int rowBase = blockIdx.x * 128;

    if (tid < 128) { ssum[tid] = 0.f; ssq[tid] = 0.f; }

    float acc[2][NT][4];
#pragma unroll
    for (int mt = 0; mt < 2; mt++)
#pragma unroll
        for (int nt = 0; nt < NT; nt++)
#pragma unroll
            for (int j = 0; j < 4; j++) acc[mt][nt][j] = 0.f;

    auto issue = [&](int stage, int b) {
        const __half* Asrc = (stage < 2) ? M : selfSrc;
        const int colBase = (stage & 1) * 64;
        __half* sA = sm + b * 2 * BUF;
        __half* sW = sA + BUF;
#pragma unroll
        for (int t = 0; t < 4; t++) {
            int idx = tid + t * 256;
            int r = idx >> 3, c = idx & 7;
            int row = rowBase + r;
            int ok = (row < N_NODES) ? 16 : 0;
            int srow = (row < N_NODES) ? row : 0;
            cp_async16(smem_u32(sA + r * RS + c * 8),
                       Asrc + (size_t)srow * D + colBase + c * 8, ok);
        }
#pragma unroll
        for (int t = 0; t < 4; t++) {
            int idx = tid + t * 256;
            int n = idx >> 3, c = idx & 7;
            cp_async16(smem_u32(sW + n * RS + c * 8),
                       W + (size_t)n * 256 + stage * 64 + c * 8, 16);
        }
        cp_commit();
    };

    issue(0, 0);

    for (int stage = 0; stage < 4; stage++) {
        cp_wait0();
        __syncthreads();
        if (stage + 1 < 4) issue(stage + 1, (stage + 1) & 1);

        const uint32_t sbA = smem_u32(sm + (stage & 1) * 2 * BUF);
        const uint32_t sbW = sbA + BUF * 2;

#pragma unroll
        for (int ks = 0; ks < 4; ks++) {
            const uint32_t koff = (uint32_t)(ks * 16 + (lane >> 4) * 8) * 2;
            uint32_t a[2][4];
#pragma unroll
            for (int mt = 0; mt < 2; mt++) {
                uint32_t roff = (uint32_t)(wr * 32 + mt * 16 + (lane & 15)) * (RS * 2) + koff;
                ldsm4(a[mt], sbA + roff);
            }
            uint32_t b[NT][2];
#pragma unroll
            for (int g = 0; g < NT / 2; g++) {
                uint32_t roff = (uint32_t)(wc * 64 + g * 16 + (lane & 15)) * (RS * 2) + koff;
                uint32_t r[4];
                ldsm4(r, sbW + roff);
                b[2 * g][0] = r[0]; b[2 * g][1] = r[2];
                b[2 * g + 1][0] = r[1]; b[2 * g + 1][1] = r[3];
            }
#pragma unroll
            for (int mt = 0; mt < 2; mt++)
#pragma unroll
                for (int nt = 0; nt < NT; nt++)
                    mma16816f(acc[mt][nt], a[mt], b[nt]);
        }
        __syncthreads();
    }

#pragma unroll
    for (int nt = 0; nt < NT; nt++) {
        int col = wc * 64 + nt * 8 + (lane & 3) * 2;
        float2 bb = *reinterpret_cast<const float2*>(bias + col);
        float s0 = 0.f, s1 = 0.f, q0 = 0.f, q1 = 0.f;
#pragma unroll
        for (int mt = 0; mt < 2; mt++) {
            int r0 = rowBase + wr * 32 + mt * 16 + (lane >> 2);
            float v0 = acc[mt][nt][0] + bb.x, v1 = acc[mt][nt][1] + bb.y;
            float v2 = acc[mt][nt][2] + bb.x, v3 = acc[mt][nt][3] + bb.y;
            if (r0 < N_NODES) {
                *reinterpret_cast<__half2*>(out + (size_t)r0 * 128 + col) =
                    __float22half2_rn(make_float2(v0, v1));
                s0 += v0; s1 += v1; q0 += v0 * v0; q1 += v1 * v1;
            }
            if (r0 + 8 < N_NODES) {
                *reinterpret_cast<__half2*>(out + (size_t)(r0 + 8) * 128 + col) =
                    __float22half2_rn(make_float2(v2, v3));
                s0 += v2; s1 += v3; q0 += v2 * v2; q1 += v3 * v3;
            }
        }
#pragma unroll
        for (int off = 4; off < 32; off <<= 1) {
            s0 += __shfl_down_sync(0xffffffffu, s0, off);
            s1 += __shfl_down_sync(0xffffffffu, s1, off);
            q0 += __shfl_down_sync(0xffffffffu, q0, off);
            q1 += __shfl_down_sync(0xffffffffu, q1, off);
        }
        if ((lane >> 2) == 0) {
            atomicAdd(&ssum[col], s0); atomicAdd(&ssum[col + 1], s1);
            atomicAdd(&ssq[col], q0);  atomicAdd(&ssq[col + 1], q1);
        }
    }
    __syncthreads();
    if (tid < 128) {
        atomicAdd(&stOutSum[tid], ssum[tid]);
        atomicAdd(&stOutSq[tid], ssq[tid]);
    }
}

// ---------------- layer-2 GEMM: [z | s+b2] = h1bn @ [Wl2|Wr2]^T (fp16) ------
__global__ __launch_bounds__(256)
void k_gemm_l2(const __half* __restrict__ hin, const __half* __restrict__ W,
               const float* __restrict__ b2, __half* __restrict__ zout) {
    constexpr int RS = 72;
    constexpr int NT = 8;
    constexpr int BUF = 128 * RS;
    extern __shared__ __half sm[];

    const int tid = threadIdx.x;
    const int lane = tid & 31;
    const int warp = tid >> 5;
    const int wr = warp & 3;
    const int wc = warp >> 2;
    const int rowBase = blockIdx.x * 128;

    float acc[2][NT][4];
#pragma unroll
    for (int mt = 0; mt < 2; mt++)
#pragma unroll
        for (int nt = 0; nt < NT; nt++)
#pragma unroll
            for (int j = 0; j < 4; j++) acc[mt][nt][j] = 0.f;

    auto issue = [&](int stage, int b) {
        __half* sA = sm + b * 2 * BUF;
        __half* sW = sA + BUF;
#pragma unroll
        for (int t = 0; t < 4; t++) {
            int idx = tid + t * 256;
            int r = idx >> 3, c = idx & 7;
            int row = rowBase + r;
            int ok = (row < N_NODES) ? 16 : 0;
            int srow = (row < N_NODES) ? row : 0;
            cp_async16(smem_u32(sA + r * RS + c * 8),
                       hin + (size_t)srow * D + stage * 64 + c * 8, ok);
        }
#pragma unroll
        for (int t = 0; t < 4; t++) {
            int idx = tid + t * 256;
            int n = idx >> 3, c = idx & 7;
            cp_async16(smem_u32(sW + n * RS + c * 8),
                       W + (size_t)n * 128 + stage * 64 + c * 8, 16);
        }
        cp_commit();
    };

    issue(0, 0);

    for (int stage = 0; stage < 2; stage++) {
        cp_wait0();
        __syncthreads();
        if (stage + 1 < 2) issue(stage + 1, 1);

        const uint32_t sbA = smem_u32(sm + (stage & 1) * 2 * BUF);
        const uint32_t sbW = sbA + BUF * 2;

#pragma unroll
        for (int ks = 0; ks < 4; ks++) {
            const uint32_t koff = (uint32_t)(ks * 16 + (lane >> 4) * 8) * 2;
            uint32_t a[2][4];
#pragma unroll
            for (int mt = 0; mt < 2; mt++) {
                uint32_t roff = (uint32_t)(wr * 32 + mt * 16 + (lane & 15)) * (RS * 2) + koff;
                ldsm4(a[mt], sbA + roff);
            }
            uint32_t b[NT][2];
#pragma unroll
            for (int g = 0; g < NT / 2; g++) {
                uint32_t roff = (uint32_t)(wc * 64 + g * 16 + (lane & 15)) * (RS * 2) + koff;
                uint32_t r[4];
                ldsm4(r, sbW + roff);
                b[2 * g][0] = r[0]; b[2 * g][1] = r[2];
                b[2 * g + 1][0] = r[1]; b[2 * g + 1][1] = r[3];
            }
#pragma unroll
            for (int mt = 0; mt < 2; mt++)
#pragma unroll
                for (int nt = 0; nt < NT; nt++)
                    mma16816f(acc[mt][nt], a[mt], b[nt]);
        }
        __syncthreads();
    }

    // epilogue: wc==1 warps own the s-columns (64..127) -> fold b2 in now
#pragma unroll
    for (int nt = 0; nt < NT; nt++) {
        int col = wc * 64 + nt * 8 + (lane & 3) * 2;
        float2 bb = make_float2(0.f, 0.f);
        if (wc == 1) bb = *reinterpret_cast<const float2*>(b2 + (col - 64));
#pragma unroll
        for (int mt = 0; mt < 2; mt++) {
            int r0 = rowBase + wr * 32 + mt * 16 + (lane >> 2);
            if (r0 < N_NODES)
                *reinterpret_cast<__half2*>(zout + (size_t)r0 * 128 + col) =
                    __float22half2_rn(make_float2(acc[mt][nt][0] + bb.x, acc[mt][nt][1] + bb.y));
            if (r0 + 8 < N_NODES)
                *reinterpret_cast<__half2*>(zout + (size_t)(r0 + 8) * 128 + col) =
                    __float22half2_rn(make_float2(acc[mt][nt][2] + bb.x, acc[mt][nt][3] + bb.y));
        }
    }
}

// ---------------- final: out = log_softmax(mean(z[src]) + (s+b2)) -----------
// zs rows (fp16): [z (cols 0..63) | s+b2 (cols 64..127)]; warp per node.
__global__ __launch_bounds__(256)
void k_final(const __half* __restrict__ zs, const int* __restrict__ csr,
             const int* __restrict__ row_ptr, float* __restrict__ out) {
    int w = (blockIdx.x * blockDim.x + threadIdx.x) >> 5;
    if (w >= N_NODES) return;
    int lane = threadIdx.x & 31;
    int beg = __ldg(row_ptr + w);
    int end = __ldg(row_ptr + w + 1);
    float2 a = make_float2(0.f, 0.f);
    int i = beg;
    for (; i + 3 < end; i += 4) {
        int s0 = __ldg(csr + i);
        int s1 = __ldg(csr + i + 1);
        int s2 = __ldg(csr + i + 2);
        int s3 = __ldg(csr + i + 3);
        __half2 u0 = __ldg(reinterpret_cast<const __half2*>(zs + (size_t)s0 * 128) + lane);
        __half2 u1 = __ldg(reinterpret_cast<const __half2*>(zs + (size_t)s1 * 128) + lane);
        __half2 u2 = __ldg(reinterpret_cast<const __half2*>(zs + (size_t)s2 * 128) + lane);
        __half2 u3 = __ldg(reinterpret_cast<const __half2*>(zs + (size_t)s3 * 128) + lane);
        __half2 t = __hadd2(__hadd2(u0, u1), __hadd2(u2, u3));
        float2 f = __half22float2(t);
        a.x += f.x; a.y += f.y;
    }
    for (; i < end; i++) {
        int s0 = __ldg(csr + i);
        float2 f = __half22float2(__ldg(reinterpret_cast<const __half2*>(zs + (size_t)s0 * 128) + lane));
        a.x += f.x; a.y += f.y;
    }
    float inv = 1.f / (float)max(end - beg, 1);
    float2 sv = __half22float2(__ldg(reinterpret_cast<const __half2*>(zs + (size_t)w * 128 + 64) + lane));
    float v0 = a.x * inv + sv.x;
    float v1 = a.y * inv + sv.y;
    float m = fmaxf(v0, v1);
#pragma unroll
    for (int o = 16; o > 0; o >>= 1) m = fmaxf(m, __shfl_xor_sync(0xffffffffu, m, o));
    float e = expf(v0 - m) + expf(v1 - m);
#pragma unroll
    for (int o = 16; o > 0; o >>= 1) e += __shfl_xor_sync(0xffffffffu, e, o);
    float l = m + logf(e);
    *(reinterpret_cast<float2*>(out + (size_t)w * D_OUT) + lane) = make_float2(v0 - l, v1 - l);
}

// ---------------- launch ----------------------------------------------------
extern "C" void kernel_launch(void* const* d_in, const int* in_sizes, int n_in,
                              void* d_out, int out_size) {
    const float* x   = (const float*)d_in[0];
    const int* ei    = (const int*)d_in[1];
    const float* Wl0 = (const float*)d_in[2];
    const float* Wr0 = (const float*)d_in[3];
    const float* b0  = (const float*)d_in[4];
    const float* g0  = (const float*)d_in[5];
    const float* be0 = (const float*)d_in[6];
    const float* Wl1 = (const float*)d_in[7];
    const float* Wr1 = (const float*)d_in[8];
    const float* b1  = (const float*)d_in[9];
    const float* g1  = (const float*)d_in[10];
    const float* be1 = (const float*)d_in[11];
    const float* Wl2 = (const float*)d_in[12];
    const float* Wr2 = (const float*)d_in[13];
    const float* b2  = (const float*)d_in[14];
    float* out = (float*)d_out;

    const int E = in_sizes[1] / 2;
    const int* src = ei;
    const int* dst = ei + E;

    __half *xh, *M, *W, *h0, *h1;
    float *sum0, *sq0, *sum1, *sq1;
    int *cnti, *rowptr, *rank, *csr;
    cudaGetSymbolAddress((void**)&xh, g_xh);
    cudaGetSymbolAddress((void**)&M, g_M);
    cudaGetSymbolAddress((void**)&W, g_W);
    cudaGetSymbolAddress((void**)&h0, g_h0);
    cudaGetSymbolAddress((void**)&h1, g_h1);
    cudaGetSymbolAddress((void**)&cnti, g_cnti);
    cudaGetSymbolAddress((void**)&rowptr, g_rowptr);
    cudaGetSymbolAddress((void**)&rank, g_rank);
    cudaGetSymbolAddress((void**)&csr, g_csr);
    cudaGetSymbolAddress((void**)&sum0, g_sum0);
    cudaGetSymbolAddress((void**)&sq0, g_sq0);
    cudaGetSymbolAddress((void**)&sum1, g_sum1);
    cudaGetSymbolAddress((void**)&sq1, g_sq1);

    constexpr int RS = 72;
    const int SMEM = 4 * 128 * RS * 2;  // 73728 bytes: 2 buffers x (A + W)
    cudaFuncSetAttribute((const void*)k_mma_gemm, cudaFuncAttributeMaxDynamicSharedMemorySize, SMEM);
    cudaFuncSetAttribute((const void*)k_gemm_l2, cudaFuncAttributeMaxDynamicSharedMemorySize, SMEM);

    const int aggBlocks  = (N_NODES * 32 + 255) / 256;
    const int gemmBlocks = (N_NODES + 127) / 128;

    __half* W0 = W;
    __half* W1 = W + 128 * 256;
    __half* W2 = W + 256 * 256;

    // ---- prep: weights + x->fp16 + CSR ----
    k_prep<<<1024, 256>>>(dst, E, cnti, rank, x, xh,
                          Wl0, Wr0, Wl1, Wr1, Wl2, Wr2, W);
    k_scan<<<1, 1024>>>(cnti, rowptr);
    k_fill<<<1024, 256>>>(src, dst, E, rank, rowptr, csr);

    // ---- layer 0 ----
    k_aggregate<<<aggBlocks, 256>>>(xh, csr, rowptr, M, sum0, sq0);
    k_mma_gemm<<<gemmBlocks, 256, SMEM>>>(M, xh, W0, b0, h0, sum0, sq0);
    k_bn_apply<<<1024, 256>>>(h0, sum0, sq0, g0, be0);

    // ---- layer 1 ----
    k_aggregate<<<aggBlocks, 256>>>(h0, csr, rowptr, M, sum1, sq1);
    k_mma_gemm<<<gemmBlocks, 256, SMEM>>>(M, h0, W1, b1, h1, sum1, sq1);
    k_bn_apply<<<1024, 256>>>(h1, sum1, sq1, g1, be1);

    // ---- layer 2 (commuted: GEMM first, then fp16 gather + log-softmax) ----
    k_gemm_l2<<<gemmBlocks, 256, SMEM>>>(h1, W2, b2, h0);
    k_final<<<aggBlocks, 256>>>(h0, csr, rowptr, out);
}

// round 15
// speedup vs baseline: 1.5981x; 1.1357x over previous
#include <cuda_runtime.h>
#include <cuda_fp16.h>
#include <cstdint>

#define N_NODES 50000
#define E_MAX   800000
#define D 128
#define D_OUT 64
#define BN_EPS 1e-5f
#define WTOT (2 * 128 * 256 + 128 * 128)

// ---------------- scratch (device globals; no allocation allowed) ----------
__device__ __half g_xh[(size_t)N_NODES * D];   // fp16 copy of x
__device__ __half g_M[(size_t)N_NODES * D];    // neighbor mean (fp16)
__device__ __half g_W[WTOT];                   // fp16 weights (all layers, transposed)
__device__ __half g_h0[(size_t)N_NODES * D];   // layer0 out; later reused for [z2|s2]
__device__ __half g_h1[(size_t)N_NODES * D];
__device__ int    g_cnti[N_NODES];
__device__ int    g_rowptr[N_NODES + 1];
__device__ int    g_rank[E_MAX];
__device__ int    g_csr[E_MAX];
__device__ float  g_sum0[D];
__device__ float  g_sq0[D];
__device__ float  g_sum1[D];
__device__ float  g_sq1[D];

// ---------------- helpers ----------------------------------------------------
__device__ __forceinline__ uint32_t smem_u32(const void* p) {
    return (uint32_t)__cvta_generic_to_shared(p);
}

__device__ __forceinline__ void ldsm4(uint32_t* r, uint32_t a) {
    asm volatile("ldmatrix.sync.aligned.m8n8.x4.shared.b16 {%0,%1,%2,%3}, [%4];"
                 : "=r"(r[0]), "=r"(r[1]), "=r"(r[2]), "=r"(r[3]) : "r"(a));
}

__device__ __forceinline__ void mma16816f(float* d, const uint32_t* a, const uint32_t* b) {
    asm volatile("mma.sync.aligned.m16n8k16.row.col.f32.f16.f16.f32 "
                 "{%0,%1,%2,%3}, {%4,%5,%6,%7}, {%8,%9}, {%0,%1,%2,%3};"
                 : "+f"(d[0]), "+f"(d[1]), "+f"(d[2]), "+f"(d[3])
                 : "r"(a[0]), "r"(a[1]), "r"(a[2]), "r"(a[3]), "r"(b[0]), "r"(b[1]));
}

__device__ __forceinline__ void cp_async16(uint32_t sa, const void* g, int sz) {
    asm volatile("cp.async.cg.shared.global [%0], [%1], 16, %2;"
                 :: "r"(sa), "l"(g), "r"(sz) : "memory");
}
__device__ __forceinline__ void cp_commit() {
    asm volatile("cp.async.commit_group;" ::: "memory");
}
__device__ __forceinline__ void cp_wait0() {
    asm volatile("cp.async.wait_group 0;" ::: "memory");
}

// ---------------- prep: weights->fp16, x->fp16, degree hist + ranks ---------
__global__ void k_prep(const int* __restrict__ dst, int E,
                       int* __restrict__ cnt, int* __restrict__ rank,
                       const float* __restrict__ x, __half* __restrict__ xh,
                       const float* __restrict__ Wl0, const float* __restrict__ Wr0,
                       const float* __restrict__ Wl1, const float* __restrict__ Wr1,
                       const float* __restrict__ Wl2, const float* __restrict__ Wr2,
                       __half* __restrict__ W) {
    int idx = blockIdx.x * blockDim.x + threadIdx.x;
    int stride = gridDim.x * blockDim.x;

    if (idx < WTOT) {
        const int T01 = 128 * 256;
        float v;
        if (idx < T01) {
            int n = idx >> 8, k = idx & 255;
            v = (k < 128) ? __ldg(Wl0 + k * 128 + n) : __ldg(Wr0 + (k - 128) * 128 + n);
        } else if (idx < 2 * T01) {
            int l = idx - T01;
            int n = l >> 8, k = l & 255;
            v = (k < 128) ? __ldg(Wl1 + k * 128 + n) : __ldg(Wr1 + (k - 128) * 128 + n);
        } else {
            int l = idx - 2 * T01;
            int n = l >> 7, k = l & 127;
            v = (n < 64) ? __ldg(Wl2 + k * 64 + n) : __ldg(Wr2 + k * 64 + (n - 64));
        }
        W[idx] = __float2half_rn(v);
    }

    // x -> fp16 (8 elements per iteration)
    const int X8 = N_NODES * D / 8;
    for (int i = idx; i < X8; i += stride) {
        float4 u0 = __ldg(reinterpret_cast<const float4*>(x) + i * 2);
        float4 u1 = __ldg(reinterpret_cast<const float4*>(x) + i * 2 + 1);
        __half2 h[4];
        h[0] = __float22half2_rn(make_float2(u0.x, u0.y));
        h[1] = __float22half2_rn(make_float2(u0.z, u0.w));
        h[2] = __float22half2_rn(make_float2(u1.x, u1.y));
        h[3] = __float22half2_rn(make_float2(u1.z, u1.w));
        reinterpret_cast<uint4*>(xh)[i] = *reinterpret_cast<uint4*>(h);
    }

    int nQ = E >> 2;
    for (int q = idx; q < nQ; q += stride) {
        int4 d = __ldg(reinterpret_cast<const int4*>(dst) + q);
        int4 r;
        r.x = atomicAdd(&cnt[d.x], 1);
        r.y = atomicAdd(&cnt[d.y], 1);
        r.z = atomicAdd(&cnt[d.z], 1);
        r.w = atomicAdd(&cnt[d.w], 1);
        *(reinterpret_cast<int4*>(rank) + q) = r;
    }
    for (int e = nQ * 4 + idx; e < E; e += stride)
        rank[e] = atomicAdd(&cnt[__ldg(dst + e)], 1);
}

// single block, 1024 threads: chunked warp-shuffle exclusive scan.
// Coalesced loads; self-zeroes cnt for next graph replay.
__global__ void k_scan(int* __restrict__ cnt, int* __restrict__ row_ptr) {
    __shared__ int warpsum[32];
    __shared__ int carry;
    const int t = threadIdx.x;
    const int lane = t & 31;
    const int wid = t >> 5;
    if (t == 0) carry = 0;
    __syncthreads();

    const int NCH = (N_NODES + 1023) / 1024;
    for (int ch = 0; ch < NCH; ch++) {
        int i = ch * 1024 + t;
        int v = 0;
        if (i < N_NODES) { v = cnt[i]; cnt[i] = 0; }
        // inclusive warp scan
        int s = v;
#pragma unroll
        for (int o = 1; o < 32; o <<= 1) {
            int u = __shfl_up_sync(0xffffffffu, s, o);
            if (lane >= o) s += u;
        }
        if (lane == 31) warpsum[wid] = s;
        __syncthreads();
        if (wid == 0) {
            int ws = warpsum[lane];
#pragma unroll
            for (int o = 1; o < 32; o <<= 1) {
                int u = __shfl_up_sync(0xffffffffu, ws, o);
                if (lane >= o) ws += u;
            }
            warpsum[lane] = ws;
        }
        __syncthreads();
        int wbase = (wid > 0) ? warpsum[wid - 1] : 0;
        int base = carry;
        if (i < N_NODES) row_ptr[i] = base + wbase + s - v;
        __syncthreads();
        if (t == 0) carry += warpsum[31];
        __syncthreads();
    }
    if (t == 0) row_ptr[N_NODES] = carry;
}

// atomic-free fill using precomputed ranks
__global__ void k_fill(const int* __restrict__ src, const int* __restrict__ dst,
                       int E, const int* __restrict__ rank,
                       const int* __restrict__ row_ptr, int* __restrict__ csr) {
    int i = blockIdx.x * blockDim.x + threadIdx.x;
    int stride = gridDim.x * blockDim.x;
    int nQ = E >> 2;
    for (int q = i; q < nQ; q += stride) {
        int4 d = __ldg(reinterpret_cast<const int4*>(dst) + q);
        int4 s = __ldg(reinterpret_cast<const int4*>(src) + q);
        int4 r = __ldg(reinterpret_cast<const int4*>(rank) + q);
        csr[__ldg(row_ptr + d.x) + r.x] = s.x;
        csr[__ldg(row_ptr + d.y) + r.y] = s.y;
        csr[__ldg(row_ptr + d.z) + r.z] = s.z;
        csr[__ldg(row_ptr + d.w) + r.w] = s.w;
    }
    for (int e = nQ * 4 + i; e < E; e += stride)
        csr[__ldg(row_ptr + __ldg(dst + e)) + __ldg(rank + e)] = __ldg(src + e);
}

// ---------------- aggregation: fp16 gather, 4-edge fp16 tree reduction ------
// One warp per node; block 0 zeroes the given stats buffers.
__global__ __launch_bounds__(256)
void k_aggregate(const __half* __restrict__ xin, const int* __restrict__ csr,
                 const int* __restrict__ row_ptr, __half* __restrict__ M,
                 float* __restrict__ zSum, float* __restrict__ zSq) {
    int tid = threadIdx.x;
    if (blockIdx.x == 0 && tid < 128) { zSum[tid] = 0.f; zSq[tid] = 0.f; }

    int w = (blockIdx.x * blockDim.x + tid) >> 5;
    if (w >= N_NODES) return;
    int lane = tid & 31;

    int beg = __ldg(row_ptr + w);
    int end = __ldg(row_ptr + w + 1);
    float4 acc = make_float4(0.f, 0.f, 0.f, 0.f);

    int i = beg;
    for (; i + 3 < end; i += 4) {
        int s0 = __ldg(csr + i);
        int s1 = __ldg(csr + i + 1);
        int s2 = __ldg(csr + i + 2);
        int s3 = __ldg(csr + i + 3);
        uint2 u0 = __ldg(reinterpret_cast<const uint2*>(xin + (size_t)s0 * D) + lane);
        uint2 u1 = __ldg(reinterpret_cast<const uint2*>(xin + (size_t)s1 * D) + lane);
        uint2 u2 = __ldg(reinterpret_cast<const uint2*>(xin + (size_t)s2 * D) + lane);
        uint2 u3 = __ldg(reinterpret_cast<const uint2*>(xin + (size_t)s3 * D) + lane);
        __half2 a_lo = __hadd2(*reinterpret_cast<__half2*>(&u0.x), *reinterpret_cast<__half2*>(&u1.x));
        __half2 a_hi = __hadd2(*reinterpret_cast<__half2*>(&u0.y), *reinterpret_cast<__half2*>(&u1.y));
        __half2 b_lo = __hadd2(*reinterpret_cast<__half2*>(&u2.x), *reinterpret_cast<__half2*>(&u3.x));
        __half2 b_hi = __hadd2(*reinterpret_cast<__half2*>(&u2.y), *reinterpret_cast<__half2*>(&u3.y));
        __half2 t_lo = __hadd2(a_lo, b_lo);
        __half2 t_hi = __hadd2(a_hi, b_hi);
        float2 f0 = __half22float2(t_lo);
        float2 f1 = __half22float2(t_hi);
        acc.x += f0.x; acc.y += f0.y; acc.z += f1.x; acc.w += f1.y;
    }
    for (; i < end; i++) {
        int s0 = __ldg(csr + i);
        uint2 u0 = __ldg(reinterpret_cast<const uint2*>(xin + (size_t)s0 * D) + lane);
        float2 f0 = __half22float2(*reinterpret_cast<__half2*>(&u0.x));
        float2 f1 = __half22float2(*reinterpret_cast<__half2*>(&u0.y));
        acc.x += f0.x; acc.y += f0.y; acc.z += f1.x; acc.w += f1.y;
    }

    float inv = 1.f / (float)max(end - beg, 1);
    __half2 o[2];
    o[0] = __float22half2_rn(make_float2(acc.x * inv, acc.y * inv));
    o[1] = __float22half2_rn(make_float2(acc.z * inv, acc.w * inv));
    *reinterpret_cast<uint2*>(M + (size_t)w * D + lane * 4) = *reinterpret_cast<uint2*>(o);
}

// ---------------- BN+ReLU in place on fp16 h (layer 0 only) -----------------
__global__ __launch_bounds__(256)
void k_bn_apply(__half* __restrict__ h,
                const float* __restrict__ stSum, const float* __restrict__ stSq,
                const float* __restrict__ gamma, const float* __restrict__ beta) {
    __shared__ float ssc[128], ssh[128];
    int tid = threadIdx.x;
    if (tid < 128) {
        float mu = __ldg(stSum + tid) / (float)N_NODES;
        float var = __ldg(stSq + tid) / (float)N_NODES - mu * mu;
        float sc = __ldg(gamma + tid) * rsqrtf(var + BN_EPS);
        ssc[tid] = sc;
        ssh[tid] = __ldg(beta + tid) - mu * sc;
    }
    __syncthreads();

    const int T8 = N_NODES * D / 8;
    for (int i = blockIdx.x * blockDim.x + tid; i < T8; i += gridDim.x * blockDim.x) {
        int c8 = (i & 15) * 8;
        uint4 u = *(reinterpret_cast<uint4*>(h) + i);
        __half2* hp = reinterpret_cast<__half2*>(&u);
#pragma unroll
        for (int j = 0; j < 4; j++) {
            float2 f = __half22float2(hp[j]);
            f.x = fmaxf(fmaf(f.x, ssc[c8 + 2 * j], ssh[c8 + 2 * j]), 0.f);
            f.y = fmaxf(fmaf(f.y, ssc[c8 + 2 * j + 1], ssh[c8 + 2 * j + 1]), 0.f);
            hp[j] = __float22half2_rn(f);
        }
        *(reinterpret_cast<uint4*>(h) + i) = u;
    }
}

// ---------------- fp16 HMMA GEMM layers 0/1 (K=256, N=128), cp.async 2-buf --
// A = [mean (fp16) | self (fp16, already BN'd)]; out = A@W^T + b (fp16 store)
// Fused BN column-stat accumulation (fp32) into stOut.
__global__ __launch_bounds__(256)
void k_mma_gemm(const __half* __restrict__ M, const __half* __restrict__ selfSrc,
                const __half* __restrict__ W, const float* __restrict__ bias,
                __half* __restrict__ out,
                float* __restrict__ stOutSum, float* __restrict__ stOutSq) {
    constexpr int RS = 72;
    constexpr int NT = 8;
    constexpr int BUF = 128 * RS;          // halves per A (or W) section
    extern __shared__ __half sm[];

    __shared__ float ssum[128];
    __shared__ float ssq[128];

    const int tid = threadIdx.x;
    const int lane = tid & 31;
    const int warp = tid >> 5;
    const int wr = warp & 3;
    const int wc = warp >> 2;
    const int rowBase = blockIdx.x * 128;

    if (tid < 128) { ssum[tid] = 0.f; ssq[tid] = 0.f; }

    float acc[2][NT][4];
#pragma unroll
    for (int mt = 0; mt < 2; mt++)
#pragma unroll
        for (int nt = 0; nt < NT; nt++)
#pragma unroll
            for (int j = 0; j < 4; j++) acc[mt][nt][j] = 0.f;

    auto issue = [&](int stage, int b) {
        const __half* Asrc = (stage < 2) ? M : selfSrc;
        const int colBase = (stage & 1) * 64;
        __half* sA = sm + b * 2 * BUF;
        __half* sW = sA + BUF;
#pragma unroll
        for (int t = 0; t < 4; t++) {
            int idx = tid + t * 256;
            int r = idx >> 3, c = idx & 7;
            int row = rowBase + r;
            int ok = (row < N_NODES) ? 16 : 0;
            int srow = (row < N_NODES) ? row : 0;
            cp_async16(smem_u32(sA + r * RS + c * 8),
                       Asrc + (size_t)srow * D + colBase + c * 8, ok);
        }
#pragma unroll
        for (int t = 0; t < 4; t++) {
            int idx = tid + t * 256;
            int n = idx >> 3, c = idx & 7;
            cp_async16(smem_u32(sW + n * RS + c * 8),
                       W + (size_t)n * 256 + stage * 64 + c * 8, 16);
        }
        cp_commit();
    };

    issue(0, 0);

    for (int stage = 0; stage < 4; stage++) {
        cp_wait0();
        __syncthreads();
        if (stage + 1 < 4) issue(stage + 1, (stage + 1) & 1);

        const uint32_t sbA = smem_u32(sm + (stage & 1) * 2 * BUF);
        const uint32_t sbW = sbA + BUF * 2;

#pragma unroll
        for (int ks = 0; ks < 4; ks++) {
            const uint32_t koff = (uint32_t)(ks * 16 + (lane >> 4) * 8) * 2;
            uint32_t a[2][4];
#pragma unroll
            for (int mt = 0; mt < 2; mt++) {
                uint32_t roff = (uint32_t)(wr * 32 + mt * 16 + (lane & 15)) * (RS * 2) + koff;
                ldsm4(a[mt], sbA + roff);
            }
            uint32_t b[NT][2];
#pragma unroll
            for (int g = 0; g < NT / 2; g++) {
                uint32_t roff = (uint32_t)(wc * 64 + g * 16 + (lane & 15)) * (RS * 2) + koff;
                uint32_t r[4];
                ldsm4(r, sbW + roff);
                b[2 * g][0] = r[0]; b[2 * g][1] = r[2];
                b[2 * g + 1][0] = r[1]; b[2 * g + 1][1] = r[3];
            }
#pragma unroll
            for (int mt = 0; mt < 2; mt++)
#pragma unroll
                for (int nt = 0; nt < NT; nt++)
                    mma16816f(acc[mt][nt], a[mt], b[nt]);
        }
        __syncthreads();
    }

#pragma unroll
    for (int nt = 0; nt < NT; nt++) {
        int col = wc * 64 + nt * 8 + (lane & 3) * 2;
        float2 bb = *reinterpret_cast<const float2*>(bias + col);
        float s0 = 0.f, s1 = 0.f, q0 = 0.f, q1 = 0.f;
#pragma unroll
        for (int mt = 0; mt < 2; mt++) {
            int r0 = rowBase + wr * 32 + mt * 16 + (lane >> 2);
            float v0 = acc[mt][nt][0] + bb.x, v1 = acc[mt][nt][1] + bb.y;
            float v2 = acc[mt][nt][2] + bb.x, v3 = acc[mt][nt][3] + bb.y;
            if (r0 < N_NODES) {
                *reinterpret_cast<__half2*>(out + (size_t)r0 * 128 + col) =
                    __float22half2_rn(make_float2(v0, v1));
                s0 += v0; s1 += v1; q0 += v0 * v0; q1 += v1 * v1;
            }
            if (r0 + 8 < N_NODES) {
                *reinterpret_cast<__half2*>(out + (size_t)(r0 + 8) * 128 + col) =
                    __float22half2_rn(make_float2(v2, v3));
                s0 += v2; s1 += v3; q0 += v2 * v2; q1 += v3 * v3;
            }
        }
#pragma unroll
        for (int off = 4; off < 32; off <<= 1) {
            s0 += __shfl_down_sync(0xffffffffu, s0, off);
            s1 += __shfl_down_sync(0xffffffffu, s1, off);
            q0 += __shfl_down_sync(0xffffffffu, q0, off);
            q1 += __shfl_down_sync(0xffffffffu, q1, off);
        }
        if ((lane >> 2) == 0) {
            atomicAdd(&ssum[col], s0); atomicAdd(&ssum[col + 1], s1);
            atomicAdd(&ssq[col], q0);  atomicAdd(&ssq[col + 1], q1);
        }
    }
    __syncthreads();
    if (tid < 128) {
        atomicAdd(&stOutSum[tid], ssum[tid]);
        atomicAdd(&stOutSq[tid], ssq[tid]);
    }
}

// ---------------- layer-2 GEMM: [z | s+b2] = relu(bn(h1)) @ [Wl2|Wr2]^T -----
// BN1+ReLU fused into the A-load (h1's only consumer); b2 folded into s-cols.
__global__ __launch_bounds__(256)
void k_gemm_l2(const __half* __restrict__ hin,
               const float* __restrict__ stSum, const float* __restrict__ stSq,
               const float* __restrict__ gamma, const float* __restrict__ beta,
               const __half* __restrict__ W, const float* __restrict__ b2,
               __half* __restrict__ zout) {
    constexpr int RS = 72;
    constexpr int NT = 8;
    extern __shared__ __half sm[];
    __half* sA = sm;
    __half* sW = sm + 128 * RS;

    __shared__ float ssc[128], ssh[128];

    const int tid = threadIdx.x;
    const int lane = tid & 31;
    const int warp = tid >> 5;
    const int wr = warp & 3;
    const int wc = warp >> 2;
    const int rowBase = blockIdx.x * 128;

    if (tid < 128) {
        float mu = __ldg(stSum + tid) / (float)N_NODES;
        float var = __ldg(stSq + tid) / (float)N_NODES - mu * mu;
        float sc = __ldg(gamma + tid) * rsqrtf(var + BN_EPS);
        ssc[tid] = sc;
        ssh[tid] = __ldg(beta + tid) - mu * sc;
    }
    __syncthreads();

    const uint32_t sbA = smem_u32(sA);
    const uint32_t sbW = smem_u32(sW);

    float acc[2][NT][4];
#pragma unroll
    for (int mt = 0; mt < 2; mt++)
#pragma unroll
        for (int nt = 0; nt < NT; nt++)
#pragma unroll
            for (int j = 0; j < 4; j++) acc[mt][nt][j] = 0.f;

    for (int stage = 0; stage < 2; stage++) {
#pragma unroll
        for (int t = 0; t < 4; t++) {
            int idx = tid + t * 256;
            int r = idx >> 3, c = idx & 7;
            int row = rowBase + r;
            int col0 = stage * 64 + c * 8;
            uint4 u = make_uint4(0, 0, 0, 0);
            if (row < N_NODES) {
                u = __ldg(reinterpret_cast<const uint4*>(hin + (size_t)row * D + col0));
                __half2* hp = reinterpret_cast<__half2*>(&u);
#pragma unroll
                for (int j = 0; j < 4; j++) {
                    float2 f = __half22float2(hp[j]);
                    f.x = fmaxf(fmaf(f.x, ssc[col0 + 2 * j], ssh[col0 + 2 * j]), 0.f);
                    f.y = fmaxf(fmaf(f.y, ssc[col0 + 2 * j + 1], ssh[col0 + 2 * j + 1]), 0.f);
                    hp[j] = __float22half2_rn(f);
                }
            }
            *reinterpret_cast<uint4*>(sA + r * RS + c * 8) = u;
        }
#pragma unroll
        for (int t = 0; t < 4; t++) {
            int idx = tid + t * 256;
            int n = idx >> 3, c = idx & 7;
            uint4 v = __ldg(reinterpret_cast<const uint4*>(W + (size_t)n * 128 + stage * 64) + c);
            *reinterpret_cast<uint4*>(sW + n * RS + c * 8) = v;
        }
        __syncthreads();

#pragma unroll
        for (int ks = 0; ks < 4; ks++) {
            const uint32_t koff = (uint32_t)(ks * 16 + (lane >> 4) * 8) * 2;
            uint32_t a[2][4];
#pragma unroll
            for (int mt = 0; mt < 2; mt++) {
                uint32_t roff = (uint32_t)(wr * 32 + mt * 16 + (lane & 15)) * (RS * 2) + koff;
                ldsm4(a[mt], sbA + roff);
            }
            uint32_t b[NT][2];
#pragma unroll
            for (int g = 0; g < NT / 2; g++) {
                uint32_t roff = (uint32_t)(wc * 64 + g * 16 + (lane & 15)) * (RS * 2) + koff;
                uint32_t r[4];
                ldsm4(r, sbW + roff);
                b[2 * g][0] = r[0]; b[2 * g][1] = r[2];
                b[2 * g + 1][0] = r[1]; b[2 * g + 1][1] = r[3];
            }
#pragma unroll
            for (int mt = 0; mt < 2; mt++)
#pragma unroll
                for (int nt = 0; nt < NT; nt++)
                    mma16816f(acc[mt][nt], a[mt], b[nt]);
        }
        __syncthreads();
    }

    // epilogue: wc==1 warps own the s-columns (64..127) -> fold b2 in now
#pragma unroll
    for (int nt = 0; nt < NT; nt++) {
        int col = wc * 64 + nt * 8 + (lane & 3) * 2;
        float2 bb = make_float2(0.f, 0.f);
        if (wc == 1) bb = *reinterpret_cast<const float2*>(b2 + (col - 64));
#pragma unroll
        for (int mt = 0; mt < 2; mt++) {
            int r0 = rowBase + wr * 32 + mt * 16 + (lane >> 2);
            if (r0 < N_NODES)
                *reinterpret_cast<__half2*>(zout + (size_t)r0 * 128 + col) =
                    __float22half2_rn(make_float2(acc[mt][nt][0] + bb.x, acc[mt][nt][1] + bb.y));
            if (r0 + 8 < N_NODES)
                *reinterpret_cast<__half2*>(zout + (size_t)(r0 + 8) * 128 + col) =
                    __float22half2_rn(make_float2(acc[mt][nt][2] + bb.x, acc[mt][nt][3] + bb.y));
        }
    }
}

// ---------------- final: out = log_softmax(mean(z[src]) + (s+b2)) -----------
// zs rows (fp16): [z (cols 0..63) | s+b2 (cols 64..127)]; warp per node.
__global__ __launch_bounds__(256)
void k_final(const __half* __restrict__ zs, const int* __restrict__ csr,
             const int* __restrict__ row_ptr, float* __restrict__ out) {
    int w = (blockIdx.x * blockDim.x + threadIdx.x) >> 5;
    if (w >= N_NODES) return;
    int lane = threadIdx.x & 31;
    int beg = __ldg(row_ptr + w);
    int end = __ldg(row_ptr + w + 1);
    float2 a = make_float2(0.f, 0.f);
    int i = beg;
    for (; i + 3 < end; i += 4) {
        int s0 = __ldg(csr + i);
        int s1 = __ldg(csr + i + 1);
        int s2 = __ldg(csr + i + 2);
        int s3 = __ldg(csr + i + 3);
        __half2 u0 = __ldg(reinterpret_cast<const __half2*>(zs + (size_t)s0 * 128) + lane);
        __half2 u1 = __ldg(reinterpret_cast<const __half2*>(zs + (size_t)s1 * 128) + lane);
        __half2 u2 = __ldg(reinterpret_cast<const __half2*>(zs + (size_t)s2 * 128) + lane);
        __half2 u3 = __ldg(reinterpret_cast<const __half2*>(zs + (size_t)s3 * 128) + lane);
        __half2 t = __hadd2(__hadd2(u0, u1), __hadd2(u2, u3));
        float2 f = __half22float2(t);
        a.x += f.x; a.y += f.y;
    }
    for (; i < end; i++) {
        int s0 = __ldg(csr + i);
        float2 f = __half22float2(__ldg(reinterpret_cast<const __half2*>(zs + (size_t)s0 * 128) + lane));
        a.x += f.x; a.y += f.y;
    }
    float inv = 1.f / (float)max(end - beg, 1);
    float2 sv = __half22float2(__ldg(reinterpret_cast<const __half2*>(zs + (size_t)w * 128 + 64) + lane));
    float v0 = a.x * inv + sv.x;
    float v1 = a.y * inv + sv.y;
    float m = fmaxf(v0, v1);
#pragma unroll
    for (int o = 16; o > 0; o >>= 1) m = fmaxf(m, __shfl_xor_sync(0xffffffffu, m, o));
    float e = expf(v0 - m) + expf(v1 - m);
#pragma unroll
    for (int o = 16; o > 0; o >>= 1) e += __shfl_xor_sync(0xffffffffu, e, o);
    float l = m + logf(e);
    *(reinterpret_cast<float2*>(out + (size_t)w * D_OUT) + lane) = make_float2(v0 - l, v1 - l);
}

// ---------------- launch ----------------------------------------------------
extern "C" void kernel_launch(void* const* d_in, const int* in_sizes, int n_in,
                              void* d_out, int out_size) {
    const float* x   = (const float*)d_in[0];
    const int* ei    = (const int*)d_in[1];
    const float* Wl0 = (const float*)d_in[2];
    const float* Wr0 = (const float*)d_in[3];
    const float* b0  = (const float*)d_in[4];
    const float* g0  = (const float*)d_in[5];
    const float* be0 = (const float*)d_in[6];
    const float* Wl1 = (const float*)d_in[7];
    const float* Wr1 = (const float*)d_in[8];
    const float* b1  = (const float*)d_in[9];
    const float* g1  = (const float*)d_in[10];
    const float* be1 = (const float*)d_in[11];
    const float* Wl2 = (const float*)d_in[12];
    const float* Wr2 = (const float*)d_in[13];
    const float* b2  = (const float*)d_in[14];
    float* out = (float*)d_out;

    const int E = in_sizes[1] / 2;
    const int* src = ei;
    const int* dst = ei + E;

    __half *xh, *M, *W, *h0, *h1;
    float *sum0, *sq0, *sum1, *sq1;
    int *cnti, *rowptr, *rank, *csr;
    cudaGetSymbolAddress((void**)&xh, g_xh);
    cudaGetSymbolAddress((void**)&M, g_M);
    cudaGetSymbolAddress((void**)&W, g_W);
    cudaGetSymbolAddress((void**)&h0, g_h0);
    cudaGetSymbolAddress((void**)&h1, g_h1);
    cudaGetSymbolAddress((void**)&cnti, g_cnti);
    cudaGetSymbolAddress((void**)&rowptr, g_rowptr);
    cudaGetSymbolAddress((void**)&rank, g_rank);
    cudaGetSymbolAddress((void**)&csr, g_csr);
    cudaGetSymbolAddress((void**)&sum0, g_sum0);
    cudaGetSymbolAddress((void**)&sq0, g_sq0);
    cudaGetSymbolAddress((void**)&sum1, g_sum1);
    cudaGetSymbolAddress((void**)&sq1, g_sq1);

    constexpr int RS = 72;
    const int SMEM  = 4 * 128 * RS * 2;  // 73728: 2 buffers x (A + W)
    const int SMEM2 = 2 * 128 * RS * 2;  // 36864: single buffer (gemm_l2)
    cudaFuncSetAttribute((const void*)k_mma_gemm, cudaFuncAttributeMaxDynamicSharedMemorySize, SMEM);
    cudaFuncSetAttribute((const void*)k_gemm_l2, cudaFuncAttributeMaxDynamicSharedMemorySize, SMEM2);

    const int aggBlocks  = (N_NODES * 32 + 255) / 256;
    const int gemmBlocks = (N_NODES + 127) / 128;

    __half* W0 = W;
    __half* W1 = W + 128 * 256;
    __half* W2 = W + 256 * 256;

    // ---- prep: weights + x->fp16 + CSR ----
    k_prep<<<1024, 256>>>(dst, E, cnti, rank, x, xh,
                          Wl0, Wr0, Wl1, Wr1, Wl2, Wr2, W);
    k_scan<<<1, 1024>>>(cnti, rowptr);
    k_fill<<<1024, 256>>>(src, dst, E, rank, rowptr, csr);

    // ---- layer 0 ----
    k_aggregate<<<aggBlocks, 256>>>(xh, csr, rowptr, M, sum0, sq0);
    k_mma_gemm<<<gemmBlocks, 256, SMEM>>>(M, xh, W0, b0, h0, sum0, sq0);
    k_bn_apply<<<1024, 256>>>(h0, sum0, sq0, g0, be0);

    // ---- layer 1 ----
    k_aggregate<<<aggBlocks, 256>>>(h0, csr, rowptr, M, sum1, sq1);
    k_mma_gemm<<<gemmBlocks, 256, SMEM>>>(M, h0, W1, b1, h1, sum1, sq1);

    // ---- layer 2 (BN1 fused into GEMM A-load; then fp16 gather + softmax) --
    k_gemm_l2<<<gemmBlocks, 256, SMEM2>>>(h1, sum1, sq1, g1, be1, W2, b2, h0);
    k_final<<<aggBlocks, 256>>>(h0, csr, rowptr, out);
}